// round 8
// baseline (speedup 1.0000x reference)
#include <cuda_runtime.h>
#include <cuda_fp16.h>
#include <cstdint>

#define BB   2048
#define TT   64
#define DD   256
#define HH   256
#define CC   1000
#define SS   26
#define DCC  1256   // D + C
#define MROWS 16    // batch rows per recurrence CTA
#define XS   516    // sh_x row stride (floats): conflict-free frags
#define MMS  268    // mm kernel smem row stride (floats): conflict-free frags
#define MM_SMEM ((64 + 128) * MMS * 4)

// Scratch (allocation-free: __device__ globals)
__device__ __half g_Hproj[(size_t)BB * TT * HH];   // 64 MB (fp16)
__device__ __half g_bhH[(size_t)BB * TT * DD];     // 64 MB fp16 copy of batch_H
__device__ float  g_hidden[(size_t)BB * SS * HH];  // 52 MB
__device__ float2 g_WfragGates[128 * 64 * 32];     // 2 MB   B-frags, gates GEMM
__device__ float2 g_WfragH2h[32 * 32 * 32];        // 256 KB B-frags, h2h GEMM
__device__ float  g_WohP[1000 * 1024];             // 4 MB   one-hot cols, packed order
__device__ float  g_biasP[1024];                   // b_ih+b_hh, packed order

__device__ __forceinline__ float ftanh(float x) {
    float y;
    asm("tanh.approx.f32 %0, %1;" : "=f"(y) : "f"(x));
    return y;
}
__device__ __forceinline__ float fsig(float x) {
    return 0.5f * ftanh(0.5f * x) + 0.5f;
}
__device__ __forceinline__ uint32_t tf32_bits(float x) {
    uint32_t r;
    asm("cvt.rna.tf32.f32 %0, %1;" : "=r"(r) : "f"(x));
    return r;
}
__device__ __forceinline__ float tf32f(float x) {
    return __uint_as_float(tf32_bits(x));
}
__device__ __forceinline__ void mma_tf32(float* c,
    uint32_t a0, uint32_t a1, uint32_t a2, uint32_t a3,
    uint32_t b0, uint32_t b1)
{
    asm volatile(
        "mma.sync.aligned.m16n8k8.row.col.f32.tf32.tf32.f32 "
        "{%0,%1,%2,%3}, {%4,%5,%6,%7}, {%8,%9}, {%0,%1,%2,%3};"
        : "+f"(c[0]), "+f"(c[1]), "+f"(c[2]), "+f"(c[3])
        : "r"(a0), "r"(a1), "r"(a2), "r"(a3), "r"(b0), "r"(b1));
}

// Packed gate-column decode: n' in [0,1024): [IF(512) | GO(512)], col 2u+b.
__device__ __forceinline__ int packed_gate_row(int nprime) {
    const int np = nprime & 511, u = np >> 1, b = np & 1;
    const bool go = nprime >= 512;
    return u + (go ? (b ? 768 : 512) : (b ? 256 : 0));   // rows: i|f|g|o
}

// ---------------------------------------------------------------------------
// Pack kernels
// ---------------------------------------------------------------------------
__global__ void __launch_bounds__(1024) pack_gates(
    const float* __restrict__ W_ih, const float* __restrict__ W_hh)
{
    const int idx = blockIdx.x * 1024 + threadIdx.x;
    const int lane = idx & 31;
    const int kt   = (idx >> 5) & 63;
    const int nt   = idx >> 11;
    const int npr  = (nt & 63) * 8 + (lane >> 2) + ((nt >= 64) ? 512 : 0);
    const int row  = packed_gate_row(npr);
    const int k0   = kt * 8 + (lane & 3);
    const int k1   = k0 + 4;
    const float v0 = (k0 < 256) ? W_ih[(size_t)row * DCC + k0]
                                : W_hh[(size_t)row * HH + k0 - 256];
    const float v1 = (k1 < 256) ? W_ih[(size_t)row * DCC + k1]
                                : W_hh[(size_t)row * HH + k1 - 256];
    g_WfragGates[idx] = make_float2(tf32f(v0), tf32f(v1));
}

__global__ void __launch_bounds__(1024) pack_h2h(const float* __restrict__ W_h2h)
{
    const int idx = blockIdx.x * 1024 + threadIdx.x;
    const int lane = idx & 31;
    const int kt   = (idx >> 5) & 31;
    const int nt   = idx >> 10;
    const int n    = nt * 8 + (lane >> 2);
    const int k0   = kt * 8 + (lane & 3);
    g_WfragH2h[idx] = make_float2(tf32f(W_h2h[n * HH + k0]),
                                  tf32f(W_h2h[n * HH + k0 + 4]));
}

__global__ void __launch_bounds__(1024) pack_oh(
    const float* __restrict__ W_ih,
    const float* __restrict__ b_ih, const float* __restrict__ b_hh)
{
    const int c  = blockIdx.x;
    const int np = threadIdx.x;
    const int row = packed_gate_row(np);
    g_WohP[(size_t)c * 1024 + np] = W_ih[(size_t)row * DCC + 256 + c];
    if (c == 0) g_biasP[np] = b_ih[row] + b_hh[row];
}

__global__ void __launch_bounds__(1024) pack_bh(const float* __restrict__ bH)
{
    const size_t i = ((size_t)blockIdx.x * 1024 + threadIdx.x) * 4;
    const float4 v = *(const float4*)(bH + i);
    __half2 h0 = __floats2half2_rn(v.x, v.y);
    __half2 h1 = __floats2half2_rn(v.z, v.w);
    *(__half2*)(g_bhH + i)     = h0;
    *(__half2*)(g_bhH + i + 2) = h1;
}

// ---------------------------------------------------------------------------
// tf32 mma GEMM: out[M,N] = A[M,256] * B[N,256]^T (+bias), BM=64, BN=128,
// K=256 smem-resident. GEN=false: A=batch_H, out=g_Hproj (half).
// GEN=true: A=g_hidden, out=d_out (float, +bias, N<1000 guard).
// ---------------------------------------------------------------------------
template<bool GEN>
__global__ void __launch_bounds__(256) mm_tf32_kernel(
    const float* __restrict__ Ain, const float* __restrict__ B,
    const float* __restrict__ bias, float* __restrict__ outp)
{
    extern __shared__ float smx[];
    float* sh_a = smx;                 // 64 x MMS
    float* sh_b = smx + 64 * MMS;      // 128 x MMS

    const float* A = GEN ? g_hidden : Ain;
    const int tid = threadIdx.x;
    const int w = tid >> 5, lane = tid & 31;
    const int g = lane >> 2, tq = lane & 3;
    const int bm = blockIdx.x * 64;
    const int bn = blockIdx.y * 128;
    const int rsub = lane >> 4;        // 0,1
    const int c4   = lane & 15;        // float4 col within row

    // Load A tile (64 x 256): warp w -> rows w*8..w*8+7, 2 rows per LDG pass
    #pragma unroll
    for (int rg = 0; rg < 4; rg++) {
        const int r = w * 8 + rg * 2 + rsub;
        const float* src = A + (size_t)(bm + r) * 256;
        float* dst = sh_a + r * MMS;
        #pragma unroll
        for (int i = 0; i < 4; i++) {
            const int c = (c4 + 16 * i) * 4;
            float4 v = *(const float4*)(src + c);
            dst[c]   = tf32f(v.x); dst[c+1] = tf32f(v.y);
            dst[c+2] = tf32f(v.z); dst[c+3] = tf32f(v.w);
        }
    }
    // Load B tile (128 x 256): warp w -> rows w*16..w*16+15
    #pragma unroll
    for (int rg = 0; rg < 8; rg++) {
        const int r = w * 16 + rg * 2 + rsub;
        const int gn = bn + r;
        const bool ok = !GEN || (gn < CC);
        const float* src = B + (size_t)gn * 256;
        float* dst = sh_b + r * MMS;
        #pragma unroll
        for (int i = 0; i < 4; i++) {
            const int c = (c4 + 16 * i) * 4;
            float4 v = ok ? *(const float4*)(src + c) : make_float4(0.f,0.f,0.f,0.f);
            dst[c]   = tf32f(v.x); dst[c+1] = tf32f(v.y);
            dst[c+2] = tf32f(v.z); dst[c+3] = tf32f(v.w);
        }
    }
    __syncthreads();

    const int mr = w & 3;          // m16 tile row
    const int nh = w >> 2;         // n64 half
    float acc[8][4];
    #pragma unroll
    for (int jt = 0; jt < 8; jt++)
        #pragma unroll
        for (int q = 0; q < 4; q++) acc[jt][q] = 0.f;

    const float* arow0 = sh_a + (mr * 16 + g) * MMS;
    const float* arow1 = sh_a + (mr * 16 + g + 8) * MMS;
    #pragma unroll 4
    for (int kt = 0; kt < 32; kt++) {
        const int k0 = kt * 8 + tq;
        uint32_t a0 = __float_as_uint(arow0[k0]);
        uint32_t a1 = __float_as_uint(arow1[k0]);
        uint32_t a2 = __float_as_uint(arow0[k0 + 4]);
        uint32_t a3 = __float_as_uint(arow1[k0 + 4]);
        #pragma unroll
        for (int jt = 0; jt < 8; jt++) {
            const float* brow = sh_b + (nh * 64 + jt * 8 + g) * MMS;
            uint32_t b0 = __float_as_uint(brow[k0]);
            uint32_t b1 = __float_as_uint(brow[k0 + 4]);
            mma_tf32(acc[jt], a0, a1, a2, a3, b0, b1);
        }
    }

    // Epilogue
    #pragma unroll
    for (int jt = 0; jt < 8; jt++) {
        const int n = bn + nh * 64 + jt * 8 + 2 * tq;
        const int m0g = bm + mr * 16 + g;
        if (GEN) {
            if (n < CC) {
                const float b0 = bias[n], b1 = bias[n + 1];
                *(float2*)(outp + (size_t)m0g * CC + n) =
                    make_float2(acc[jt][0] + b0, acc[jt][1] + b1);
                *(float2*)(outp + (size_t)(m0g + 8) * CC + n) =
                    make_float2(acc[jt][2] + b0, acc[jt][3] + b1);
            }
        } else {
            *(__half2*)(g_Hproj + (size_t)m0g * HH + n) =
                __floats2half2_rn(acc[jt][0], acc[jt][1]);
            *(__half2*)(g_Hproj + (size_t)(m0g + 8) * HH + n) =
                __floats2half2_rn(acc[jt][2], acc[jt][3]);
        }
    }
}

// ---------------------------------------------------------------------------
// Persistent recurrence. 128 CTAs x 512 threads. Gates + h2h via tf32 mma.
// ---------------------------------------------------------------------------
__global__ void __launch_bounds__(512) recur_kernel(
    const int* __restrict__ text,
    const float* __restrict__ b_h2h, const float* __restrict__ W_score)
{
    extern __shared__ float sm[];
    float* sh_x   = sm;                      // 16 x XS: [0,256)=ctx, [256,512)=h (tf32)
    float* sh_hp  = sh_x  + MROWS * XS;      // 16 x 256
    float* sh_e   = sh_hp + MROWS * HH;      // 16 x 64
    float* sh_ws  = sh_e  + MROWS * TT;      // 256
    int*   sh_ch  = (int*)(sh_ws + HH);      // 16

    const int tid  = threadIdx.x;
    const int w    = tid >> 5;       // warp 0..15
    const int lane = tid & 31;
    const int g    = lane >> 2;      // fragment row group 0..7
    const int tq   = lane & 3;       // fragment quad col
    const int r0   = blockIdx.x * MROWS;

    for (int i = tid; i < MROWS * XS; i += 512) sh_x[i] = 0.f;
    if (tid < 256) sh_ws[tid] = W_score[tid];

    float cst0[4] = {0.f, 0.f, 0.f, 0.f};
    float cst1[4] = {0.f, 0.f, 0.f, 0.f};

    float2 bh2h_r[2];
    #pragma unroll
    for (int jt = 0; jt < 2; jt++) {
        const int nc = w * 16 + jt * 8 + 2 * tq;
        bh2h_r[jt] = make_float2(b_h2h[nc], b_h2h[nc + 1]);
    }
    __syncthreads();

    for (int s = 0; s < SS; s++) {
        if (tid < MROWS) sh_ch[tid] = text[(r0 + tid) * SS + s];

        // ---- Stage 1: hp = h @ W_h2h^T + b  (tf32 mma) --------------------
        {
            float accH[2][4];
            #pragma unroll
            for (int jt = 0; jt < 2; jt++) {
                accH[jt][0] = bh2h_r[jt].x; accH[jt][1] = bh2h_r[jt].y;
                accH[jt][2] = bh2h_r[jt].x; accH[jt][3] = bh2h_r[jt].y;
            }
            const float2* bp0 = g_WfragH2h + ((size_t)(w * 2    ) * 32) * 32 + lane;
            const float2* bp1 = g_WfragH2h + ((size_t)(w * 2 + 1) * 32) * 32 + lane;
            #pragma unroll 2
            for (int kt = 0; kt < 32; kt++) {
                const float* xk = sh_x + 256 + kt * 8;
                uint32_t a0 = __float_as_uint(xk[ g      * XS + tq]);
                uint32_t a1 = __float_as_uint(xk[(g + 8) * XS + tq]);
                uint32_t a2 = __float_as_uint(xk[ g      * XS + tq + 4]);
                uint32_t a3 = __float_as_uint(xk[(g + 8) * XS + tq + 4]);
                float2 b0 = bp0[kt * 32];
                float2 b1 = bp1[kt * 32];
                mma_tf32(accH[0], a0, a1, a2, a3,
                         __float_as_uint(b0.x), __float_as_uint(b0.y));
                mma_tf32(accH[1], a0, a1, a2, a3,
                         __float_as_uint(b1.x), __float_as_uint(b1.y));
            }
            #pragma unroll
            for (int jt = 0; jt < 2; jt++) {
                const int nc = w * 16 + jt * 8 + 2 * tq;
                *(float2*)(sh_hp +  g      * HH + nc) = make_float2(accH[jt][0], accH[jt][1]);
                *(float2*)(sh_hp + (g + 8) * HH + nc) = make_float2(accH[jt][2], accH[jt][3]);
            }
        }
        __syncthreads();

        // ---- Stage 2: e[m,t] = Wscore . tanh(Hproj + hp), fp16 Hproj ------
        for (int pb = w * 4; pb < MROWS * TT; pb += 64) {
            float sum[4];
            #pragma unroll
            for (int q = 0; q < 4; q++) sum[q] = 0.f;
            #pragma unroll
            for (int i = 0; i < 2; i++) {
                const int h0 = i * 128 + lane * 4;
                const float4 wv = *(const float4*)(sh_ws + h0);
                #pragma unroll
                for (int q = 0; q < 4; q++) {
                    const int pp = pb + q;
                    const int m = pp >> 6, t = pp & 63;
                    const uint2 raw = *(const uint2*)(g_Hproj +
                        ((size_t)(r0 + m) * TT + t) * HH + h0);
                    const float2 f0 = __half22float2(*(const __half2*)&raw.x);
                    const float2 f1 = __half22float2(*(const __half2*)&raw.y);
                    const float4 b = *(const float4*)(sh_hp + m * HH + h0);
                    sum[q] += wv.x * ftanh(f0.x + b.x) + wv.y * ftanh(f0.y + b.y)
                            + wv.z * ftanh(f1.x + b.z) + wv.w * ftanh(f1.y + b.w);
                }
            }
            #pragma unroll
            for (int q = 0; q < 4; q++) {
                float sq = sum[q];
                #pragma unroll
                for (int o = 16; o > 0; o >>= 1)
                    sq += __shfl_xor_sync(0xffffffffu, sq, o);
                if (lane == 0) sh_e[pb + q] = sq;
            }
        }
        __syncthreads();

        // ---- Stage 3: softmax over t, 1 row per warp ----------------------
        {
            const int m = w;
            float e0 = sh_e[m * TT + lane];
            float e1 = sh_e[m * TT + 32 + lane];
            float mx = fmaxf(e0, e1);
            #pragma unroll
            for (int o = 16; o > 0; o >>= 1)
                mx = fmaxf(mx, __shfl_xor_sync(0xffffffffu, mx, o));
            float x0 = __expf(e0 - mx), x1 = __expf(e1 - mx);
            float sume = x0 + x1;
            #pragma unroll
            for (int o = 16; o > 0; o >>= 1)
                sume += __shfl_xor_sync(0xffffffffu, sume, o);
            float inv = __frcp_rn(sume);
            sh_e[m * TT + lane]      = x0 * inv;
            sh_e[m * TT + 32 + lane] = x1 * inv;
        }
        __syncthreads();

        // ---- Stage 4: ctx from fp16 batch_H copy --------------------------
        {
            const int dg = tid & 63;
            const int mg = tid >> 6;
            #pragma unroll
            for (int mi = 0; mi < 2; mi++) {
                const int m = mg * 2 + mi;
                const __half* bh = g_bhH + ((size_t)(r0 + m) * TT) * DD + dg * 4;
                float4 acc = make_float4(0.f, 0.f, 0.f, 0.f);
                #pragma unroll 8
                for (int t = 0; t < TT; t++) {
                    const float a = sh_e[m * TT + t];
                    const uint2 raw = *(const uint2*)(bh + (size_t)t * DD);
                    const float2 v0 = __half22float2(*(const __half2*)&raw.x);
                    const float2 v1 = __half22float2(*(const __half2*)&raw.y);
                    acc.x += a * v0.x; acc.y += a * v0.y;
                    acc.z += a * v1.x; acc.w += a * v1.y;
                }
                float4 r;
                r.x = __uint_as_float(tf32_bits(acc.x));
                r.y = __uint_as_float(tf32_bits(acc.y));
                r.z = __uint_as_float(tf32_bits(acc.z));
                r.w = __uint_as_float(tf32_bits(acc.w));
                *(float4*)(sh_x + m * XS + dg * 4) = r;
            }
        }
        __syncthreads();

        // ---- Stage 5: gates (tf32 mma) + LSTM -----------------------------
        {
            const int chg  = sh_ch[g];
            const int chg8 = sh_ch[g + 8];
            float accIF[4][4], accGO[4][4];
            #pragma unroll
            for (int jt = 0; jt < 4; jt++) {
                const int nIF = w * 32 + jt * 8 + 2 * tq;
                const float2 bIF = *(const float2*)(g_biasP + nIF);
                const float2 bGO = *(const float2*)(g_biasP + 512 + nIF);
                const float2 oIg  = *(const float2*)(g_WohP + (size_t)chg  * 1024 + nIF);
                const float2 oIg8 = *(const float2*)(g_WohP + (size_t)chg8 * 1024 + nIF);
                const float2 oGg  = *(const float2*)(g_WohP + (size_t)chg  * 1024 + 512 + nIF);
                const float2 oGg8 = *(const float2*)(g_WohP + (size_t)chg8 * 1024 + 512 + nIF);
                accIF[jt][0] = bIF.x + oIg.x;  accIF[jt][1] = bIF.y + oIg.y;
                accIF[jt][2] = bIF.x + oIg8.x; accIF[jt][3] = bIF.y + oIg8.y;
                accGO[jt][0] = bGO.x + oGg.x;  accGO[jt][1] = bGO.y + oGg.y;
                accGO[jt][2] = bGO.x + oGg8.x; accGO[jt][3] = bGO.y + oGg8.y;
            }
            const float2* bIFp = g_WfragGates + (size_t)(w * 4)      * 64 * 32 + lane;
            const float2* bGOp = g_WfragGates + (size_t)(64 + w * 4) * 64 * 32 + lane;
            #pragma unroll 2
            for (int kt = 0; kt < 64; kt++) {
                const float* xk = sh_x + kt * 8;
                uint32_t a0 = __float_as_uint(xk[ g      * XS + tq]);
                uint32_t a1 = __float_as_uint(xk[(g + 8) * XS + tq]);
                uint32_t a2 = __float_as_uint(xk[ g      * XS + tq + 4]);
                uint32_t a3 = __float_as_uint(xk[(g + 8) * XS + tq + 4]);
                #pragma unroll
                for (int jt = 0; jt < 4; jt++) {
                    const float2 bv = bIFp[(jt * 64 + kt) * 32];
                    mma_tf32(accIF[jt], a0, a1, a2, a3,
                             __float_as_uint(bv.x), __float_as_uint(bv.y));
                    const float2 bw = bGOp[(jt * 64 + kt) * 32];
                    mma_tf32(accGO[jt], a0, a1, a2, a3,
                             __float_as_uint(bw.x), __float_as_uint(bw.y));
                }
            }
            __syncthreads();   // all sh_x reads done before h overwrite
            #pragma unroll
            for (int jt = 0; jt < 4; jt++) {
                const int u = w * 16 + jt * 4 + tq;
                {
                    const float cnew = fsig(accIF[jt][1]) * cst0[jt]
                                     + fsig(accIF[jt][0]) * ftanh(accGO[jt][0]);
                    cst0[jt] = cnew;
                    const float hv = fsig(accGO[jt][1]) * ftanh(cnew);
                    g_hidden[((size_t)(r0 + g) * SS + s) * HH + u] = hv;
                    sh_x[g * XS + 256 + u] = __uint_as_float(tf32_bits(hv));
                }
                {
                    const float cnew = fsig(accIF[jt][3]) * cst1[jt]
                                     + fsig(accIF[jt][2]) * ftanh(accGO[jt][2]);
                    cst1[jt] = cnew;
                    const float hv = fsig(accGO[jt][3]) * ftanh(cnew);
                    g_hidden[((size_t)(r0 + g + 8) * SS + s) * HH + u] = hv;
                    sh_x[(g + 8) * XS + 256 + u] = __uint_as_float(tf32_bits(hv));
                }
            }
        }
        __syncthreads();
    }
}

// ---------------------------------------------------------------------------
extern "C" void kernel_launch(void* const* d_in, const int* in_sizes, int n_in,
                              void* d_out, int out_size)
{
    const float* batch_H = (const float*)d_in[0];
    const int*   text    = (const int*)  d_in[1];
    const float* W_i2h   = (const float*)d_in[2];
    const float* W_h2h   = (const float*)d_in[3];
    const float* b_h2h   = (const float*)d_in[4];
    const float* W_score = (const float*)d_in[5];
    const float* W_ih    = (const float*)d_in[6];
    const float* W_hh    = (const float*)d_in[7];
    const float* b_ih    = (const float*)d_in[8];
    const float* b_hh    = (const float*)d_in[9];
    const float* W_gen   = (const float*)d_in[10];
    const float* b_gen   = (const float*)d_in[11];
    float* out = (float*)d_out;

    pack_gates<<<256, 1024>>>(W_ih, W_hh);
    pack_h2h<<<32, 1024>>>(W_h2h);
    pack_oh<<<1000, 1024>>>(W_ih, b_ih, b_hh);
    pack_bh<<<(BB * TT * DD) / 4096, 1024>>>(batch_H);

    cudaFuncSetAttribute(mm_tf32_kernel<false>,
                         cudaFuncAttributeMaxDynamicSharedMemorySize, MM_SMEM);
    cudaFuncSetAttribute(mm_tf32_kernel<true>,
                         cudaFuncAttributeMaxDynamicSharedMemorySize, MM_SMEM);

    // H_proj: M=131072, N=256 -> grid (2048, 2)
    mm_tf32_kernel<false><<<dim3((BB * TT) / 64, 2), 256, MM_SMEM>>>(
        batch_H, W_i2h, nullptr, nullptr);

    const int smem_bytes = (MROWS * XS + MROWS * HH + MROWS * TT + HH) * 4 + MROWS * 4;
    cudaFuncSetAttribute(recur_kernel, cudaFuncAttributeMaxDynamicSharedMemorySize,
                         smem_bytes);
    recur_kernel<<<BB / MROWS, 512, smem_bytes>>>(text, b_h2h, W_score);

    // probs: M=53248, N=1000 -> grid (832, 8)
    mm_tf32_kernel<true><<<dim3((BB * SS) / 64, 8), 256, MM_SMEM>>>(
        nullptr, W_gen, b_gen, out);
}

// round 10
// speedup vs baseline: 1.2406x; 1.2406x over previous
#include <cuda_runtime.h>
#include <cuda_fp16.h>
#include <cstdint>

#define BB   2048
#define TT   64
#define DD   256
#define HH   256
#define CC   1000
#define SS   26
#define DCC  1256   // D + C
#define MROWS 16    // batch rows per recurrence CTA
#define XS   516    // sh_x row stride (floats): conflict-free frags

// Scratch (allocation-free: __device__ globals)
__device__ __half g_Hproj[(size_t)BB * TT * HH];   // 64 MB (fp16)
__device__ __half g_bhH[(size_t)BB * TT * DD];     // 64 MB fp16 copy of batch_H
__device__ float  g_hidden[(size_t)BB * SS * HH];  // 52 MB
__device__ float2 g_WfragGates[128 * 64 * 32];     // 2 MB   B-frags, gates GEMM
__device__ float2 g_WfragH2h[32 * 32 * 32];        // 256 KB B-frags, h2h GEMM
__device__ float  g_WohP[1000 * 1024];             // 4 MB   one-hot cols, packed
__device__ float  g_biasP[1024];                   // b_ih+b_hh, packed order

__device__ __forceinline__ float ftanh(float x) {
    float y;
    asm("tanh.approx.f32 %0, %1;" : "=f"(y) : "f"(x));
    return y;
}
__device__ __forceinline__ float fsig(float x) {
    return 0.5f * ftanh(0.5f * x) + 0.5f;
}
__device__ __forceinline__ uint32_t tf32_bits(float x) {
    uint32_t r;
    asm("cvt.rna.tf32.f32 %0, %1;" : "=r"(r) : "f"(x));
    return r;
}
__device__ __forceinline__ float tf32f(float x) {
    return __uint_as_float(tf32_bits(x));
}
__device__ __forceinline__ void mma_tf32(float* c,
    uint32_t a0, uint32_t a1, uint32_t a2, uint32_t a3,
    uint32_t b0, uint32_t b1)
{
    asm volatile(
        "mma.sync.aligned.m16n8k8.row.col.f32.tf32.tf32.f32 "
        "{%0,%1,%2,%3}, {%4,%5,%6,%7}, {%8,%9}, {%0,%1,%2,%3};"
        : "+f"(c[0]), "+f"(c[1]), "+f"(c[2]), "+f"(c[3])
        : "r"(a0), "r"(a1), "r"(a2), "r"(a3), "r"(b0), "r"(b1));
}

__device__ __forceinline__ int packed_gate_row(int nprime) {
    const int np = nprime & 511, u = np >> 1, b = np & 1;
    const bool go = nprime >= 512;
    return u + (go ? (b ? 768 : 512) : (b ? 256 : 0));   // rows: i|f|g|o
}

// ---------------------------------------------------------------------------
// Pack kernels
// ---------------------------------------------------------------------------
__global__ void __launch_bounds__(1024) pack_gates(
    const float* __restrict__ W_ih, const float* __restrict__ W_hh)
{
    const int idx = blockIdx.x * 1024 + threadIdx.x;
    const int lane = idx & 31;
    const int kt   = (idx >> 5) & 63;
    const int nt   = idx >> 11;
    const int npr  = (nt & 63) * 8 + (lane >> 2) + ((nt >= 64) ? 512 : 0);
    const int row  = packed_gate_row(npr);
    const int k0   = kt * 8 + (lane & 3);
    const int k1   = k0 + 4;
    const float v0 = (k0 < 256) ? W_ih[(size_t)row * DCC + k0]
                                : W_hh[(size_t)row * HH + k0 - 256];
    const float v1 = (k1 < 256) ? W_ih[(size_t)row * DCC + k1]
                                : W_hh[(size_t)row * HH + k1 - 256];
    g_WfragGates[idx] = make_float2(tf32f(v0), tf32f(v1));
}

__global__ void __launch_bounds__(1024) pack_h2h(const float* __restrict__ W_h2h)
{
    const int idx = blockIdx.x * 1024 + threadIdx.x;
    const int lane = idx & 31;
    const int kt   = (idx >> 5) & 31;
    const int nt   = idx >> 10;
    const int n    = nt * 8 + (lane >> 2);
    const int k0   = kt * 8 + (lane & 3);
    g_WfragH2h[idx] = make_float2(tf32f(W_h2h[n * HH + k0]),
                                  tf32f(W_h2h[n * HH + k0 + 4]));
}

__global__ void __launch_bounds__(1024) pack_oh(
    const float* __restrict__ W_ih,
    const float* __restrict__ b_ih, const float* __restrict__ b_hh)
{
    const int c  = blockIdx.x;
    const int np = threadIdx.x;
    const int row = packed_gate_row(np);
    g_WohP[(size_t)c * 1024 + np] = W_ih[(size_t)row * DCC + 256 + c];
    if (c == 0) g_biasP[np] = b_ih[row] + b_hh[row];
}

__global__ void __launch_bounds__(1024) pack_bh(const float* __restrict__ bH)
{
    const size_t i = ((size_t)blockIdx.x * 1024 + threadIdx.x) * 4;
    const float4 v = *(const float4*)(bH + i);
    *(__half2*)(g_bhH + i)     = __floats2half2_rn(v.x, v.y);
    *(__half2*)(g_bhH + i + 2) = __floats2half2_rn(v.z, v.w);
}

// ---------------------------------------------------------------------------
// SIMT NT GEMM 128x128x8, double-buffered (measured-good). Writes fp16 Hproj.
// ---------------------------------------------------------------------------
__global__ void __launch_bounds__(256) hproj_kernel(
    const float* __restrict__ A, const float* __restrict__ W)
{
    __shared__ float As[2][8][132];
    __shared__ float Ws[2][8][132];
    const int bm = blockIdx.x * 128;
    const int bn = blockIdx.y * 128;
    const int tid = threadIdx.x;
    const int tx = tid & 15, ty = tid >> 4;
    const int lr = tid >> 1;
    const int lk = (tid & 1) * 4;

    const float* arow = A + (size_t)(bm + lr) * DD + lk;
    const float* wrow = W + (size_t)(bn + lr) * DD + lk;

    {
        float4 av = *(const float4*)arow;
        float4 wv = *(const float4*)wrow;
        As[0][lk+0][lr]=av.x; As[0][lk+1][lr]=av.y; As[0][lk+2][lr]=av.z; As[0][lk+3][lr]=av.w;
        Ws[0][lk+0][lr]=wv.x; Ws[0][lk+1][lr]=wv.y; Ws[0][lk+2][lr]=wv.z; Ws[0][lk+3][lr]=wv.w;
    }
    __syncthreads();

    float acc[8][8] = {};
    int p = 0;
    const int KT = DD / 8;
    for (int kt = 0; kt < KT; kt++) {
        float4 nav, nwv;
        const bool more = (kt + 1 < KT);
        if (more) {
            nav = *(const float4*)(arow + (kt + 1) * 8);
            nwv = *(const float4*)(wrow + (kt + 1) * 8);
        }
        #pragma unroll
        for (int kk = 0; kk < 8; kk++) {
            float4 a0 = *(const float4*)&As[p][kk][ty * 8];
            float4 a1 = *(const float4*)&As[p][kk][ty * 8 + 4];
            float4 b0 = *(const float4*)&Ws[p][kk][tx * 8];
            float4 b1 = *(const float4*)&Ws[p][kk][tx * 8 + 4];
            float a[8] = {a0.x,a0.y,a0.z,a0.w,a1.x,a1.y,a1.z,a1.w};
            float b[8] = {b0.x,b0.y,b0.z,b0.w,b1.x,b1.y,b1.z,b1.w};
            #pragma unroll
            for (int i = 0; i < 8; i++)
                #pragma unroll
                for (int j = 0; j < 8; j++)
                    acc[i][j] += a[i] * b[j];
        }
        if (more) {
            const int q = p ^ 1;
            As[q][lk+0][lr]=nav.x; As[q][lk+1][lr]=nav.y; As[q][lk+2][lr]=nav.z; As[q][lk+3][lr]=nav.w;
            Ws[q][lk+0][lr]=nwv.x; Ws[q][lk+1][lr]=nwv.y; Ws[q][lk+2][lr]=nwv.z; Ws[q][lk+3][lr]=nwv.w;
        }
        __syncthreads();
        p ^= 1;
    }
    #pragma unroll
    for (int i = 0; i < 8; i++) {
        __half* dst = g_Hproj + (size_t)(bm + ty * 8 + i) * HH + bn + tx * 8;
        uint4 pk;
        *(__half2*)&pk.x = __floats2half2_rn(acc[i][0], acc[i][1]);
        *(__half2*)&pk.y = __floats2half2_rn(acc[i][2], acc[i][3]);
        *(__half2*)&pk.z = __floats2half2_rn(acc[i][4], acc[i][5]);
        *(__half2*)&pk.w = __floats2half2_rn(acc[i][6], acc[i][7]);
        *(uint4*)dst = pk;
    }
}

__global__ void __launch_bounds__(256) gen_kernel(
    const float* __restrict__ Wg, const float* __restrict__ bg,
    float* __restrict__ out)
{
    __shared__ float As[2][8][132];
    __shared__ float Ws[2][8][132];
    const int bm = blockIdx.x * 128;
    const int bn = blockIdx.y * 128;
    const int tid = threadIdx.x;
    const int tx = tid & 15, ty = tid >> 4;
    const int lr = tid >> 1;
    const int lk = (tid & 1) * 4;

    const float* arow = g_hidden + (size_t)(bm + lr) * HH + lk;
    const bool wok = (bn + lr < CC);
    const float* wrow = Wg + (size_t)(bn + lr) * HH + lk;

    {
        float4 av = *(const float4*)arow;
        float4 wv = wok ? *(const float4*)wrow : make_float4(0.f,0.f,0.f,0.f);
        As[0][lk+0][lr]=av.x; As[0][lk+1][lr]=av.y; As[0][lk+2][lr]=av.z; As[0][lk+3][lr]=av.w;
        Ws[0][lk+0][lr]=wv.x; Ws[0][lk+1][lr]=wv.y; Ws[0][lk+2][lr]=wv.z; Ws[0][lk+3][lr]=wv.w;
    }
    __syncthreads();

    float acc[8][8] = {};
    int p = 0;
    const int KT = HH / 8;
    for (int kt = 0; kt < KT; kt++) {
        float4 nav, nwv;
        const bool more = (kt + 1 < KT);
        if (more) {
            nav = *(const float4*)(arow + (kt + 1) * 8);
            nwv = wok ? *(const float4*)(wrow + (kt + 1) * 8) : make_float4(0.f,0.f,0.f,0.f);
        }
        #pragma unroll
        for (int kk = 0; kk < 8; kk++) {
            float4 a0 = *(const float4*)&As[p][kk][ty * 8];
            float4 a1 = *(const float4*)&As[p][kk][ty * 8 + 4];
            float4 b0 = *(const float4*)&Ws[p][kk][tx * 8];
            float4 b1 = *(const float4*)&Ws[p][kk][tx * 8 + 4];
            float a[8] = {a0.x,a0.y,a0.z,a0.w,a1.x,a1.y,a1.z,a1.w};
            float b[8] = {b0.x,b0.y,b0.z,b0.w,b1.x,b1.y,b1.z,b1.w};
            #pragma unroll
            for (int i = 0; i < 8; i++)
                #pragma unroll
                for (int j = 0; j < 8; j++)
                    acc[i][j] += a[i] * b[j];
        }
        if (more) {
            const int q = p ^ 1;
            As[q][lk+0][lr]=nav.x; As[q][lk+1][lr]=nav.y; As[q][lk+2][lr]=nav.z; As[q][lk+3][lr]=nav.w;
            Ws[q][lk+0][lr]=nwv.x; Ws[q][lk+1][lr]=nwv.y; Ws[q][lk+2][lr]=nwv.z; Ws[q][lk+3][lr]=nwv.w;
        }
        __syncthreads();
        p ^= 1;
    }
    #pragma unroll
    for (int i = 0; i < 8; i++) {
        const int m = bm + ty * 8 + i;
        #pragma unroll
        for (int j = 0; j < 8; j++) {
            const int nn = bn + tx * 8 + j;
            if (nn < CC) out[(size_t)m * CC + nn] = acc[i][j] + bg[nn];
        }
    }
}

// ---------------------------------------------------------------------------
// Persistent recurrence. 128 CTAs x 512 threads. Gates + h2h via tf32 mma.
// fp16 streams for Hproj (stage 2) and batch_H (stage 4).
// ---------------------------------------------------------------------------
__global__ void __launch_bounds__(512) recur_kernel(
    const int* __restrict__ text,
    const float* __restrict__ b_h2h, const float* __restrict__ W_score)
{
    extern __shared__ float sm[];
    float* sh_x   = sm;                      // 16 x XS: [0,256)=ctx, [256,512)=h (tf32)
    float* sh_hp  = sh_x  + MROWS * XS;      // 16 x 256
    float* sh_e   = sh_hp + MROWS * HH;      // 16 x 64
    int*   sh_ch  = (int*)(sh_e + MROWS * TT); // 16

    const int tid  = threadIdx.x;
    const int w    = tid >> 5;       // warp 0..15
    const int lane = tid & 31;
    const int g    = lane >> 2;      // fragment row group 0..7
    const int tq   = lane & 3;       // fragment quad col
    const int r0   = blockIdx.x * MROWS;

    for (int i = tid; i < MROWS * XS; i += 512) sh_x[i] = 0.f;

    float cst0[4] = {0.f, 0.f, 0.f, 0.f};
    float cst1[4] = {0.f, 0.f, 0.f, 0.f};

    // W_score slice for stage 2 (this lane covers h = lane*8 .. lane*8+7)
    float wsr[8];
    #pragma unroll
    for (int j = 0; j < 8; j++) wsr[j] = W_score[lane * 8 + j];

    float2 bh2h_r[2];
    #pragma unroll
    for (int jt = 0; jt < 2; jt++) {
        const int nc = w * 16 + jt * 8 + 2 * tq;
        bh2h_r[jt] = make_float2(b_h2h[nc], b_h2h[nc + 1]);
    }
    __syncthreads();

    for (int s = 0; s < SS; s++) {
        if (tid < MROWS) sh_ch[tid] = text[(r0 + tid) * SS + s];

        // ---- Stage 1: hp = h @ W_h2h^T + b  (tf32 mma) --------------------
        {
            float accH[2][4];
            #pragma unroll
            for (int jt = 0; jt < 2; jt++) {
                accH[jt][0] = bh2h_r[jt].x; accH[jt][1] = bh2h_r[jt].y;
                accH[jt][2] = bh2h_r[jt].x; accH[jt][3] = bh2h_r[jt].y;
            }
            const float2* bp0 = g_WfragH2h + ((size_t)(w * 2    ) * 32) * 32 + lane;
            const float2* bp1 = g_WfragH2h + ((size_t)(w * 2 + 1) * 32) * 32 + lane;
            #pragma unroll 2
            for (int kt = 0; kt < 32; kt++) {
                const float* xk = sh_x + 256 + kt * 8;
                uint32_t a0 = __float_as_uint(xk[ g      * XS + tq]);
                uint32_t a1 = __float_as_uint(xk[(g + 8) * XS + tq]);
                uint32_t a2 = __float_as_uint(xk[ g      * XS + tq + 4]);
                uint32_t a3 = __float_as_uint(xk[(g + 8) * XS + tq + 4]);
                float2 b0 = bp0[kt * 32];
                float2 b1 = bp1[kt * 32];
                mma_tf32(accH[0], a0, a1, a2, a3,
                         __float_as_uint(b0.x), __float_as_uint(b0.y));
                mma_tf32(accH[1], a0, a1, a2, a3,
                         __float_as_uint(b1.x), __float_as_uint(b1.y));
            }
            #pragma unroll
            for (int jt = 0; jt < 2; jt++) {
                const int nc = w * 16 + jt * 8 + 2 * tq;
                *(float2*)(sh_hp +  g      * HH + nc) = make_float2(accH[jt][0], accH[jt][1]);
                *(float2*)(sh_hp + (g + 8) * HH + nc) = make_float2(accH[jt][2], accH[jt][3]);
            }
        }
        __syncthreads();

        // ---- Stage 2: e[m,t] = Wscore . tanh(Hproj + hp), one LDG.128/row -
        for (int pb = w * 4; pb < MROWS * TT; pb += 64) {
            float sum[4];
            #pragma unroll
            for (int q = 0; q < 4; q++) {
                const int pp = pb + q;
                const int m = pp >> 6, t = pp & 63;
                const uint4 raw = *(const uint4*)(g_Hproj +
                    ((size_t)(r0 + m) * TT + t) * HH + lane * 8);
                const __half2* hr = (const __half2*)&raw;
                const float4 b0 = *(const float4*)(sh_hp + m * HH + lane * 8);
                const float4 b1 = *(const float4*)(sh_hp + m * HH + lane * 8 + 4);
                const float2 f0 = __half22float2(hr[0]);
                const float2 f1 = __half22float2(hr[1]);
                const float2 f2 = __half22float2(hr[2]);
                const float2 f3 = __half22float2(hr[3]);
                sum[q] = wsr[0] * ftanh(f0.x + b0.x) + wsr[1] * ftanh(f0.y + b0.y)
                       + wsr[2] * ftanh(f1.x + b0.z) + wsr[3] * ftanh(f1.y + b0.w)
                       + wsr[4] * ftanh(f2.x + b1.x) + wsr[5] * ftanh(f2.y + b1.y)
                       + wsr[6] * ftanh(f3.x + b1.z) + wsr[7] * ftanh(f3.y + b1.w);
            }
            #pragma unroll
            for (int q = 0; q < 4; q++) {
                float sq = sum[q];
                #pragma unroll
                for (int o = 16; o > 0; o >>= 1)
                    sq += __shfl_xor_sync(0xffffffffu, sq, o);
                if (lane == 0) sh_e[pb + q] = sq;
            }
        }
        __syncthreads();

        // ---- Stage 3: softmax over t, 1 row per warp ----------------------
        {
            const int m = w;
            float e0 = sh_e[m * TT + lane];
            float e1 = sh_e[m * TT + 32 + lane];
            float mx = fmaxf(e0, e1);
            #pragma unroll
            for (int o = 16; o > 0; o >>= 1)
                mx = fmaxf(mx, __shfl_xor_sync(0xffffffffu, mx, o));
            float x0 = __expf(e0 - mx), x1 = __expf(e1 - mx);
            float sume = x0 + x1;
            #pragma unroll
            for (int o = 16; o > 0; o >>= 1)
                sume += __shfl_xor_sync(0xffffffffu, sume, o);
            float inv = __frcp_rn(sume);
            sh_e[m * TT + lane]      = x0 * inv;
            sh_e[m * TT + 32 + lane] = x1 * inv;
        }
        __syncthreads();

        // ---- Stage 4: ctx[m,:] — warp m, lane covers d = lane*8..+8 -------
        {
            const int m = w;
            const __half* bh = g_bhH + ((size_t)(r0 + m) * TT) * DD + lane * 8;
            float acc[8] = {};
            #pragma unroll 8
            for (int t = 0; t < TT; t++) {
                const float a = sh_e[m * TT + t];
                const uint4 raw = *(const uint4*)(bh + (size_t)t * DD);
                const __half2* hr = (const __half2*)&raw;
                const float2 v0 = __half22float2(hr[0]);
                const float2 v1 = __half22float2(hr[1]);
                const float2 v2 = __half22float2(hr[2]);
                const float2 v3 = __half22float2(hr[3]);
                acc[0] += a * v0.x; acc[1] += a * v0.y;
                acc[2] += a * v1.x; acc[3] += a * v1.y;
                acc[4] += a * v2.x; acc[5] += a * v2.y;
                acc[6] += a * v3.x; acc[7] += a * v3.y;
            }
            float* dst = sh_x + m * XS + lane * 8;
            #pragma unroll
            for (int j = 0; j < 8; j++) dst[j] = tf32f(acc[j]);
        }
        __syncthreads();

        // ---- Stage 5: gates (tf32 mma) + LSTM -----------------------------
        {
            const int chg  = sh_ch[g];
            const int chg8 = sh_ch[g + 8];
            float accIF[4][4], accGO[4][4];
            #pragma unroll
            for (int jt = 0; jt < 4; jt++) {
                const int nIF = w * 32 + jt * 8 + 2 * tq;
                const float2 bIF = *(const float2*)(g_biasP + nIF);
                const float2 bGO = *(const float2*)(g_biasP + 512 + nIF);
                const float2 oIg  = *(const float2*)(g_WohP + (size_t)chg  * 1024 + nIF);
                const float2 oIg8 = *(const float2*)(g_WohP + (size_t)chg8 * 1024 + nIF);
                const float2 oGg  = *(const float2*)(g_WohP + (size_t)chg  * 1024 + 512 + nIF);
                const float2 oGg8 = *(const float2*)(g_WohP + (size_t)chg8 * 1024 + 512 + nIF);
                accIF[jt][0] = bIF.x + oIg.x;  accIF[jt][1] = bIF.y + oIg.y;
                accIF[jt][2] = bIF.x + oIg8.x; accIF[jt][3] = bIF.y + oIg8.y;
                accGO[jt][0] = bGO.x + oGg.x;  accGO[jt][1] = bGO.y + oGg.y;
                accGO[jt][2] = bGO.x + oGg8.x; accGO[jt][3] = bGO.y + oGg8.y;
            }
            const float2* bIFp = g_WfragGates + (size_t)(w * 4)      * 64 * 32 + lane;
            const float2* bGOp = g_WfragGates + (size_t)(64 + w * 4) * 64 * 32 + lane;
            #pragma unroll 2
            for (int kt = 0; kt < 64; kt++) {
                const float* xk = sh_x + kt * 8;
                uint32_t a0 = __float_as_uint(xk[ g      * XS + tq]);
                uint32_t a1 = __float_as_uint(xk[(g + 8) * XS + tq]);
                uint32_t a2 = __float_as_uint(xk[ g      * XS + tq + 4]);
                uint32_t a3 = __float_as_uint(xk[(g + 8) * XS + tq + 4]);
                #pragma unroll
                for (int jt = 0; jt < 4; jt++) {
                    const float2 bv = bIFp[(jt * 64 + kt) * 32];
                    mma_tf32(accIF[jt], a0, a1, a2, a3,
                             __float_as_uint(bv.x), __float_as_uint(bv.y));
                    const float2 bw = bGOp[(jt * 64 + kt) * 32];
                    mma_tf32(accGO[jt], a0, a1, a2, a3,
                             __float_as_uint(bw.x), __float_as_uint(bw.y));
                }
            }
            __syncthreads();   // all sh_x reads done before h overwrite
            #pragma unroll
            for (int jt = 0; jt < 4; jt++) {
                const int u = w * 16 + jt * 4 + tq;
                {
                    const float cnew = fsig(accIF[jt][1]) * cst0[jt]
                                     + fsig(accIF[jt][0]) * ftanh(accGO[jt][0]);
                    cst0[jt] = cnew;
                    const float hv = fsig(accGO[jt][1]) * ftanh(cnew);
                    g_hidden[((size_t)(r0 + g) * SS + s) * HH + u] = hv;
                    sh_x[g * XS + 256 + u] = tf32f(hv);
                }
                {
                    const float cnew = fsig(accIF[jt][3]) * cst1[jt]
                                     + fsig(accIF[jt][2]) * ftanh(accGO[jt][2]);
                    cst1[jt] = cnew;
                    const float hv = fsig(accGO[jt][3]) * ftanh(cnew);
                    g_hidden[((size_t)(r0 + g + 8) * SS + s) * HH + u] = hv;
                    sh_x[(g + 8) * XS + 256 + u] = tf32f(hv);
                }
            }
        }
        __syncthreads();
    }
}

// ---------------------------------------------------------------------------
extern "C" void kernel_launch(void* const* d_in, const int* in_sizes, int n_in,
                              void* d_out, int out_size)
{
    const float* batch_H = (const float*)d_in[0];
    const int*   text    = (const int*)  d_in[1];
    const float* W_i2h   = (const float*)d_in[2];
    const float* W_h2h   = (const float*)d_in[3];
    const float* b_h2h   = (const float*)d_in[4];
    const float* W_score = (const float*)d_in[5];
    const float* W_ih    = (const float*)d_in[6];
    const float* W_hh    = (const float*)d_in[7];
    const float* b_ih    = (const float*)d_in[8];
    const float* b_hh    = (const float*)d_in[9];
    const float* W_gen   = (const float*)d_in[10];
    const float* b_gen   = (const float*)d_in[11];
    float* out = (float*)d_out;

    pack_gates<<<256, 1024>>>(W_ih, W_hh);
    pack_h2h<<<32, 1024>>>(W_h2h);
    pack_oh<<<1000, 1024>>>(W_ih, b_ih, b_hh);
    pack_bh<<<(BB * TT * DD) / 4096, 1024>>>(batch_H);

    hproj_kernel<<<dim3((BB * TT) / 128, HH / 128), 256>>>(batch_H, W_i2h);

    const int smem_bytes = (MROWS * XS + MROWS * HH + MROWS * TT) * 4 + MROWS * 4;
    cudaFuncSetAttribute(recur_kernel, cudaFuncAttributeMaxDynamicSharedMemorySize,
                         smem_bytes);
    recur_kernel<<<BB / MROWS, 512, smem_bytes>>>(text, b_h2h, W_score);

    gen_kernel<<<dim3((BB * SS) / 128, (CC + 127) / 128), 256>>>(W_gen, b_gen, out);
}

// round 11
// speedup vs baseline: 1.5301x; 1.2334x over previous
#include <cuda_runtime.h>
#include <cuda_fp16.h>
#include <cstdint>

#define BB   2048
#define TT   64
#define DD   256
#define HH   256
#define CC   1000
#define SS   26
#define DCC  1256   // D + C
#define MROWS 16    // batch rows per recurrence CTA
#define XS   516    // sh_x row stride (floats): conflict-free frags
#define GS   36     // mm2 smem row stride (floats): conflict-free frags
#define MMBUF (384 * GS)           // floats per buffer (A 128 rows + B 256 rows)
#define MM2_SMEM (2 * MMBUF * 4)   // bytes

// Scratch (allocation-free: __device__ globals)
__device__ __half g_Hproj[(size_t)BB * TT * HH];   // 64 MB (fp16)
__device__ __half g_bhH[(size_t)BB * TT * DD];     // 64 MB fp16 copy of batch_H
__device__ float  g_hidden[(size_t)BB * SS * HH];  // 52 MB
__device__ float2 g_WfragGates[128 * 64 * 32];     // 2 MB   B-frags, gates GEMM
__device__ float2 g_WfragH2h[32 * 32 * 32];        // 256 KB B-frags, h2h GEMM
__device__ float  g_WohP[1000 * 1024];             // 4 MB   one-hot cols, packed
__device__ float  g_biasP[1024];                   // b_ih+b_hh, packed order

__device__ __forceinline__ float ftanh(float x) {
    float y;
    asm("tanh.approx.f32 %0, %1;" : "=f"(y) : "f"(x));
    return y;
}
__device__ __forceinline__ float fsig(float x) {
    return 0.5f * ftanh(0.5f * x) + 0.5f;
}
__device__ __forceinline__ uint32_t tf32_bits(float x) {
    uint32_t r;
    asm("cvt.rna.tf32.f32 %0, %1;" : "=r"(r) : "f"(x));
    return r;
}
__device__ __forceinline__ float tf32f(float x) {
    return __uint_as_float(tf32_bits(x));
}
__device__ __forceinline__ void mma_tf32(float* c,
    uint32_t a0, uint32_t a1, uint32_t a2, uint32_t a3,
    uint32_t b0, uint32_t b1)
{
    asm volatile(
        "mma.sync.aligned.m16n8k8.row.col.f32.tf32.tf32.f32 "
        "{%0,%1,%2,%3}, {%4,%5,%6,%7}, {%8,%9}, {%0,%1,%2,%3};"
        : "+f"(c[0]), "+f"(c[1]), "+f"(c[2]), "+f"(c[3])
        : "r"(a0), "r"(a1), "r"(a2), "r"(a3), "r"(b0), "r"(b1));
}
__device__ __forceinline__ void cp16(uint32_t dst, const void* src, bool pred) {
    const int sz = pred ? 16 : 0;
    asm volatile("cp.async.cg.shared.global [%0], [%1], 16, %2;"
                 :: "r"(dst), "l"(src), "r"(sz));
}

__device__ __forceinline__ int packed_gate_row(int nprime) {
    const int np = nprime & 511, u = np >> 1, b = np & 1;
    const bool go = nprime >= 512;
    return u + (go ? (b ? 768 : 512) : (b ? 256 : 0));   // rows: i|f|g|o
}

// ---------------------------------------------------------------------------
// Pack kernels
// ---------------------------------------------------------------------------
__global__ void __launch_bounds__(1024) pack_gates(
    const float* __restrict__ W_ih, const float* __restrict__ W_hh)
{
    const int idx = blockIdx.x * 1024 + threadIdx.x;
    const int lane = idx & 31;
    const int kt   = (idx >> 5) & 63;
    const int nt   = idx >> 11;
    const int npr  = (nt & 63) * 8 + (lane >> 2) + ((nt >= 64) ? 512 : 0);
    const int row  = packed_gate_row(npr);
    const int k0   = kt * 8 + (lane & 3);
    const int k1   = k0 + 4;
    const float v0 = (k0 < 256) ? W_ih[(size_t)row * DCC + k0]
                                : W_hh[(size_t)row * HH + k0 - 256];
    const float v1 = (k1 < 256) ? W_ih[(size_t)row * DCC + k1]
                                : W_hh[(size_t)row * HH + k1 - 256];
    g_WfragGates[idx] = make_float2(tf32f(v0), tf32f(v1));
}

__global__ void __launch_bounds__(1024) pack_h2h(const float* __restrict__ W_h2h)
{
    const int idx = blockIdx.x * 1024 + threadIdx.x;
    const int lane = idx & 31;
    const int kt   = (idx >> 5) & 31;
    const int nt   = idx >> 10;
    const int n    = nt * 8 + (lane >> 2);
    const int k0   = kt * 8 + (lane & 3);
    g_WfragH2h[idx] = make_float2(tf32f(W_h2h[n * HH + k0]),
                                  tf32f(W_h2h[n * HH + k0 + 4]));
}

__global__ void __launch_bounds__(1024) pack_oh(
    const float* __restrict__ W_ih,
    const float* __restrict__ b_ih, const float* __restrict__ b_hh)
{
    const int c  = blockIdx.x;
    const int np = threadIdx.x;
    const int row = packed_gate_row(np);
    g_WohP[(size_t)c * 1024 + np] = W_ih[(size_t)row * DCC + 256 + c];
    if (c == 0) g_biasP[np] = b_ih[row] + b_hh[row];
}

__global__ void __launch_bounds__(1024) pack_bh(const float* __restrict__ bH)
{
    const size_t i = ((size_t)blockIdx.x * 1024 + threadIdx.x) * 4;
    const float4 v = *(const float4*)(bH + i);
    *(__half2*)(g_bhH + i)     = __floats2half2_rn(v.x, v.y);
    *(__half2*)(g_bhH + i + 2) = __floats2half2_rn(v.z, v.w);
}

// ---------------------------------------------------------------------------
// tf32 mma GEMM: out[M,N] = A[M,256] * B[N,256]^T (+bias).
// BM=128, BN=256, BK=32, 512 threads, cp.async double-buffered.
// GEN=false: A=batch_H, out=g_Hproj (fp16). GEN=true: A=g_hidden, out (+bias).
// ---------------------------------------------------------------------------
template<bool GEN>
__global__ void __launch_bounds__(512) mm2_kernel(
    const float* __restrict__ Ain, const float* __restrict__ Bw,
    const float* __restrict__ bias, float* __restrict__ outp)
{
    extern __shared__ float sm2[];
    const int tid = threadIdx.x, w = tid >> 5, lane = tid & 31;
    const int g = lane >> 2, tq = lane & 3;
    const int bm = blockIdx.x * 128, bn = blockIdx.y * 256;
    const int mw = w & 3, nw = w >> 2;       // warp tile: rows mw*32.., cols nw*64..
    const float* A = GEN ? g_hidden : Ain;
    const uint32_t smem_base = (uint32_t)__cvta_generic_to_shared(sm2);

    float acc[2][8][4] = {};

    // ---- async tile loader: k-block kb -> buffer p ----
    auto load_block = [&](int kb, int p) {
        #pragma unroll
        for (int i = 0; i < 2; i++) {          // A: 1024 x 16B chunks
            const int chunk = tid + i * 512;
            const int row = chunk >> 3, c = chunk & 7;
            const float* src = A + (size_t)(bm + row) * 256 + kb * 32 + c * 4;
            cp16(smem_base + (uint32_t)(p * MMBUF + row * GS + c * 4) * 4, src, true);
        }
        #pragma unroll
        for (int i = 0; i < 4; i++) {          // B: 2048 x 16B chunks
            const int chunk = tid + i * 512;
            const int row = chunk >> 3, c = chunk & 7;
            const bool ok = !GEN || (bn + row < CC);
            const float* src = Bw + (size_t)(bn + row) * 256 + kb * 32 + c * 4;
            cp16(smem_base + (uint32_t)(p * MMBUF + 128 * GS + row * GS + c * 4) * 4,
                 src, ok);
        }
        asm volatile("cp.async.commit_group;");
    };

    load_block(0, 0);
    for (int kb = 0; kb < 8; kb++) {
        if (kb < 7) {
            load_block(kb + 1, (kb + 1) & 1);
            asm volatile("cp.async.wait_group 1;");
        } else {
            asm volatile("cp.async.wait_group 0;");
        }
        __syncthreads();

        const float* sa = sm2 + (kb & 1) * MMBUF + (mw * 32) * GS;
        const float* sb = sm2 + (kb & 1) * MMBUF + 128 * GS + (nw * 64) * GS;
        #pragma unroll
        for (int kt = 0; kt < 4; kt++) {
            const int k0 = kt * 8 + tq;
            uint32_t a[2][4];
            #pragma unroll
            for (int t = 0; t < 2; t++) {
                a[t][0] = tf32_bits(sa[(t * 16 + g    ) * GS + k0]);
                a[t][1] = tf32_bits(sa[(t * 16 + g + 8) * GS + k0]);
                a[t][2] = tf32_bits(sa[(t * 16 + g    ) * GS + k0 + 4]);
                a[t][3] = tf32_bits(sa[(t * 16 + g + 8) * GS + k0 + 4]);
            }
            #pragma unroll
            for (int j = 0; j < 8; j++) {
                const uint32_t b0 = tf32_bits(sb[(j * 8 + g) * GS + k0]);
                const uint32_t b1 = tf32_bits(sb[(j * 8 + g) * GS + k0 + 4]);
                mma_tf32(acc[0][j], a[0][0], a[0][1], a[0][2], a[0][3], b0, b1);
                mma_tf32(acc[1][j], a[1][0], a[1][1], a[1][2], a[1][3], b0, b1);
            }
        }
        __syncthreads();
    }

    // ---- epilogue ----
    #pragma unroll
    for (int t = 0; t < 2; t++) {
        const int row = bm + mw * 32 + t * 16 + g;
        #pragma unroll
        for (int j = 0; j < 8; j++) {
            const int col = bn + nw * 64 + j * 8 + 2 * tq;
            if (GEN) {
                if (col < CC) {
                    const float b0 = bias[col], b1 = bias[col + 1];
                    *(float2*)(outp + (size_t)row * CC + col) =
                        make_float2(acc[t][j][0] + b0, acc[t][j][1] + b1);
                    *(float2*)(outp + (size_t)(row + 8) * CC + col) =
                        make_float2(acc[t][j][2] + b0, acc[t][j][3] + b1);
                }
            } else {
                *(__half2*)(g_Hproj + (size_t)row * HH + col) =
                    __floats2half2_rn(acc[t][j][0], acc[t][j][1]);
                *(__half2*)(g_Hproj + (size_t)(row + 8) * HH + col) =
                    __floats2half2_rn(acc[t][j][2], acc[t][j][3]);
            }
        }
    }
}

// ---------------------------------------------------------------------------
// Persistent recurrence. 128 CTAs x 512 threads. Gates + h2h via tf32 mma.
// fp16 streams for Hproj (stage 2) and batch_H (stage 4).
// ---------------------------------------------------------------------------
__global__ void __launch_bounds__(512) recur_kernel(
    const int* __restrict__ text,
    const float* __restrict__ b_h2h, const float* __restrict__ W_score)
{
    extern __shared__ float sm[];
    float* sh_x   = sm;                      // 16 x XS: [0,256)=ctx, [256,512)=h (tf32)
    float* sh_hp  = sh_x  + MROWS * XS;      // 16 x 256
    float* sh_e   = sh_hp + MROWS * HH;      // 16 x 64
    int*   sh_ch  = (int*)(sh_e + MROWS * TT); // 16

    const int tid  = threadIdx.x;
    const int w    = tid >> 5;       // warp 0..15
    const int lane = tid & 31;
    const int g    = lane >> 2;      // fragment row group 0..7
    const int tq   = lane & 3;       // fragment quad col
    const int r0   = blockIdx.x * MROWS;

    for (int i = tid; i < MROWS * XS; i += 512) sh_x[i] = 0.f;

    float cst0[4] = {0.f, 0.f, 0.f, 0.f};
    float cst1[4] = {0.f, 0.f, 0.f, 0.f};

    float wsr[8];
    #pragma unroll
    for (int j = 0; j < 8; j++) wsr[j] = W_score[lane * 8 + j];

    float2 bh2h_r[2];
    #pragma unroll
    for (int jt = 0; jt < 2; jt++) {
        const int nc = w * 16 + jt * 8 + 2 * tq;
        bh2h_r[jt] = make_float2(b_h2h[nc], b_h2h[nc + 1]);
    }
    __syncthreads();

    for (int s = 0; s < SS; s++) {
        if (tid < MROWS) sh_ch[tid] = text[(r0 + tid) * SS + s];

        // ---- Stage 1: hp = h @ W_h2h^T + b  (tf32 mma) --------------------
        {
            float accH[2][4];
            #pragma unroll
            for (int jt = 0; jt < 2; jt++) {
                accH[jt][0] = bh2h_r[jt].x; accH[jt][1] = bh2h_r[jt].y;
                accH[jt][2] = bh2h_r[jt].x; accH[jt][3] = bh2h_r[jt].y;
            }
            const float2* bp0 = g_WfragH2h + ((size_t)(w * 2    ) * 32) * 32 + lane;
            const float2* bp1 = g_WfragH2h + ((size_t)(w * 2 + 1) * 32) * 32 + lane;
            #pragma unroll 2
            for (int kt = 0; kt < 32; kt++) {
                const float* xk = sh_x + 256 + kt * 8;
                uint32_t a0 = __float_as_uint(xk[ g      * XS + tq]);
                uint32_t a1 = __float_as_uint(xk[(g + 8) * XS + tq]);
                uint32_t a2 = __float_as_uint(xk[ g      * XS + tq + 4]);
                uint32_t a3 = __float_as_uint(xk[(g + 8) * XS + tq + 4]);
                float2 b0 = bp0[kt * 32];
                float2 b1 = bp1[kt * 32];
                mma_tf32(accH[0], a0, a1, a2, a3,
                         __float_as_uint(b0.x), __float_as_uint(b0.y));
                mma_tf32(accH[1], a0, a1, a2, a3,
                         __float_as_uint(b1.x), __float_as_uint(b1.y));
            }
            #pragma unroll
            for (int jt = 0; jt < 2; jt++) {
                const int nc = w * 16 + jt * 8 + 2 * tq;
                *(float2*)(sh_hp +  g      * HH + nc) = make_float2(accH[jt][0], accH[jt][1]);
                *(float2*)(sh_hp + (g + 8) * HH + nc) = make_float2(accH[jt][2], accH[jt][3]);
            }
        }
        __syncthreads();

        // ---- Stage 2: e[m,t] = Wscore . tanh(Hproj + hp), one LDG.128/row -
        for (int pb = w * 4; pb < MROWS * TT; pb += 64) {
            float sum[4];
            #pragma unroll
            for (int q = 0; q < 4; q++) {
                const int pp = pb + q;
                const int m = pp >> 6, t = pp & 63;
                const uint4 raw = *(const uint4*)(g_Hproj +
                    ((size_t)(r0 + m) * TT + t) * HH + lane * 8);
                const __half2* hr = (const __half2*)&raw;
                const float4 b0 = *(const float4*)(sh_hp + m * HH + lane * 8);
                const float4 b1 = *(const float4*)(sh_hp + m * HH + lane * 8 + 4);
                const float2 f0 = __half22float2(hr[0]);
                const float2 f1 = __half22float2(hr[1]);
                const float2 f2 = __half22float2(hr[2]);
                const float2 f3 = __half22float2(hr[3]);
                sum[q] = wsr[0] * ftanh(f0.x + b0.x) + wsr[1] * ftanh(f0.y + b0.y)
                       + wsr[2] * ftanh(f1.x + b0.z) + wsr[3] * ftanh(f1.y + b0.w)
                       + wsr[4] * ftanh(f2.x + b1.x) + wsr[5] * ftanh(f2.y + b1.y)
                       + wsr[6] * ftanh(f3.x + b1.z) + wsr[7] * ftanh(f3.y + b1.w);
            }
            #pragma unroll
            for (int q = 0; q < 4; q++) {
                float sq = sum[q];
                #pragma unroll
                for (int o = 16; o > 0; o >>= 1)
                    sq += __shfl_xor_sync(0xffffffffu, sq, o);
                if (lane == 0) sh_e[pb + q] = sq;
            }
        }
        __syncthreads();

        // ---- Stage 3: softmax over t, 1 row per warp ----------------------
        {
            const int m = w;
            float e0 = sh_e[m * TT + lane];
            float e1 = sh_e[m * TT + 32 + lane];
            float mx = fmaxf(e0, e1);
            #pragma unroll
            for (int o = 16; o > 0; o >>= 1)
                mx = fmaxf(mx, __shfl_xor_sync(0xffffffffu, mx, o));
            float x0 = __expf(e0 - mx), x1 = __expf(e1 - mx);
            float sume = x0 + x1;
            #pragma unroll
            for (int o = 16; o > 0; o >>= 1)
                sume += __shfl_xor_sync(0xffffffffu, sume, o);
            float inv = __frcp_rn(sume);
            sh_e[m * TT + lane]      = x0 * inv;
            sh_e[m * TT + 32 + lane] = x1 * inv;
        }
        __syncthreads();

        // ---- Stage 4: ctx[m,:] — warp m, lane covers d = lane*8..+8 -------
        {
            const int m = w;
            const __half* bh = g_bhH + ((size_t)(r0 + m) * TT) * DD + lane * 8;
            float acc[8] = {};
            #pragma unroll 8
            for (int t = 0; t < TT; t++) {
                const float a = sh_e[m * TT + t];
                const uint4 raw = *(const uint4*)(bh + (size_t)t * DD);
                const __half2* hr = (const __half2*)&raw;
                const float2 v0 = __half22float2(hr[0]);
                const float2 v1 = __half22float2(hr[1]);
                const float2 v2 = __half22float2(hr[2]);
                const float2 v3 = __half22float2(hr[3]);
                acc[0] += a * v0.x; acc[1] += a * v0.y;
                acc[2] += a * v1.x; acc[3] += a * v1.y;
                acc[4] += a * v2.x; acc[5] += a * v2.y;
                acc[6] += a * v3.x; acc[7] += a * v3.y;
            }
            float* dst = sh_x + m * XS + lane * 8;
            #pragma unroll
            for (int j = 0; j < 8; j++) dst[j] = tf32f(acc[j]);
        }
        __syncthreads();

        // ---- Stage 5: gates (tf32 mma) + LSTM -----------------------------
        {
            const int chg  = sh_ch[g];
            const int chg8 = sh_ch[g + 8];
            float accIF[4][4], accGO[4][4];
            #pragma unroll
            for (int jt = 0; jt < 4; jt++) {
                const int nIF = w * 32 + jt * 8 + 2 * tq;
                const float2 bIF = *(const float2*)(g_biasP + nIF);
                const float2 bGO = *(const float2*)(g_biasP + 512 + nIF);
                const float2 oIg  = *(const float2*)(g_WohP + (size_t)chg  * 1024 + nIF);
                const float2 oIg8 = *(const float2*)(g_WohP + (size_t)chg8 * 1024 + nIF);
                const float2 oGg  = *(const float2*)(g_WohP + (size_t)chg  * 1024 + 512 + nIF);
                const float2 oGg8 = *(const float2*)(g_WohP + (size_t)chg8 * 1024 + 512 + nIF);
                accIF[jt][0] = bIF.x + oIg.x;  accIF[jt][1] = bIF.y + oIg.y;
                accIF[jt][2] = bIF.x + oIg8.x; accIF[jt][3] = bIF.y + oIg8.y;
                accGO[jt][0] = bGO.x + oGg.x;  accGO[jt][1] = bGO.y + oGg.y;
                accGO[jt][2] = bGO.x + oGg8.x; accGO[jt][3] = bGO.y + oGg8.y;
            }
            const float2* bIFp = g_WfragGates + (size_t)(w * 4)      * 64 * 32 + lane;
            const float2* bGOp = g_WfragGates + (size_t)(64 + w * 4) * 64 * 32 + lane;
            #pragma unroll 2
            for (int kt = 0; kt < 64; kt++) {
                const float* xk = sh_x + kt * 8;
                uint32_t a0 = __float_as_uint(xk[ g      * XS + tq]);
                uint32_t a1 = __float_as_uint(xk[(g + 8) * XS + tq]);
                uint32_t a2 = __float_as_uint(xk[ g      * XS + tq + 4]);
                uint32_t a3 = __float_as_uint(xk[(g + 8) * XS + tq + 4]);
                #pragma unroll
                for (int jt = 0; jt < 4; jt++) {
                    const float2 bv = bIFp[(jt * 64 + kt) * 32];
                    mma_tf32(accIF[jt], a0, a1, a2, a3,
                             __float_as_uint(bv.x), __float_as_uint(bv.y));
                    const float2 bw = bGOp[(jt * 64 + kt) * 32];
                    mma_tf32(accGO[jt], a0, a1, a2, a3,
                             __float_as_uint(bw.x), __float_as_uint(bw.y));
                }
            }
            __syncthreads();   // all sh_x reads done before h overwrite
            #pragma unroll
            for (int jt = 0; jt < 4; jt++) {
                const int u = w * 16 + jt * 4 + tq;
                {
                    const float cnew = fsig(accIF[jt][1]) * cst0[jt]
                                     + fsig(accIF[jt][0]) * ftanh(accGO[jt][0]);
                    cst0[jt] = cnew;
                    const float hv = fsig(accGO[jt][1]) * ftanh(cnew);
                    g_hidden[((size_t)(r0 + g) * SS + s) * HH + u] = hv;
                    sh_x[g * XS + 256 + u] = tf32f(hv);
                }
                {
                    const float cnew = fsig(accIF[jt][3]) * cst1[jt]
                                     + fsig(accIF[jt][2]) * ftanh(accGO[jt][2]);
                    cst1[jt] = cnew;
                    const float hv = fsig(accGO[jt][3]) * ftanh(cnew);
                    g_hidden[((size_t)(r0 + g + 8) * SS + s) * HH + u] = hv;
                    sh_x[(g + 8) * XS + 256 + u] = tf32f(hv);
                }
            }
        }
        __syncthreads();
    }
}

// ---------------------------------------------------------------------------
extern "C" void kernel_launch(void* const* d_in, const int* in_sizes, int n_in,
                              void* d_out, int out_size)
{
    const float* batch_H = (const float*)d_in[0];
    const int*   text    = (const int*)  d_in[1];
    const float* W_i2h   = (const float*)d_in[2];
    const float* W_h2h   = (const float*)d_in[3];
    const float* b_h2h   = (const float*)d_in[4];
    const float* W_score = (const float*)d_in[5];
    const float* W_ih    = (const float*)d_in[6];
    const float* W_hh    = (const float*)d_in[7];
    const float* b_ih    = (const float*)d_in[8];
    const float* b_hh    = (const float*)d_in[9];
    const float* W_gen   = (const float*)d_in[10];
    const float* b_gen   = (const float*)d_in[11];
    float* out = (float*)d_out;

    pack_gates<<<256, 1024>>>(W_ih, W_hh);
    pack_h2h<<<32, 1024>>>(W_h2h);
    pack_oh<<<1000, 1024>>>(W_ih, b_ih, b_hh);
    pack_bh<<<(BB * TT * DD) / 4096, 1024>>>(batch_H);

    cudaFuncSetAttribute(mm2_kernel<false>,
                         cudaFuncAttributeMaxDynamicSharedMemorySize, MM2_SMEM);
    cudaFuncSetAttribute(mm2_kernel<true>,
                         cudaFuncAttributeMaxDynamicSharedMemorySize, MM2_SMEM);

    // H_proj: M=131072, N=256 -> grid (1024, 1)
    mm2_kernel<false><<<dim3((BB * TT) / 128, 1), 512, MM2_SMEM>>>(
        batch_H, W_i2h, nullptr, nullptr);

    const int smem_bytes = (MROWS * XS + MROWS * HH + MROWS * TT) * 4 + MROWS * 4;
    cudaFuncSetAttribute(recur_kernel, cudaFuncAttributeMaxDynamicSharedMemorySize,
                         smem_bytes);
    recur_kernel<<<BB / MROWS, 512, smem_bytes>>>(text, b_h2h, W_score);

    // probs: M=53248, N=1000 -> grid (416, 4)
    mm2_kernel<true><<<dim3((BB * SS) / 128, 4), 512, MM2_SMEM>>>(
        nullptr, W_gen, b_gen, out);
}

// round 12
// speedup vs baseline: 2.2638x; 1.4795x over previous
#include <cuda_runtime.h>
#include <cuda_fp16.h>
#include <cstdint>

#define BB   2048
#define TT   64
#define DD   256
#define HH   256
#define CC   1000
#define SS   26
#define DCC  1256   // D + C
#define MROWS 16    // batch rows per recurrence CTA
#define XSH  520    // sh_xh row stride (halfs): 260 words, %32==4 -> conflict-free
#define GS   36     // mm2 smem row stride (floats)
#define MMBUF (384 * GS)
#define MM2_SMEM (2 * MMBUF * 4)

// Scratch (allocation-free: __device__ globals)
__device__ __half g_Hproj[(size_t)BB * TT * HH];   // 64 MB (fp16)
__device__ __half g_bhH[(size_t)BB * TT * DD];     // 64 MB fp16 copy of batch_H
__device__ float  g_hidden[(size_t)BB * SS * HH];  // 52 MB
__device__ uint2  g_WfGatesH[128 * 32 * 32];       // 1 MB   fp16 B-frags, gates
__device__ uint2  g_WfH2hH[32 * 16 * 32];          // 128 KB fp16 B-frags, h2h
__device__ float  g_WohP[1000 * 1024];             // 4 MB   one-hot cols, packed
__device__ float  g_biasP[1024];                   // b_ih+b_hh, packed order

__device__ __forceinline__ float ftanh(float x) {
    float y;
    asm("tanh.approx.f32 %0, %1;" : "=f"(y) : "f"(x));
    return y;
}
__device__ __forceinline__ float fsig(float x) {
    return 0.5f * ftanh(0.5f * x) + 0.5f;
}
__device__ __forceinline__ uint32_t tf32_bits(float x) {
    uint32_t r;
    asm("cvt.rna.tf32.f32 %0, %1;" : "=r"(r) : "f"(x));
    return r;
}
// tf32 k8 mma (mm2 kernels)
__device__ __forceinline__ void mma_tf32(float* c,
    uint32_t a0, uint32_t a1, uint32_t a2, uint32_t a3,
    uint32_t b0, uint32_t b1)
{
    asm volatile(
        "mma.sync.aligned.m16n8k8.row.col.f32.tf32.tf32.f32 "
        "{%0,%1,%2,%3}, {%4,%5,%6,%7}, {%8,%9}, {%0,%1,%2,%3};"
        : "+f"(c[0]), "+f"(c[1]), "+f"(c[2]), "+f"(c[3])
        : "r"(a0), "r"(a1), "r"(a2), "r"(a3), "r"(b0), "r"(b1));
}
// fp16 k16 mma, fp32 accum (recurrence)
__device__ __forceinline__ void mma_f16(float* c,
    uint32_t a0, uint32_t a1, uint32_t a2, uint32_t a3,
    uint32_t b0, uint32_t b1)
{
    asm volatile(
        "mma.sync.aligned.m16n8k16.row.col.f32.f16.f16.f32 "
        "{%0,%1,%2,%3}, {%4,%5,%6,%7}, {%8,%9}, {%0,%1,%2,%3};"
        : "+f"(c[0]), "+f"(c[1]), "+f"(c[2]), "+f"(c[3])
        : "r"(a0), "r"(a1), "r"(a2), "r"(a3), "r"(b0), "r"(b1));
}
__device__ __forceinline__ void cp16(uint32_t dst, const void* src, bool pred) {
    const int sz = pred ? 16 : 0;
    asm volatile("cp.async.cg.shared.global [%0], [%1], 16, %2;"
                 :: "r"(dst), "l"(src), "r"(sz));
}

__device__ __forceinline__ int packed_gate_row(int nprime) {
    const int np = nprime & 511, u = np >> 1, b = np & 1;
    const bool go = nprime >= 512;
    return u + (go ? (b ? 768 : 512) : (b ? 256 : 0));   // rows: i|f|g|o
}
__device__ __forceinline__ float gate_w(const float* W_ih, const float* W_hh,
                                        int row, int k) {
    return (k < 256) ? W_ih[(size_t)row * DCC + k]
                     : W_hh[(size_t)row * HH + k - 256];
}

// ---------------------------------------------------------------------------
// Pack kernels
// ---------------------------------------------------------------------------
// gates fp16 fragments: [nt(128)][kt(32)][lane] -> uint2 {b0 = k(2tq,2tq+1),
// b1 = k(2tq+8,2tq+9)} at col n' = nt*8 + g  (IF tiles 0..63, GO 64..127)
__global__ void __launch_bounds__(1024) pack_gates_h(
    const float* __restrict__ W_ih, const float* __restrict__ W_hh)
{
    const int idx = blockIdx.x * 1024 + threadIdx.x;
    const int lane = idx & 31, g = lane >> 2, tq = lane & 3;
    const int kt = (idx >> 5) & 31;
    const int nt = idx >> 10;
    const int npr = (nt & 63) * 8 + g + ((nt >= 64) ? 512 : 0);
    const int row = packed_gate_row(npr);
    const int k0 = kt * 16 + 2 * tq;
    __half2 h0 = __floats2half2_rn(gate_w(W_ih, W_hh, row, k0),
                                   gate_w(W_ih, W_hh, row, k0 + 1));
    __half2 h1 = __floats2half2_rn(gate_w(W_ih, W_hh, row, k0 + 8),
                                   gate_w(W_ih, W_hh, row, k0 + 9));
    uint2 v;
    v.x = *(uint32_t*)&h0; v.y = *(uint32_t*)&h1;
    g_WfGatesH[idx] = v;
}

// h2h fp16 fragments: [nt(32)][kt(16)][lane]
__global__ void __launch_bounds__(1024) pack_h2h_h(const float* __restrict__ W_h2h)
{
    const int idx = blockIdx.x * 1024 + threadIdx.x;
    const int lane = idx & 31, g = lane >> 2, tq = lane & 3;
    const int kt = (idx >> 5) & 15;
    const int nt = idx >> 9;
    const int n = nt * 8 + g;
    const int k0 = kt * 16 + 2 * tq;
    __half2 h0 = __floats2half2_rn(W_h2h[n * HH + k0],     W_h2h[n * HH + k0 + 1]);
    __half2 h1 = __floats2half2_rn(W_h2h[n * HH + k0 + 8], W_h2h[n * HH + k0 + 9]);
    uint2 v;
    v.x = *(uint32_t*)&h0; v.y = *(uint32_t*)&h1;
    g_WfH2hH[idx] = v;
}

__global__ void __launch_bounds__(1024) pack_oh(
    const float* __restrict__ W_ih,
    const float* __restrict__ b_ih, const float* __restrict__ b_hh)
{
    const int c  = blockIdx.x;
    const int np = threadIdx.x;
    const int row = packed_gate_row(np);
    g_WohP[(size_t)c * 1024 + np] = W_ih[(size_t)row * DCC + 256 + c];
    if (c == 0) g_biasP[np] = b_ih[row] + b_hh[row];
}

__global__ void __launch_bounds__(1024) pack_bh(const float* __restrict__ bH)
{
    const size_t i = ((size_t)blockIdx.x * 1024 + threadIdx.x) * 4;
    const float4 v = *(const float4*)(bH + i);
    *(__half2*)(g_bhH + i)     = __floats2half2_rn(v.x, v.y);
    *(__half2*)(g_bhH + i + 2) = __floats2half2_rn(v.z, v.w);
}

// ---------------------------------------------------------------------------
// tf32 mma GEMM (measured-good R10): BM=128, BN=256, BK=32, cp.async 2-buf.
// ---------------------------------------------------------------------------
template<bool GEN>
__global__ void __launch_bounds__(512) mm2_kernel(
    const float* __restrict__ Ain, const float* __restrict__ Bw,
    const float* __restrict__ bias, float* __restrict__ outp)
{
    extern __shared__ float sm2[];
    const int tid = threadIdx.x, w = tid >> 5, lane = tid & 31;
    const int g = lane >> 2, tq = lane & 3;
    const int bm = blockIdx.x * 128, bn = blockIdx.y * 256;
    const int mw = w & 3, nw = w >> 2;
    const float* A = GEN ? g_hidden : Ain;
    const uint32_t smem_base = (uint32_t)__cvta_generic_to_shared(sm2);

    float acc[2][8][4] = {};

    auto load_block = [&](int kb, int p) {
        #pragma unroll
        for (int i = 0; i < 2; i++) {
            const int chunk = tid + i * 512;
            const int row = chunk >> 3, c = chunk & 7;
            const float* src = A + (size_t)(bm + row) * 256 + kb * 32 + c * 4;
            cp16(smem_base + (uint32_t)(p * MMBUF + row * GS + c * 4) * 4, src, true);
        }
        #pragma unroll
        for (int i = 0; i < 4; i++) {
            const int chunk = tid + i * 512;
            const int row = chunk >> 3, c = chunk & 7;
            const bool ok = !GEN || (bn + row < CC);
            const float* src = Bw + (size_t)(bn + row) * 256 + kb * 32 + c * 4;
            cp16(smem_base + (uint32_t)(p * MMBUF + 128 * GS + row * GS + c * 4) * 4,
                 src, ok);
        }
        asm volatile("cp.async.commit_group;");
    };

    load_block(0, 0);
    for (int kb = 0; kb < 8; kb++) {
        if (kb < 7) {
            load_block(kb + 1, (kb + 1) & 1);
            asm volatile("cp.async.wait_group 1;");
        } else {
            asm volatile("cp.async.wait_group 0;");
        }
        __syncthreads();

        const float* sa = sm2 + (kb & 1) * MMBUF + (mw * 32) * GS;
        const float* sb = sm2 + (kb & 1) * MMBUF + 128 * GS + (nw * 64) * GS;
        #pragma unroll
        for (int kt = 0; kt < 4; kt++) {
            const int k0 = kt * 8 + tq;
            uint32_t a[2][4];
            #pragma unroll
            for (int t = 0; t < 2; t++) {
                a[t][0] = tf32_bits(sa[(t * 16 + g    ) * GS + k0]);
                a[t][1] = tf32_bits(sa[(t * 16 + g + 8) * GS + k0]);
                a[t][2] = tf32_bits(sa[(t * 16 + g    ) * GS + k0 + 4]);
                a[t][3] = tf32_bits(sa[(t * 16 + g + 8) * GS + k0 + 4]);
            }
            #pragma unroll
            for (int j = 0; j < 8; j++) {
                const uint32_t b0 = tf32_bits(sb[(j * 8 + g) * GS + k0]);
                const uint32_t b1 = tf32_bits(sb[(j * 8 + g) * GS + k0 + 4]);
                mma_tf32(acc[0][j], a[0][0], a[0][1], a[0][2], a[0][3], b0, b1);
                mma_tf32(acc[1][j], a[1][0], a[1][1], a[1][2], a[1][3], b0, b1);
            }
        }
        __syncthreads();
    }

    #pragma unroll
    for (int t = 0; t < 2; t++) {
        const int row = bm + mw * 32 + t * 16 + g;
        #pragma unroll
        for (int j = 0; j < 8; j++) {
            const int col = bn + nw * 64 + j * 8 + 2 * tq;
            if (GEN) {
                if (col < CC) {
                    const float b0 = bias[col], b1 = bias[col + 1];
                    *(float2*)(outp + (size_t)row * CC + col) =
                        make_float2(acc[t][j][0] + b0, acc[t][j][1] + b1);
                    *(float2*)(outp + (size_t)(row + 8) * CC + col) =
                        make_float2(acc[t][j][2] + b0, acc[t][j][3] + b1);
                }
            } else {
                *(__half2*)(g_Hproj + (size_t)row * HH + col) =
                    __floats2half2_rn(acc[t][j][0], acc[t][j][1]);
                *(__half2*)(g_Hproj + (size_t)(row + 8) * HH + col) =
                    __floats2half2_rn(acc[t][j][2], acc[t][j][3]);
            }
        }
    }
}

// ---------------------------------------------------------------------------
// Persistent recurrence. 128 CTAs x 512 threads. Gates + h2h via fp16 k16 mma.
// ---------------------------------------------------------------------------
__global__ void __launch_bounds__(512) recur_kernel(
    const int* __restrict__ text,
    const float* __restrict__ b_h2h, const float* __restrict__ W_score)
{
    extern __shared__ char smraw[];
    __half* sh_xh = (__half*)smraw;                         // 16 x XSH halfs
    float*  sh_hp = (float*)(smraw + MROWS * XSH * 2);      // 16 x 256
    float*  sh_e  = sh_hp + MROWS * HH;                     // 16 x 64
    int*    sh_ch = (int*)(sh_e + MROWS * TT);              // 16

    const int tid  = threadIdx.x;
    const int w    = tid >> 5;
    const int lane = tid & 31;
    const int g    = lane >> 2;
    const int tq   = lane & 3;
    const int r0   = blockIdx.x * MROWS;

    for (int i = tid; i < MROWS * XSH / 2; i += 512) ((uint32_t*)sh_xh)[i] = 0u;

    float cst0[4] = {0.f, 0.f, 0.f, 0.f};
    float cst1[4] = {0.f, 0.f, 0.f, 0.f};

    float wsr[8];
    #pragma unroll
    for (int j = 0; j < 8; j++) wsr[j] = W_score[lane * 8 + j];

    float2 bh2h_r[2];
    #pragma unroll
    for (int jt = 0; jt < 2; jt++) {
        const int nc = w * 16 + jt * 8 + 2 * tq;
        bh2h_r[jt] = make_float2(b_h2h[nc], b_h2h[nc + 1]);
    }
    __syncthreads();

    for (int s = 0; s < SS; s++) {
        if (tid < MROWS) sh_ch[tid] = text[(r0 + tid) * SS + s];

        // ---- Stage 1: hp = h @ W_h2h^T + b  (fp16 mma, K=256) -------------
        {
            float accH[2][4];
            #pragma unroll
            for (int jt = 0; jt < 2; jt++) {
                accH[jt][0] = bh2h_r[jt].x; accH[jt][1] = bh2h_r[jt].y;
                accH[jt][2] = bh2h_r[jt].x; accH[jt][3] = bh2h_r[jt].y;
            }
            const uint2* bp0 = g_WfH2hH + ((size_t)(w * 2    ) * 16) * 32 + lane;
            const uint2* bp1 = g_WfH2hH + ((size_t)(w * 2 + 1) * 16) * 32 + lane;
            #pragma unroll 4
            for (int kt = 0; kt < 16; kt++) {
                const __half* xk = sh_xh + 256 + kt * 16;
                uint32_t a0 = *(const uint32_t*)(xk +  g      * XSH + 2 * tq);
                uint32_t a1 = *(const uint32_t*)(xk + (g + 8) * XSH + 2 * tq);
                uint32_t a2 = *(const uint32_t*)(xk +  g      * XSH + 2 * tq + 8);
                uint32_t a3 = *(const uint32_t*)(xk + (g + 8) * XSH + 2 * tq + 8);
                const uint2 b0 = bp0[kt * 32];
                const uint2 b1 = bp1[kt * 32];
                mma_f16(accH[0], a0, a1, a2, a3, b0.x, b0.y);
                mma_f16(accH[1], a0, a1, a2, a3, b1.x, b1.y);
            }
            #pragma unroll
            for (int jt = 0; jt < 2; jt++) {
                const int nc = w * 16 + jt * 8 + 2 * tq;
                *(float2*)(sh_hp +  g      * HH + nc) = make_float2(accH[jt][0], accH[jt][1]);
                *(float2*)(sh_hp + (g + 8) * HH + nc) = make_float2(accH[jt][2], accH[jt][3]);
            }
        }
        __syncthreads();

        // ---- Stage 2: e[m,t] = Wscore . tanh(Hproj + hp) ------------------
        for (int pb = w * 4; pb < MROWS * TT; pb += 64) {
            float sum[4];
            #pragma unroll
            for (int q = 0; q < 4; q++) {
                const int pp = pb + q;
                const int m = pp >> 6, t = pp & 63;
                const uint4 raw = *(const uint4*)(g_Hproj +
                    ((size_t)(r0 + m) * TT + t) * HH + lane * 8);
                const __half2* hr = (const __half2*)&raw;
                const float4 b0 = *(const float4*)(sh_hp + m * HH + lane * 8);
                const float4 b1 = *(const float4*)(sh_hp + m * HH + lane * 8 + 4);
                const float2 f0 = __half22float2(hr[0]);
                const float2 f1 = __half22float2(hr[1]);
                const float2 f2 = __half22float2(hr[2]);
                const float2 f3 = __half22float2(hr[3]);
                sum[q] = wsr[0] * ftanh(f0.x + b0.x) + wsr[1] * ftanh(f0.y + b0.y)
                       + wsr[2] * ftanh(f1.x + b0.z) + wsr[3] * ftanh(f1.y + b0.w)
                       + wsr[4] * ftanh(f2.x + b1.x) + wsr[5] * ftanh(f2.y + b1.y)
                       + wsr[6] * ftanh(f3.x + b1.z) + wsr[7] * ftanh(f3.y + b1.w);
            }
            #pragma unroll
            for (int q = 0; q < 4; q++) {
                float sq = sum[q];
                #pragma unroll
                for (int o = 16; o > 0; o >>= 1)
                    sq += __shfl_xor_sync(0xffffffffu, sq, o);
                if (lane == 0) sh_e[pb + q] = sq;
            }
        }
        __syncthreads();

        // ---- Stage 3: softmax over t, 1 row per warp ----------------------
        {
            const int m = w;
            float e0 = sh_e[m * TT + lane];
            float e1 = sh_e[m * TT + 32 + lane];
            float mx = fmaxf(e0, e1);
            #pragma unroll
            for (int o = 16; o > 0; o >>= 1)
                mx = fmaxf(mx, __shfl_xor_sync(0xffffffffu, mx, o));
            float x0 = __expf(e0 - mx), x1 = __expf(e1 - mx);
            float sume = x0 + x1;
            #pragma unroll
            for (int o = 16; o > 0; o >>= 1)
                sume += __shfl_xor_sync(0xffffffffu, sume, o);
            float inv = __frcp_rn(sume);
            sh_e[m * TT + lane]      = x0 * inv;
            sh_e[m * TT + 32 + lane] = x1 * inv;
        }
        __syncthreads();

        // ---- Stage 4: ctx[m,:] -> sh_xh (fp16). warp m, lane d=lane*8.. ---
        {
            const int m = w;
            const __half* bh = g_bhH + ((size_t)(r0 + m) * TT) * DD + lane * 8;
            float acc[8] = {};
            #pragma unroll 8
            for (int t = 0; t < TT; t++) {
                const float a = sh_e[m * TT + t];
                const uint4 raw = *(const uint4*)(bh + (size_t)t * DD);
                const __half2* hr = (const __half2*)&raw;
                const float2 v0 = __half22float2(hr[0]);
                const float2 v1 = __half22float2(hr[1]);
                const float2 v2 = __half22float2(hr[2]);
                const float2 v3 = __half22float2(hr[3]);
                acc[0] += a * v0.x; acc[1] += a * v0.y;
                acc[2] += a * v1.x; acc[3] += a * v1.y;
                acc[4] += a * v2.x; acc[5] += a * v2.y;
                acc[6] += a * v3.x; acc[7] += a * v3.y;
            }
            __half* dst = sh_xh + m * XSH + lane * 8;
            uint2 p0, p1;
            __half2 t0 = __floats2half2_rn(acc[0], acc[1]);
            __half2 t1 = __floats2half2_rn(acc[2], acc[3]);
            __half2 t2 = __floats2half2_rn(acc[4], acc[5]);
            __half2 t3 = __floats2half2_rn(acc[6], acc[7]);
            p0.x = *(uint32_t*)&t0; p0.y = *(uint32_t*)&t1;
            p1.x = *(uint32_t*)&t2; p1.y = *(uint32_t*)&t3;
            *(uint2*)dst       = p0;
            *(uint2*)(dst + 4) = p1;
        }
        __syncthreads();

        // ---- Stage 5: gates (fp16 mma, N=1024, K=512) + LSTM --------------
        {
            const int chg  = sh_ch[g];
            const int chg8 = sh_ch[g + 8];
            float accIF[4][4], accGO[4][4];
            #pragma unroll
            for (int jt = 0; jt < 4; jt++) {
                const int nIF = w * 32 + jt * 8 + 2 * tq;
                const float2 bIF = *(const float2*)(g_biasP + nIF);
                const float2 bGO = *(const float2*)(g_biasP + 512 + nIF);
                const float2 oIg  = *(const float2*)(g_WohP + (size_t)chg  * 1024 + nIF);
                const float2 oIg8 = *(const float2*)(g_WohP + (size_t)chg8 * 1024 + nIF);
                const float2 oGg  = *(const float2*)(g_WohP + (size_t)chg  * 1024 + 512 + nIF);
                const float2 oGg8 = *(const float2*)(g_WohP + (size_t)chg8 * 1024 + 512 + nIF);
                accIF[jt][0] = bIF.x + oIg.x;  accIF[jt][1] = bIF.y + oIg.y;
                accIF[jt][2] = bIF.x + oIg8.x; accIF[jt][3] = bIF.y + oIg8.y;
                accGO[jt][0] = bGO.x + oGg.x;  accGO[jt][1] = bGO.y + oGg.y;
                accGO[jt][2] = bGO.x + oGg8.x; accGO[jt][3] = bGO.y + oGg8.y;
            }
            const uint2* bIFp = g_WfGatesH + ((size_t)(w * 4)      * 32) * 32 + lane;
            const uint2* bGOp = g_WfGatesH + ((size_t)(64 + w * 4) * 32) * 32 + lane;
            #pragma unroll 4
            for (int kt = 0; kt < 32; kt++) {
                const __half* xk = sh_xh + kt * 16;
                uint32_t a0 = *(const uint32_t*)(xk +  g      * XSH + 2 * tq);
                uint32_t a1 = *(const uint32_t*)(xk + (g + 8) * XSH + 2 * tq);
                uint32_t a2 = *(const uint32_t*)(xk +  g      * XSH + 2 * tq + 8);
                uint32_t a3 = *(const uint32_t*)(xk + (g + 8) * XSH + 2 * tq + 8);
                #pragma unroll
                for (int jt = 0; jt < 4; jt++) {
                    const uint2 bv = bIFp[(jt * 32 + kt) * 32];
                    mma_f16(accIF[jt], a0, a1, a2, a3, bv.x, bv.y);
                    const uint2 bw = bGOp[(jt * 32 + kt) * 32];
                    mma_f16(accGO[jt], a0, a1, a2, a3, bw.x, bw.y);
                }
            }
            __syncthreads();   // all sh_xh reads done before h overwrite
            #pragma unroll
            for (int jt = 0; jt < 4; jt++) {
                const int u = w * 16 + jt * 4 + tq;
                {
                    const float cnew = fsig(accIF[jt][1]) * cst0[jt]
                                     + fsig(accIF[jt][0]) * ftanh(accGO[jt][0]);
                    cst0[jt] = cnew;
                    const float hv = fsig(accGO[jt][1]) * ftanh(cnew);
                    g_hidden[((size_t)(r0 + g) * SS + s) * HH + u] = hv;
                    sh_xh[g * XSH + 256 + u] = __float2half_rn(hv);
                }
                {
                    const float cnew = fsig(accIF[jt][3]) * cst1[jt]
                                     + fsig(accIF[jt][2]) * ftanh(accGO[jt][2]);
                    cst1[jt] = cnew;
                    const float hv = fsig(accGO[jt][3]) * ftanh(cnew);
                    g_hidden[((size_t)(r0 + g + 8) * SS + s) * HH + u] = hv;
                    sh_xh[(g + 8) * XSH + 256 + u] = __float2half_rn(hv);
                }
            }
        }
        __syncthreads();
    }
}

// ---------------------------------------------------------------------------
extern "C" void kernel_launch(void* const* d_in, const int* in_sizes, int n_in,
                              void* d_out, int out_size)
{
    const float* batch_H = (const float*)d_in[0];
    const int*   text    = (const int*)  d_in[1];
    const float* W_i2h   = (const float*)d_in[2];
    const float* W_h2h   = (const float*)d_in[3];
    const float* b_h2h   = (const float*)d_in[4];
    const float* W_score = (const float*)d_in[5];
    const float* W_ih    = (const float*)d_in[6];
    const float* W_hh    = (const float*)d_in[7];
    const float* b_ih    = (const float*)d_in[8];
    const float* b_hh    = (const float*)d_in[9];
    const float* W_gen   = (const float*)d_in[10];
    const float* b_gen   = (const float*)d_in[11];
    float* out = (float*)d_out;

    pack_gates_h<<<128, 1024>>>(W_ih, W_hh);
    pack_h2h_h<<<16, 1024>>>(W_h2h);
    pack_oh<<<1000, 1024>>>(W_ih, b_ih, b_hh);
    pack_bh<<<(BB * TT * DD) / 4096, 1024>>>(batch_H);

    cudaFuncSetAttribute(mm2_kernel<false>,
                         cudaFuncAttributeMaxDynamicSharedMemorySize, MM2_SMEM);
    cudaFuncSetAttribute(mm2_kernel<true>,
                         cudaFuncAttributeMaxDynamicSharedMemorySize, MM2_SMEM);

    // H_proj: M=131072, N=256 -> grid (1024, 1)
    mm2_kernel<false><<<dim3((BB * TT) / 128, 1), 512, MM2_SMEM>>>(
        batch_H, W_i2h, nullptr, nullptr);

    const int smem_bytes = MROWS * XSH * 2 + (MROWS * HH + MROWS * TT) * 4 + MROWS * 4;
    cudaFuncSetAttribute(recur_kernel, cudaFuncAttributeMaxDynamicSharedMemorySize,
                         smem_bytes);
    recur_kernel<<<BB / MROWS, 512, smem_bytes>>>(text, b_h2h, W_score);

    // probs: M=53248, N=1000 -> grid (416, 4)
    mm2_kernel<true><<<dim3((BB * SS) / 128, 4), 512, MM2_SMEM>>>(
        nullptr, W_gen, b_gen, out);
}

// round 13
// speedup vs baseline: 2.5199x; 1.1131x over previous
#include <cuda_runtime.h>
#include <cuda_fp16.h>
#include <cstdint>

#define BB   2048
#define TT   64
#define DD   256
#define HH   256
#define CC   1000
#define SS   26
#define DCC  1256   // D + C
#define MROWS 16    // batch rows per recurrence CTA
#define XSH  520    // sh_xh row stride (halfs): 260 words, %32==4 -> conflict-free
#define HS   72     // mm2h smem row stride (halfs): 36 words -> conflict-free
#define BUFH (384 * HS)            // halfs per buffer (A 128 rows + B 256 rows)
#define MM2H_SMEM (2 * BUFH * 2)   // bytes = 110592

// Scratch (allocation-free: __device__ globals)
__device__ __half g_Hproj[(size_t)BB * TT * HH];   // 64 MB (fp16)
__device__ __half g_bhH[(size_t)BB * TT * DD];     // 64 MB fp16 copy of batch_H
__device__ __half g_hidden[(size_t)BB * SS * HH];  // 26 MB (fp16)
__device__ uint2  g_WfGatesH[128 * 32 * 32];       // 1 MB   fp16 B-frags, gates
__device__ uint2  g_WfH2hH[32 * 16 * 32];          // 128 KB fp16 B-frags, h2h
__device__ float  g_WohP[1000 * 1024];             // 4 MB   one-hot cols, packed
__device__ float  g_biasP[1024];                   // b_ih+b_hh, packed order
__device__ __half g_WihH[256 * 256];               // fp16 W_i2h
__device__ __half g_WgenH[1000 * 256];             // fp16 W_gen

__device__ __forceinline__ float ftanh(float x) {
    float y;
    asm("tanh.approx.f32 %0, %1;" : "=f"(y) : "f"(x));
    return y;
}
__device__ __forceinline__ float fsig(float x) {
    return 0.5f * ftanh(0.5f * x) + 0.5f;
}
// fp16 k16 mma, fp32 accum
__device__ __forceinline__ void mma_f16(float* c,
    uint32_t a0, uint32_t a1, uint32_t a2, uint32_t a3,
    uint32_t b0, uint32_t b1)
{
    asm volatile(
        "mma.sync.aligned.m16n8k16.row.col.f32.f16.f16.f32 "
        "{%0,%1,%2,%3}, {%4,%5,%6,%7}, {%8,%9}, {%0,%1,%2,%3};"
        : "+f"(c[0]), "+f"(c[1]), "+f"(c[2]), "+f"(c[3])
        : "r"(a0), "r"(a1), "r"(a2), "r"(a3), "r"(b0), "r"(b1));
}
__device__ __forceinline__ void cp16(uint32_t dst, const void* src, bool pred) {
    const int sz = pred ? 16 : 0;
    asm volatile("cp.async.cg.shared.global [%0], [%1], 16, %2;"
                 :: "r"(dst), "l"(src), "r"(sz));
}

__device__ __forceinline__ int packed_gate_row(int nprime) {
    const int np = nprime & 511, u = np >> 1, b = np & 1;
    const bool go = nprime >= 512;
    return u + (go ? (b ? 768 : 512) : (b ? 256 : 0));   // rows: i|f|g|o
}
__device__ __forceinline__ float gate_w(const float* W_ih, const float* W_hh,
                                        int row, int k) {
    return (k < 256) ? W_ih[(size_t)row * DCC + k]
                     : W_hh[(size_t)row * HH + k - 256];
}

// ---------------------------------------------------------------------------
// Pack kernels
// ---------------------------------------------------------------------------
__global__ void __launch_bounds__(1024) pack_gates_h(
    const float* __restrict__ W_ih, const float* __restrict__ W_hh)
{
    const int idx = blockIdx.x * 1024 + threadIdx.x;
    const int lane = idx & 31, g = lane >> 2, tq = lane & 3;
    const int kt = (idx >> 5) & 31;
    const int nt = idx >> 10;
    const int npr = (nt & 63) * 8 + g + ((nt >= 64) ? 512 : 0);
    const int row = packed_gate_row(npr);
    const int k0 = kt * 16 + 2 * tq;
    __half2 h0 = __floats2half2_rn(gate_w(W_ih, W_hh, row, k0),
                                   gate_w(W_ih, W_hh, row, k0 + 1));
    __half2 h1 = __floats2half2_rn(gate_w(W_ih, W_hh, row, k0 + 8),
                                   gate_w(W_ih, W_hh, row, k0 + 9));
    uint2 v;
    v.x = *(uint32_t*)&h0; v.y = *(uint32_t*)&h1;
    g_WfGatesH[idx] = v;
}

__global__ void __launch_bounds__(1024) pack_h2h_h(const float* __restrict__ W_h2h)
{
    const int idx = blockIdx.x * 1024 + threadIdx.x;
    const int lane = idx & 31, g = lane >> 2, tq = lane & 3;
    const int kt = (idx >> 5) & 15;
    const int nt = idx >> 9;
    const int n = nt * 8 + g;
    const int k0 = kt * 16 + 2 * tq;
    __half2 h0 = __floats2half2_rn(W_h2h[n * HH + k0],     W_h2h[n * HH + k0 + 1]);
    __half2 h1 = __floats2half2_rn(W_h2h[n * HH + k0 + 8], W_h2h[n * HH + k0 + 9]);
    uint2 v;
    v.x = *(uint32_t*)&h0; v.y = *(uint32_t*)&h1;
    g_WfH2hH[idx] = v;
}

__global__ void __launch_bounds__(1024) pack_oh(
    const float* __restrict__ W_ih,
    const float* __restrict__ b_ih, const float* __restrict__ b_hh)
{
    const int c  = blockIdx.x;
    const int np = threadIdx.x;
    const int row = packed_gate_row(np);
    g_WohP[(size_t)c * 1024 + np] = W_ih[(size_t)row * DCC + 256 + c];
    if (c == 0) g_biasP[np] = b_ih[row] + b_hh[row];
}

__global__ void __launch_bounds__(1024) pack_bh(const float* __restrict__ bH)
{
    const size_t i = ((size_t)blockIdx.x * 1024 + threadIdx.x) * 4;
    const float4 v = *(const float4*)(bH + i);
    *(__half2*)(g_bhH + i)     = __floats2half2_rn(v.x, v.y);
    *(__half2*)(g_bhH + i + 2) = __floats2half2_rn(v.z, v.w);
}

__global__ void __launch_bounds__(1024) pack_w_h(
    const float* __restrict__ src, __half* __restrict__ dst, int n)
{
    const int i = blockIdx.x * 1024 + threadIdx.x;
    if (i < n) dst[i] = __float2half_rn(src[i]);
}

// ---------------------------------------------------------------------------
// fp16 mma GEMM: out[M,N] = A[M,256] * B[N,256]^T (+bias), BM=128, BN=256,
// BK=64 halfs, cp.async double-buffered. GEN=false: out=g_Hproj (fp16).
// GEN=true: out fp32 (+bias, col guard).
// ---------------------------------------------------------------------------
template<bool GEN>
__global__ void __launch_bounds__(512) mm2h_kernel(
    const __half* __restrict__ Ah, const __half* __restrict__ Bh,
    const float* __restrict__ bias, float* __restrict__ outp)
{
    extern __shared__ __half smh[];
    const int tid = threadIdx.x, w = tid >> 5, lane = tid & 31;
    const int g = lane >> 2, tq = lane & 3;
    const int bm = blockIdx.x * 128, bn = blockIdx.y * 256;
    const int mw = w & 3, nw = w >> 2;
    const uint32_t smem_base = (uint32_t)__cvta_generic_to_shared(smh);

    float acc[2][8][4] = {};

    auto load_block = [&](int kb, int p) {
        #pragma unroll
        for (int i = 0; i < 2; i++) {          // A: 128 rows x 64 halfs
            const int chunk = tid + i * 512;
            const int row = chunk >> 3, c = chunk & 7;
            const __half* src = Ah + (size_t)(bm + row) * 256 + kb * 64 + c * 8;
            cp16(smem_base + (uint32_t)(p * BUFH + row * HS + c * 8) * 2, src, true);
        }
        #pragma unroll
        for (int i = 0; i < 4; i++) {          // B: 256 rows x 64 halfs
            const int chunk = tid + i * 512;
            const int row = chunk >> 3, c = chunk & 7;
            const bool ok = !GEN || (bn + row < CC);
            const __half* src = Bh + (size_t)(bn + row) * 256 + kb * 64 + c * 8;
            cp16(smem_base + (uint32_t)(p * BUFH + 128 * HS + row * HS + c * 8) * 2,
                 src, ok);
        }
        asm volatile("cp.async.commit_group;");
    };

    load_block(0, 0);
    for (int kb = 0; kb < 4; kb++) {
        if (kb < 3) {
            load_block(kb + 1, (kb + 1) & 1);
            asm volatile("cp.async.wait_group 1;");
        } else {
            asm volatile("cp.async.wait_group 0;");
        }
        __syncthreads();

        const __half* sa = smh + (kb & 1) * BUFH + (mw * 32) * HS;
        const __half* sb = smh + (kb & 1) * BUFH + 128 * HS + (nw * 64) * HS;
        #pragma unroll
        for (int kt = 0; kt < 4; kt++) {
            const int k0 = kt * 16 + 2 * tq;
            uint32_t a[2][4];
            #pragma unroll
            for (int t = 0; t < 2; t++) {
                a[t][0] = *(const uint32_t*)(sa + (t * 16 + g    ) * HS + k0);
                a[t][1] = *(const uint32_t*)(sa + (t * 16 + g + 8) * HS + k0);
                a[t][2] = *(const uint32_t*)(sa + (t * 16 + g    ) * HS + k0 + 8);
                a[t][3] = *(const uint32_t*)(sa + (t * 16 + g + 8) * HS + k0 + 8);
            }
            #pragma unroll
            for (int j = 0; j < 8; j++) {
                const uint32_t b0 = *(const uint32_t*)(sb + (j * 8 + g) * HS + k0);
                const uint32_t b1 = *(const uint32_t*)(sb + (j * 8 + g) * HS + k0 + 8);
                mma_f16(acc[0][j], a[0][0], a[0][1], a[0][2], a[0][3], b0, b1);
                mma_f16(acc[1][j], a[1][0], a[1][1], a[1][2], a[1][3], b0, b1);
            }
        }
        __syncthreads();
    }

    #pragma unroll
    for (int t = 0; t < 2; t++) {
        const int row = bm + mw * 32 + t * 16 + g;
        #pragma unroll
        for (int j = 0; j < 8; j++) {
            const int col = bn + nw * 64 + j * 8 + 2 * tq;
            if (GEN) {
                if (col < CC) {
                    const float b0 = bias[col], b1 = bias[col + 1];
                    *(float2*)(outp + (size_t)row * CC + col) =
                        make_float2(acc[t][j][0] + b0, acc[t][j][1] + b1);
                    *(float2*)(outp + (size_t)(row + 8) * CC + col) =
                        make_float2(acc[t][j][2] + b0, acc[t][j][3] + b1);
                }
            } else {
                *(__half2*)(g_Hproj + (size_t)row * HH + col) =
                    __floats2half2_rn(acc[t][j][0], acc[t][j][1]);
                *(__half2*)(g_Hproj + (size_t)(row + 8) * HH + col) =
                    __floats2half2_rn(acc[t][j][2], acc[t][j][3]);
            }
        }
    }
}

// ---------------------------------------------------------------------------
// Persistent recurrence. 128 CTAs x 512 threads. Gates + h2h via fp16 k16 mma.
// ---------------------------------------------------------------------------
__global__ void __launch_bounds__(512) recur_kernel(
    const int* __restrict__ text,
    const float* __restrict__ b_h2h, const float* __restrict__ W_score)
{
    extern __shared__ char smraw[];
    __half* sh_xh = (__half*)smraw;                         // 16 x XSH halfs
    float*  sh_hp = (float*)(smraw + MROWS * XSH * 2);      // 16 x 256
    float*  sh_e  = sh_hp + MROWS * HH;                     // 16 x 64
    int*    sh_ch = (int*)(sh_e + MROWS * TT);              // 16

    const int tid  = threadIdx.x;
    const int w    = tid >> 5;
    const int lane = tid & 31;
    const int g    = lane >> 2;
    const int tq   = lane & 3;
    const int r0   = blockIdx.x * MROWS;

    for (int i = tid; i < MROWS * XSH / 2; i += 512) ((uint32_t*)sh_xh)[i] = 0u;

    float cst0[4] = {0.f, 0.f, 0.f, 0.f};
    float cst1[4] = {0.f, 0.f, 0.f, 0.f};

    float wsr[8];
    #pragma unroll
    for (int j = 0; j < 8; j++) wsr[j] = W_score[lane * 8 + j];

    float2 bh2h_r[2];
    #pragma unroll
    for (int jt = 0; jt < 2; jt++) {
        const int nc = w * 16 + jt * 8 + 2 * tq;
        bh2h_r[jt] = make_float2(b_h2h[nc], b_h2h[nc + 1]);
    }
    __syncthreads();

    for (int s = 0; s < SS; s++) {
        if (tid < MROWS) sh_ch[tid] = text[(r0 + tid) * SS + s];

        // ---- Stage 1: hp = h @ W_h2h^T + b  (fp16 mma, K=256) -------------
        {
            float accH[2][4];
            #pragma unroll
            for (int jt = 0; jt < 2; jt++) {
                accH[jt][0] = bh2h_r[jt].x; accH[jt][1] = bh2h_r[jt].y;
                accH[jt][2] = bh2h_r[jt].x; accH[jt][3] = bh2h_r[jt].y;
            }
            const uint2* bp0 = g_WfH2hH + ((size_t)(w * 2    ) * 16) * 32 + lane;
            const uint2* bp1 = g_WfH2hH + ((size_t)(w * 2 + 1) * 16) * 32 + lane;
            #pragma unroll 4
            for (int kt = 0; kt < 16; kt++) {
                const __half* xk = sh_xh + 256 + kt * 16;
                uint32_t a0 = *(const uint32_t*)(xk +  g      * XSH + 2 * tq);
                uint32_t a1 = *(const uint32_t*)(xk + (g + 8) * XSH + 2 * tq);
                uint32_t a2 = *(const uint32_t*)(xk +  g      * XSH + 2 * tq + 8);
                uint32_t a3 = *(const uint32_t*)(xk + (g + 8) * XSH + 2 * tq + 8);
                const uint2 b0 = bp0[kt * 32];
                const uint2 b1 = bp1[kt * 32];
                mma_f16(accH[0], a0, a1, a2, a3, b0.x, b0.y);
                mma_f16(accH[1], a0, a1, a2, a3, b1.x, b1.y);
            }
            #pragma unroll
            for (int jt = 0; jt < 2; jt++) {
                const int nc = w * 16 + jt * 8 + 2 * tq;
                *(float2*)(sh_hp +  g      * HH + nc) = make_float2(accH[jt][0], accH[jt][1]);
                *(float2*)(sh_hp + (g + 8) * HH + nc) = make_float2(accH[jt][2], accH[jt][3]);
            }
        }
        __syncthreads();

        // ---- Stage 2: e[m,t] = Wscore . tanh(Hproj + hp), 8 rows/warp-iter
        for (int pb = w * 8; pb < MROWS * TT; pb += 128) {
            float sum[8];
            #pragma unroll
            for (int q = 0; q < 8; q++) {
                const int pp = pb + q;
                const int m = pp >> 6, t = pp & 63;
                const uint4 raw = *(const uint4*)(g_Hproj +
                    ((size_t)(r0 + m) * TT + t) * HH + lane * 8);
                const __half2* hr = (const __half2*)&raw;
                const float4 b0 = *(const float4*)(sh_hp + m * HH + lane * 8);
                const float4 b1 = *(const float4*)(sh_hp + m * HH + lane * 8 + 4);
                const float2 f0 = __half22float2(hr[0]);
                const float2 f1 = __half22float2(hr[1]);
                const float2 f2 = __half22float2(hr[2]);
                const float2 f3 = __half22float2(hr[3]);
                sum[q] = wsr[0] * ftanh(f0.x + b0.x) + wsr[1] * ftanh(f0.y + b0.y)
                       + wsr[2] * ftanh(f1.x + b0.z) + wsr[3] * ftanh(f1.y + b0.w)
                       + wsr[4] * ftanh(f2.x + b1.x) + wsr[5] * ftanh(f2.y + b1.y)
                       + wsr[6] * ftanh(f3.x + b1.z) + wsr[7] * ftanh(f3.y + b1.w);
            }
            #pragma unroll
            for (int q = 0; q < 8; q++) {
                float sq = sum[q];
                #pragma unroll
                for (int o = 16; o > 0; o >>= 1)
                    sq += __shfl_xor_sync(0xffffffffu, sq, o);
                if (lane == 0) sh_e[pb + q] = sq;
            }
        }
        __syncthreads();

        // ---- Stage 3: softmax over t, 1 row per warp ----------------------
        {
            const int m = w;
            float e0 = sh_e[m * TT + lane];
            float e1 = sh_e[m * TT + 32 + lane];
            float mx = fmaxf(e0, e1);
            #pragma unroll
            for (int o = 16; o > 0; o >>= 1)
                mx = fmaxf(mx, __shfl_xor_sync(0xffffffffu, mx, o));
            float x0 = __expf(e0 - mx), x1 = __expf(e1 - mx);
            float sume = x0 + x1;
            #pragma unroll
            for (int o = 16; o > 0; o >>= 1)
                sume += __shfl_xor_sync(0xffffffffu, sume, o);
            float inv = __frcp_rn(sume);
            sh_e[m * TT + lane]      = x0 * inv;
            sh_e[m * TT + 32 + lane] = x1 * inv;
        }
        __syncthreads();

        // ---- Stage 4: ctx[m,:] -> sh_xh (fp16). warp m, lane d=lane*8.. ---
        {
            const int m = w;
            const __half* bh = g_bhH + ((size_t)(r0 + m) * TT) * DD + lane * 8;
            float acc[8] = {};
            #pragma unroll 8
            for (int t = 0; t < TT; t++) {
                const float a = sh_e[m * TT + t];
                const uint4 raw = *(const uint4*)(bh + (size_t)t * DD);
                const __half2* hr = (const __half2*)&raw;
                const float2 v0 = __half22float2(hr[0]);
                const float2 v1 = __half22float2(hr[1]);
                const float2 v2 = __half22float2(hr[2]);
                const float2 v3 = __half22float2(hr[3]);
                acc[0] += a * v0.x; acc[1] += a * v0.y;
                acc[2] += a * v1.x; acc[3] += a * v1.y;
                acc[4] += a * v2.x; acc[5] += a * v2.y;
                acc[6] += a * v3.x; acc[7] += a * v3.y;
            }
            __half* dst = sh_xh + m * XSH + lane * 8;
            uint2 p0, p1;
            __half2 t0 = __floats2half2_rn(acc[0], acc[1]);
            __half2 t1 = __floats2half2_rn(acc[2], acc[3]);
            __half2 t2 = __floats2half2_rn(acc[4], acc[5]);
            __half2 t3 = __floats2half2_rn(acc[6], acc[7]);
            p0.x = *(uint32_t*)&t0; p0.y = *(uint32_t*)&t1;
            p1.x = *(uint32_t*)&t2; p1.y = *(uint32_t*)&t3;
            *(uint2*)dst       = p0;
            *(uint2*)(dst + 4) = p1;
        }
        __syncthreads();

        // ---- Stage 5: gates (fp16 mma, N=1024, K=512) + LSTM --------------
        {
            const int chg  = sh_ch[g];
            const int chg8 = sh_ch[g + 8];
            float accIF[4][4], accGO[4][4];
            #pragma unroll
            for (int jt = 0; jt < 4; jt++) {
                const int nIF = w * 32 + jt * 8 + 2 * tq;
                const float2 bIF = *(const float2*)(g_biasP + nIF);
                const float2 bGO = *(const float2*)(g_biasP + 512 + nIF);
                const float2 oIg  = *(const float2*)(g_WohP + (size_t)chg  * 1024 + nIF);
                const float2 oIg8 = *(const float2*)(g_WohP + (size_t)chg8 * 1024 + nIF);
                const float2 oGg  = *(const float2*)(g_WohP + (size_t)chg  * 1024 + 512 + nIF);
                const float2 oGg8 = *(const float2*)(g_WohP + (size_t)chg8 * 1024 + 512 + nIF);
                accIF[jt][0] = bIF.x + oIg.x;  accIF[jt][1] = bIF.y + oIg.y;
                accIF[jt][2] = bIF.x + oIg8.x; accIF[jt][3] = bIF.y + oIg8.y;
                accGO[jt][0] = bGO.x + oGg.x;  accGO[jt][1] = bGO.y + oGg.y;
                accGO[jt][2] = bGO.x + oGg8.x; accGO[jt][3] = bGO.y + oGg8.y;
            }
            const uint2* bIFp = g_WfGatesH + ((size_t)(w * 4)      * 32) * 32 + lane;
            const uint2* bGOp = g_WfGatesH + ((size_t)(64 + w * 4) * 32) * 32 + lane;
            #pragma unroll 4
            for (int kt = 0; kt < 32; kt++) {
                const __half* xk = sh_xh + kt * 16;
                uint32_t a0 = *(const uint32_t*)(xk +  g      * XSH + 2 * tq);
                uint32_t a1 = *(const uint32_t*)(xk + (g + 8) * XSH + 2 * tq);
                uint32_t a2 = *(const uint32_t*)(xk +  g      * XSH + 2 * tq + 8);
                uint32_t a3 = *(const uint32_t*)(xk + (g + 8) * XSH + 2 * tq + 8);
                #pragma unroll
                for (int jt = 0; jt < 4; jt++) {
                    const uint2 bv = bIFp[(jt * 32 + kt) * 32];
                    mma_f16(accIF[jt], a0, a1, a2, a3, bv.x, bv.y);
                    const uint2 bw = bGOp[(jt * 32 + kt) * 32];
                    mma_f16(accGO[jt], a0, a1, a2, a3, bw.x, bw.y);
                }
            }
            __syncthreads();   // all sh_xh reads done before h overwrite
            #pragma unroll
            for (int jt = 0; jt < 4; jt++) {
                const int u = w * 16 + jt * 4 + tq;
                {
                    const float cnew = fsig(accIF[jt][1]) * cst0[jt]
                                     + fsig(accIF[jt][0]) * ftanh(accGO[jt][0]);
                    cst0[jt] = cnew;
                    const float hv = fsig(accGO[jt][1]) * ftanh(cnew);
                    g_hidden[((size_t)(r0 + g) * SS + s) * HH + u] = __float2half_rn(hv);
                    sh_xh[g * XSH + 256 + u] = __float2half_rn(hv);
                }
                {
                    const float cnew = fsig(accIF[jt][3]) * cst1[jt]
                                     + fsig(accIF[jt][2]) * ftanh(accGO[jt][2]);
                    cst1[jt] = cnew;
                    const float hv = fsig(accGO[jt][3]) * ftanh(cnew);
                    g_hidden[((size_t)(r0 + g + 8) * SS + s) * HH + u] = __float2half_rn(hv);
                    sh_xh[(g + 8) * XSH + 256 + u] = __float2half_rn(hv);
                }
            }
        }
        __syncthreads();
    }
}

// ---------------------------------------------------------------------------
extern "C" void kernel_launch(void* const* d_in, const int* in_sizes, int n_in,
                              void* d_out, int out_size)
{
    const float* batch_H = (const float*)d_in[0];
    const int*   text    = (const int*)  d_in[1];
    const float* W_i2h   = (const float*)d_in[2];
    const float* W_h2h   = (const float*)d_in[3];
    const float* b_h2h   = (const float*)d_in[4];
    const float* W_score = (const float*)d_in[5];
    const float* W_ih    = (const float*)d_in[6];
    const float* W_hh    = (const float*)d_in[7];
    const float* b_ih    = (const float*)d_in[8];
    const float* b_hh    = (const float*)d_in[9];
    const float* W_gen   = (const float*)d_in[10];
    const float* b_gen   = (const float*)d_in[11];
    float* out = (float*)d_out;

    __half* d_WihH;  cudaGetSymbolAddress((void**)&d_WihH,  g_WihH);
    __half* d_WgenH; cudaGetSymbolAddress((void**)&d_WgenH, g_WgenH);
    __half* d_bhH;   cudaGetSymbolAddress((void**)&d_bhH,   g_bhH);
    __half* d_hid;   cudaGetSymbolAddress((void**)&d_hid,   g_hidden);

    pack_gates_h<<<128, 1024>>>(W_ih, W_hh);
    pack_h2h_h<<<16, 1024>>>(W_h2h);
    pack_oh<<<1000, 1024>>>(W_ih, b_ih, b_hh);
    pack_bh<<<(BB * TT * DD) / 4096, 1024>>>(batch_H);
    pack_w_h<<<64, 1024>>>(W_i2h, d_WihH, 256 * 256);
    pack_w_h<<<250, 1024>>>(W_gen, d_WgenH, 1000 * 256);

    cudaFuncSetAttribute(mm2h_kernel<false>,
                         cudaFuncAttributeMaxDynamicSharedMemorySize, MM2H_SMEM);
    cudaFuncSetAttribute(mm2h_kernel<true>,
                         cudaFuncAttributeMaxDynamicSharedMemorySize, MM2H_SMEM);

    // H_proj: M=131072, N=256 -> grid (1024, 1)
    mm2h_kernel<false><<<dim3((BB * TT) / 128, 1), 512, MM2H_SMEM>>>(
        d_bhH, d_WihH, nullptr, nullptr);

    const int smem_bytes = MROWS * XSH * 2 + (MROWS * HH + MROWS * TT) * 4 + MROWS * 4;
    cudaFuncSetAttribute(recur_kernel, cudaFuncAttributeMaxDynamicSharedMemorySize,
                         smem_bytes);
    recur_kernel<<<BB / MROWS, 512, smem_bytes>>>(text, b_h2h, W_score);

    // probs: M=53248, N=1000 -> grid (416, 4)
    mm2h_kernel<true><<<dim3((BB * SS) / 128, 4), 512, MM2H_SMEM>>>(
        d_hid, d_WgenH, b_gen, out);
}

// round 14
// speedup vs baseline: 4.4394x; 1.7617x over previous
#include <cuda_runtime.h>
#include <cuda_fp16.h>
#include <cstdint>

#define BB   2048
#define TT   64
#define DD   256
#define HH   256
#define CC   1000
#define SS   26
#define DCC  1256   // D + C
#define MROWS 16    // batch rows per recurrence CTA
#define XSH  520    // sh_xh row stride (halfs): 260 words, %32==4 -> conflict-free
#define HS   72     // mm2h smem row stride (halfs)
#define BUFH (384 * HS)
#define MM2H_SMEM (2 * BUFH * 2)

// recur smem layout (bytes)
#define SW_BYTES   (4 * 32768)                  // weight ring: 4 slices x 32 KB
#define OFF_XH     SW_BYTES                     // 16 x XSH halfs = 16640
#define OFF_HP     (OFF_XH + MROWS * XSH * 2)   // 16 x 256 f32 = 16384
#define OFF_E      (OFF_HP + MROWS * HH * 4)    // 16 x 64 f32 = 4096
#define OFF_CH     (OFF_E + MROWS * TT * 4)     // 16 ints
#define RECUR_SMEM (OFF_CH + MROWS * 4)

// Scratch (allocation-free: __device__ globals)
__device__ __half g_Hproj[(size_t)BB * TT * HH];   // 64 MB (fp16)
__device__ __half g_bhH[(size_t)BB * TT * DD];     // 64 MB fp16 copy of batch_H
__device__ __half g_hidden[(size_t)BB * SS * HH];  // 26 MB (fp16)
__device__ uint2  g_WfGatesH[32 * 128 * 32];       // 1 MB  fp16 B-frags [kt][nt][lane]
__device__ uint2  g_WfH2hH[32 * 16 * 32];          // 128 KB fp16 B-frags, h2h
__device__ float  g_WohP[1000 * 1024];             // 4 MB  one-hot cols, packed
__device__ float  g_biasP[1024];                   // b_ih+b_hh, packed order
__device__ __half g_WihH[256 * 256];               // fp16 W_i2h
__device__ __half g_WgenH[1000 * 256];             // fp16 W_gen

__device__ __forceinline__ float ftanh(float x) {
    float y;
    asm("tanh.approx.f32 %0, %1;" : "=f"(y) : "f"(x));
    return y;
}
__device__ __forceinline__ float fsig(float x) {
    return 0.5f * ftanh(0.5f * x) + 0.5f;
}
__device__ __forceinline__ void mma_f16(float* c,
    uint32_t a0, uint32_t a1, uint32_t a2, uint32_t a3,
    uint32_t b0, uint32_t b1)
{
    asm volatile(
        "mma.sync.aligned.m16n8k16.row.col.f32.f16.f16.f32 "
        "{%0,%1,%2,%3}, {%4,%5,%6,%7}, {%8,%9}, {%0,%1,%2,%3};"
        : "+f"(c[0]), "+f"(c[1]), "+f"(c[2]), "+f"(c[3])
        : "r"(a0), "r"(a1), "r"(a2), "r"(a3), "r"(b0), "r"(b1));
}
__device__ __forceinline__ void cp16(uint32_t dst, const void* src, bool pred) {
    const int sz = pred ? 16 : 0;
    asm volatile("cp.async.cg.shared.global [%0], [%1], 16, %2;"
                 :: "r"(dst), "l"(src), "r"(sz));
}
// Streaming load: bypass L1 allocation (no reuse; preserves L1 for weights)
__device__ __forceinline__ uint4 ldg_na(const void* p) {
    uint4 v;
    asm("ld.global.L1::no_allocate.v4.b32 {%0,%1,%2,%3}, [%4];"
        : "=r"(v.x), "=r"(v.y), "=r"(v.z), "=r"(v.w) : "l"(p));
    return v;
}

__device__ __forceinline__ int packed_gate_row(int nprime) {
    const int np = nprime & 511, u = np >> 1, b = np & 1;
    const bool go = nprime >= 512;
    return u + (go ? (b ? 768 : 512) : (b ? 256 : 0));   // rows: i|f|g|o
}
__device__ __forceinline__ float gate_w(const float* W_ih, const float* W_hh,
                                        int row, int k) {
    return (k < 256) ? W_ih[(size_t)row * DCC + k]
                     : W_hh[(size_t)row * HH + k - 256];
}

// ---------------------------------------------------------------------------
// Pack kernels
// ---------------------------------------------------------------------------
// gates fp16 fragments, kt-major: [kt(32)][nt(128)][lane] (slice per kt contiguous)
__global__ void __launch_bounds__(1024) pack_gates_h(
    const float* __restrict__ W_ih, const float* __restrict__ W_hh)
{
    const int idx = blockIdx.x * 1024 + threadIdx.x;   // 131072
    const int lane = idx & 31, g = lane >> 2, tq = lane & 3;
    const int nt = (idx >> 5) & 127;
    const int kt = idx >> 12;
    const int npr = (nt & 63) * 8 + g + ((nt >= 64) ? 512 : 0);
    const int row = packed_gate_row(npr);
    const int k0 = kt * 16 + 2 * tq;
    __half2 h0 = __floats2half2_rn(gate_w(W_ih, W_hh, row, k0),
                                   gate_w(W_ih, W_hh, row, k0 + 1));
    __half2 h1 = __floats2half2_rn(gate_w(W_ih, W_hh, row, k0 + 8),
                                   gate_w(W_ih, W_hh, row, k0 + 9));
    uint2 v;
    v.x = *(uint32_t*)&h0; v.y = *(uint32_t*)&h1;
    g_WfGatesH[idx] = v;
}

__global__ void __launch_bounds__(1024) pack_h2h_h(const float* __restrict__ W_h2h)
{
    const int idx = blockIdx.x * 1024 + threadIdx.x;
    const int lane = idx & 31, g = lane >> 2, tq = lane & 3;
    const int kt = (idx >> 5) & 15;
    const int nt = idx >> 9;
    const int n = nt * 8 + g;
    const int k0 = kt * 16 + 2 * tq;
    __half2 h0 = __floats2half2_rn(W_h2h[n * HH + k0],     W_h2h[n * HH + k0 + 1]);
    __half2 h1 = __floats2half2_rn(W_h2h[n * HH + k0 + 8], W_h2h[n * HH + k0 + 9]);
    uint2 v;
    v.x = *(uint32_t*)&h0; v.y = *(uint32_t*)&h1;
    g_WfH2hH[idx] = v;
}

// Coalesced one-hot pack: block = 32-column chunk, thread = packed index np.
// Each thread reads one contiguous 128B span of its gate row (1 line),
// writes 32 coalesced column stores.
__global__ void __launch_bounds__(1024) pack_oh(
    const float* __restrict__ W_ih,
    const float* __restrict__ b_ih, const float* __restrict__ b_hh)
{
    const int cb = blockIdx.x;        // 0..31
    const int np = threadIdx.x;       // 0..1023
    const int row = packed_gate_row(np);
    const float* src = W_ih + (size_t)row * DCC + 256 + cb * 32;
    #pragma unroll
    for (int j4 = 0; j4 < 8; j4++) {
        const int c = cb * 32 + j4 * 4;
        if (c + 3 < CC) {
            const float4 v = *(const float4*)(src + j4 * 4);
            g_WohP[(size_t)(c    ) * 1024 + np] = v.x;
            g_WohP[(size_t)(c + 1) * 1024 + np] = v.y;
            g_WohP[(size_t)(c + 2) * 1024 + np] = v.z;
            g_WohP[(size_t)(c + 3) * 1024 + np] = v.w;
        } else {
            #pragma unroll
            for (int j = 0; j < 4; j++)
                if (c + j < CC)
                    g_WohP[(size_t)(c + j) * 1024 + np] = src[j4 * 4 + j];
        }
    }
    if (cb == 0) g_biasP[np] = b_ih[np >= 0 ? row : 0] + b_hh[row];
}

__global__ void __launch_bounds__(1024) pack_bh(const float* __restrict__ bH)
{
    const size_t i = ((size_t)blockIdx.x * 1024 + threadIdx.x) * 4;
    const float4 v = *(const float4*)(bH + i);
    *(__half2*)(g_bhH + i)     = __floats2half2_rn(v.x, v.y);
    *(__half2*)(g_bhH + i + 2) = __floats2half2_rn(v.z, v.w);
}

__global__ void __launch_bounds__(1024) pack_w_h(
    const float* __restrict__ src, __half* __restrict__ dst, int n)
{
    const int i = blockIdx.x * 1024 + threadIdx.x;
    if (i < n) dst[i] = __float2half_rn(src[i]);
}

// ---------------------------------------------------------------------------
// fp16 mma GEMM (measured-good R12): BM=128, BN=256, BK=64h, cp.async 2-buf.
// ---------------------------------------------------------------------------
template<bool GEN>
__global__ void __launch_bounds__(512) mm2h_kernel(
    const __half* __restrict__ Ah, const __half* __restrict__ Bh,
    const float* __restrict__ bias, float* __restrict__ outp)
{
    extern __shared__ __half smh[];
    const int tid = threadIdx.x, w = tid >> 5, lane = tid & 31;
    const int g = lane >> 2, tq = lane & 3;
    const int bm = blockIdx.x * 128, bn = blockIdx.y * 256;
    const int mw = w & 3, nw = w >> 2;
    const uint32_t smem_base = (uint32_t)__cvta_generic_to_shared(smh);

    float acc[2][8][4] = {};

    auto load_block = [&](int kb, int p) {
        #pragma unroll
        for (int i = 0; i < 2; i++) {
            const int chunk = tid + i * 512;
            const int row = chunk >> 3, c = chunk & 7;
            const __half* src = Ah + (size_t)(bm + row) * 256 + kb * 64 + c * 8;
            cp16(smem_base + (uint32_t)(p * BUFH + row * HS + c * 8) * 2, src, true);
        }
        #pragma unroll
        for (int i = 0; i < 4; i++) {
            const int chunk = tid + i * 512;
            const int row = chunk >> 3, c = chunk & 7;
            const bool ok = !GEN || (bn + row < CC);
            const __half* src = Bh + (size_t)(bn + row) * 256 + kb * 64 + c * 8;
            cp16(smem_base + (uint32_t)(p * BUFH + 128 * HS + row * HS + c * 8) * 2,
                 src, ok);
        }
        asm volatile("cp.async.commit_group;");
    };

    load_block(0, 0);
    for (int kb = 0; kb < 4; kb++) {
        if (kb < 3) {
            load_block(kb + 1, (kb + 1) & 1);
            asm volatile("cp.async.wait_group 1;");
        } else {
            asm volatile("cp.async.wait_group 0;");
        }
        __syncthreads();

        const __half* sa = smh + (kb & 1) * BUFH + (mw * 32) * HS;
        const __half* sb = smh + (kb & 1) * BUFH + 128 * HS + (nw * 64) * HS;
        #pragma unroll
        for (int kt = 0; kt < 4; kt++) {
            const int k0 = kt * 16 + 2 * tq;
            uint32_t a[2][4];
            #pragma unroll
            for (int t = 0; t < 2; t++) {
                a[t][0] = *(const uint32_t*)(sa + (t * 16 + g    ) * HS + k0);
                a[t][1] = *(const uint32_t*)(sa + (t * 16 + g + 8) * HS + k0);
                a[t][2] = *(const uint32_t*)(sa + (t * 16 + g    ) * HS + k0 + 8);
                a[t][3] = *(const uint32_t*)(sa + (t * 16 + g + 8) * HS + k0 + 8);
            }
            #pragma unroll
            for (int j = 0; j < 8; j++) {
                const uint32_t b0 = *(const uint32_t*)(sb + (j * 8 + g) * HS + k0);
                const uint32_t b1 = *(const uint32_t*)(sb + (j * 8 + g) * HS + k0 + 8);
                mma_f16(acc[0][j], a[0][0], a[0][1], a[0][2], a[0][3], b0, b1);
                mma_f16(acc[1][j], a[1][0], a[1][1], a[1][2], a[1][3], b0, b1);
            }
        }
        __syncthreads();
    }

    #pragma unroll
    for (int t = 0; t < 2; t++) {
        const int row = bm + mw * 32 + t * 16 + g;
        #pragma unroll
        for (int j = 0; j < 8; j++) {
            const int col = bn + nw * 64 + j * 8 + 2 * tq;
            if (GEN) {
                if (col < CC) {
                    const float b0 = bias[col], b1 = bias[col + 1];
                    *(float2*)(outp + (size_t)row * CC + col) =
                        make_float2(acc[t][j][0] + b0, acc[t][j][1] + b1);
                    *(float2*)(outp + (size_t)(row + 8) * CC + col) =
                        make_float2(acc[t][j][2] + b0, acc[t][j][3] + b1);
                }
            } else {
                *(__half2*)(g_Hproj + (size_t)row * HH + col) =
                    __floats2half2_rn(acc[t][j][0], acc[t][j][1]);
                *(__half2*)(g_Hproj + (size_t)(row + 8) * HH + col) =
                    __floats2half2_rn(acc[t][j][2], acc[t][j][3]);
            }
        }
    }
}

// ---------------------------------------------------------------------------
// Persistent recurrence. 128 CTAs x 512 threads. fp16 k16 mma + weight ring.
// ---------------------------------------------------------------------------
__global__ void __launch_bounds__(512) recur_kernel(
    const int* __restrict__ text,
    const float* __restrict__ b_h2h, const float* __restrict__ W_score)
{
    extern __shared__ char smraw[];
    __half* sh_xh = (__half*)(smraw + OFF_XH);
    float*  sh_hp = (float*)(smraw + OFF_HP);
    float*  sh_e  = (float*)(smraw + OFF_E);
    int*    sh_ch = (int*)(smraw + OFF_CH);

    const int tid  = threadIdx.x;
    const int w    = tid >> 5;
    const int lane = tid & 31;
    const int g    = lane >> 2;
    const int tq   = lane & 3;
    const int r0   = blockIdx.x * MROWS;
    const uint32_t swb = (uint32_t)__cvta_generic_to_shared(smraw);

    for (int i = tid; i < MROWS * XSH / 2; i += 512) ((uint32_t*)sh_xh)[i] = 0u;

    float cst0[4] = {0.f, 0.f, 0.f, 0.f};
    float cst1[4] = {0.f, 0.f, 0.f, 0.f};

    float wsr[8];
    #pragma unroll
    for (int j = 0; j < 8; j++) wsr[j] = W_score[lane * 8 + j];

    float2 bh2h_r[2];
    #pragma unroll
    for (int jt = 0; jt < 2; jt++) {
        const int nc = w * 16 + jt * 8 + 2 * tq;
        bh2h_r[jt] = make_float2(b_h2h[nc], b_h2h[nc + 1]);
    }
    __syncthreads();

    for (int s = 0; s < SS; s++) {
        if (tid < MROWS) sh_ch[tid] = text[(r0 + tid) * SS + s];

        // ---- Stage 1: hp = h @ W_h2h^T + b  (fp16 mma, K=256) -------------
        {
            float accH[2][4];
            #pragma unroll
            for (int jt = 0; jt < 2; jt++) {
                accH[jt][0] = bh2h_r[jt].x; accH[jt][1] = bh2h_r[jt].y;
                accH[jt][2] = bh2h_r[jt].x; accH[jt][3] = bh2h_r[jt].y;
            }
            const uint2* bp0 = g_WfH2hH + ((size_t)(w * 2    ) * 16) * 32 + lane;
            const uint2* bp1 = g_WfH2hH + ((size_t)(w * 2 + 1) * 16) * 32 + lane;
            #pragma unroll 4
            for (int kt = 0; kt < 16; kt++) {
                const __half* xk = sh_xh + 256 + kt * 16;
                uint32_t a0 = *(const uint32_t*)(xk +  g      * XSH + 2 * tq);
                uint32_t a1 = *(const uint32_t*)(xk + (g + 8) * XSH + 2 * tq);
                uint32_t a2 = *(const uint32_t*)(xk +  g      * XSH + 2 * tq + 8);
                uint32_t a3 = *(const uint32_t*)(xk + (g + 8) * XSH + 2 * tq + 8);
                const uint2 b0 = bp0[kt * 32];
                const uint2 b1 = bp1[kt * 32];
                mma_f16(accH[0], a0, a1, a2, a3, b0.x, b0.y);
                mma_f16(accH[1], a0, a1, a2, a3, b1.x, b1.y);
            }
            #pragma unroll
            for (int jt = 0; jt < 2; jt++) {
                const int nc = w * 16 + jt * 8 + 2 * tq;
                *(float2*)(sh_hp +  g      * HH + nc) = make_float2(accH[jt][0], accH[jt][1]);
                *(float2*)(sh_hp + (g + 8) * HH + nc) = make_float2(accH[jt][2], accH[jt][3]);
            }
        }
        __syncthreads();

        // ---- Stage 2: e[m,t] = Wscore . tanh(Hproj + hp) ------------------
        for (int pb = w * 8; pb < MROWS * TT; pb += 128) {
            float sum[8];
            #pragma unroll
            for (int q = 0; q < 8; q++) {
                const int pp = pb + q;
                const int m = pp >> 6, t = pp & 63;
                const uint4 raw = ldg_na(g_Hproj +
                    ((size_t)(r0 + m) * TT + t) * HH + lane * 8);
                const __half2* hr = (const __half2*)&raw;
                const float4 b0 = *(const float4*)(sh_hp + m * HH + lane * 8);
                const float4 b1 = *(const float4*)(sh_hp + m * HH + lane * 8 + 4);
                const float2 f0 = __half22float2(hr[0]);
                const float2 f1 = __half22float2(hr[1]);
                const float2 f2 = __half22float2(hr[2]);
                const float2 f3 = __half22float2(hr[3]);
                sum[q] = wsr[0] * ftanh(f0.x + b0.x) + wsr[1] * ftanh(f0.y + b0.y)
                       + wsr[2] * ftanh(f1.x + b0.z) + wsr[3] * ftanh(f1.y + b0.w)
                       + wsr[4] * ftanh(f2.x + b1.x) + wsr[5] * ftanh(f2.y + b1.y)
                       + wsr[6] * ftanh(f3.x + b1.z) + wsr[7] * ftanh(f3.y + b1.w);
            }
            #pragma unroll
            for (int q = 0; q < 8; q++) {
                float sq = sum[q];
                #pragma unroll
                for (int o = 16; o > 0; o >>= 1)
                    sq += __shfl_xor_sync(0xffffffffu, sq, o);
                if (lane == 0) sh_e[pb + q] = sq;
            }
        }
        __syncthreads();

        // ---- Stage 3: softmax over t, 1 row per warp ----------------------
        {
            const int m = w;
            float e0 = sh_e[m * TT + lane];
            float e1 = sh_e[m * TT + 32 + lane];
            float mx = fmaxf(e0, e1);
            #pragma unroll
            for (int o = 16; o > 0; o >>= 1)
                mx = fmaxf(mx, __shfl_xor_sync(0xffffffffu, mx, o));
            float x0 = __expf(e0 - mx), x1 = __expf(e1 - mx);
            float sume = x0 + x1;
            #pragma unroll
            for (int o = 16; o > 0; o >>= 1)
                sume += __shfl_xor_sync(0xffffffffu, sume, o);
            float inv = __frcp_rn(sume);
            sh_e[m * TT + lane]      = x0 * inv;
            sh_e[m * TT + 32 + lane] = x1 * inv;
        }
        __syncthreads();

        // ---- Stage 4: ctx[m,:] -> sh_xh (fp16). warp m, lane d=lane*8.. ---
        {
            const int m = w;
            const __half* bh = g_bhH + ((size_t)(r0 + m) * TT) * DD + lane * 8;
            float acc[8] = {};
            #pragma unroll 8
            for (int t = 0; t < TT; t++) {
                const float a = sh_e[m * TT + t];
                const uint4 raw = ldg_na(bh + (size_t)t * DD);
                const __half2* hr = (const __half2*)&raw;
                const float2 v0 = __half22float2(hr[0]);
                const float2 v1 = __half22float2(hr[1]);
                const float2 v2 = __half22float2(hr[2]);
                const float2 v3 = __half22float2(hr[3]);
                acc[0] += a * v0.x; acc[1] += a * v0.y;
                acc[2] += a * v1.x; acc[3] += a * v1.y;
                acc[4] += a * v2.x; acc[5] += a * v2.y;
                acc[6] += a * v3.x; acc[7] += a * v3.y;
            }
            __half* dst = sh_xh + m * XSH + lane * 8;
            uint2 p0, p1;
            __half2 t0 = __floats2half2_rn(acc[0], acc[1]);
            __half2 t1 = __floats2half2_rn(acc[2], acc[3]);
            __half2 t2 = __floats2half2_rn(acc[4], acc[5]);
            __half2 t3 = __floats2half2_rn(acc[6], acc[7]);
            p0.x = *(uint32_t*)&t0; p0.y = *(uint32_t*)&t1;
            p1.x = *(uint32_t*)&t2; p1.y = *(uint32_t*)&t3;
            *(uint2*)dst       = p0;
            *(uint2*)(dst + 4) = p1;
        }
        __syncthreads();

        // ---- Stage 5: gates (fp16 mma) + LSTM, weights via cp.async ring --
        {
            // per-warp prefetch of this warp's 8 fragment tiles per kt
            auto issue_w = [&](int kt, int r) {
                const char* gb = (const char*)g_WfGatesH;
                const size_t ifo = ((size_t)(kt * 128 + w * 4) * 32) * 8;
                const size_t goo = ((size_t)(kt * 128 + 64 + w * 4) * 32) * 8;
                const uint32_t sb = swb + (uint32_t)(r * 32768 + w * 2048);
                #pragma unroll
                for (int c2 = 0; c2 < 2; c2++) {
                    cp16(sb + c2 * 512 + lane * 16,
                         gb + ifo + c2 * 512 + lane * 16, true);
                    cp16(sb + 1024 + c2 * 512 + lane * 16,
                         gb + goo + c2 * 512 + lane * 16, true);
                }
                asm volatile("cp.async.commit_group;");
            };
            issue_w(0, 0); issue_w(1, 1); issue_w(2, 2);

            // accumulator init (one-hot + bias) overlaps prefetch latency
            const int chg  = sh_ch[g];
            const int chg8 = sh_ch[g + 8];
            float accIF[4][4], accGO[4][4];
            #pragma unroll
            for (int jt = 0; jt < 4; jt++) {
                const int nIF = w * 32 + jt * 8 + 2 * tq;
                const float2 bIF = *(const float2*)(g_biasP + nIF);
                const float2 bGO = *(const float2*)(g_biasP + 512 + nIF);
                const float2 oIg  = *(const float2*)(g_WohP + (size_t)chg  * 1024 + nIF);
                const float2 oIg8 = *(const float2*)(g_WohP + (size_t)chg8 * 1024 + nIF);
                const float2 oGg  = *(const float2*)(g_WohP + (size_t)chg  * 1024 + 512 + nIF);
                const float2 oGg8 = *(const float2*)(g_WohP + (size_t)chg8 * 1024 + 512 + nIF);
                accIF[jt][0] = bIF.x + oIg.x;  accIF[jt][1] = bIF.y + oIg.y;
                accIF[jt][2] = bIF.x + oIg8.x; accIF[jt][3] = bIF.y + oIg8.y;
                accGO[jt][0] = bGO.x + oGg.x;  accGO[jt][1] = bGO.y + oGg.y;
                accGO[jt][2] = bGO.x + oGg8.x; accGO[jt][3] = bGO.y + oGg8.y;
            }

            for (int kt = 0; kt < 32; kt++) {
                if (kt + 3 < 32) issue_w(kt + 3, (kt + 3) & 3);
                else asm volatile("cp.async.commit_group;");
                asm volatile("cp.async.wait_group 3;");
                __syncwarp();

                const uint2* wp = (const uint2*)(smraw + ((kt & 3) * 32768 + w * 2048));
                const __half* xk = sh_xh + kt * 16;
                uint32_t a0 = *(const uint32_t*)(xk +  g      * XSH + 2 * tq);
                uint32_t a1 = *(const uint32_t*)(xk + (g + 8) * XSH + 2 * tq);
                uint32_t a2 = *(const uint32_t*)(xk +  g      * XSH + 2 * tq + 8);
                uint32_t a3 = *(const uint32_t*)(xk + (g + 8) * XSH + 2 * tq + 8);
                #pragma unroll
                for (int jt = 0; jt < 4; jt++) {
                    const uint2 bv = wp[jt * 32 + lane];
                    mma_f16(accIF[jt], a0, a1, a2, a3, bv.x, bv.y);
                    const uint2 bw = wp[128 + jt * 32 + lane];
                    mma_f16(accGO[jt], a0, a1, a2, a3, bw.x, bw.y);
                }
            }
            __syncthreads();   // all sh_xh reads done before h overwrite
            #pragma unroll
            for (int jt = 0; jt < 4; jt++) {
                const int u = w * 16 + jt * 4 + tq;
                {
                    const float cnew = fsig(accIF[jt][1]) * cst0[jt]
                                     + fsig(accIF[jt][0]) * ftanh(accGO[jt][0]);
                    cst0[jt] = cnew;
                    const float hv = fsig(accGO[jt][1]) * ftanh(cnew);
                    g_hidden[((size_t)(r0 + g) * SS + s) * HH + u] = __float2half_rn(hv);
                    sh_xh[g * XSH + 256 + u] = __float2half_rn(hv);
                }
                {
                    const float cnew = fsig(accIF[jt][3]) * cst1[jt]
                                     + fsig(accIF[jt][2]) * ftanh(accGO[jt][2]);
                    cst1[jt] = cnew;
                    const float hv = fsig(accGO[jt][3]) * ftanh(cnew);
                    g_hidden[((size_t)(r0 + g + 8) * SS + s) * HH + u] = __float2half_rn(hv);
                    sh_xh[(g + 8) * XSH + 256 + u] = __float2half_rn(hv);
                }
            }
        }
        __syncthreads();
    }
}

// ---------------------------------------------------------------------------
extern "C" void kernel_launch(void* const* d_in, const int* in_sizes, int n_in,
                              void* d_out, int out_size)
{
    const float* batch_H = (const float*)d_in[0];
    const int*   text    = (const int*)  d_in[1];
    const float* W_i2h   = (const float*)d_in[2];
    const float* W_h2h   = (const float*)d_in[3];
    const float* b_h2h   = (const float*)d_in[4];
    const float* W_score = (const float*)d_in[5];
    const float* W_ih    = (const float*)d_in[6];
    const float* W_hh    = (const float*)d_in[7];
    const float* b_ih    = (const float*)d_in[8];
    const float* b_hh    = (const float*)d_in[9];
    const float* W_gen   = (const float*)d_in[10];
    const float* b_gen   = (const float*)d_in[11];
    float* out = (float*)d_out;

    __half* d_WihH;  cudaGetSymbolAddress((void**)&d_WihH,  g_WihH);
    __half* d_WgenH; cudaGetSymbolAddress((void**)&d_WgenH, g_WgenH);
    __half* d_bhH;   cudaGetSymbolAddress((void**)&d_bhH,   g_bhH);
    __half* d_hid;   cudaGetSymbolAddress((void**)&d_hid,   g_hidden);

    pack_gates_h<<<128, 1024>>>(W_ih, W_hh);
    pack_h2h_h<<<16, 1024>>>(W_h2h);
    pack_oh<<<32, 1024>>>(W_ih, b_ih, b_hh);
    pack_bh<<<(BB * TT * DD) / 4096, 1024>>>(batch_H);
    pack_w_h<<<64, 1024>>>(W_i2h, d_WihH, 256 * 256);
    pack_w_h<<<250, 1024>>>(W_gen, d_WgenH, 1000 * 256);

    cudaFuncSetAttribute(mm2h_kernel<false>,
                         cudaFuncAttributeMaxDynamicSharedMemorySize, MM2H_SMEM);
    cudaFuncSetAttribute(mm2h_kernel<true>,
                         cudaFuncAttributeMaxDynamicSharedMemorySize, MM2H_SMEM);

    // H_proj: M=131072, N=256 -> grid (1024, 1)
    mm2h_kernel<false><<<dim3((BB * TT) / 128, 1), 512, MM2H_SMEM>>>(
        d_bhH, d_WihH, nullptr, nullptr);

    cudaFuncSetAttribute(recur_kernel, cudaFuncAttributeMaxDynamicSharedMemorySize,
                         RECUR_SMEM);
    recur_kernel<<<BB / MROWS, 512, RECUR_SMEM>>>(text, b_h2h, W_score);

    // probs: M=53248, N=1000 -> grid (416, 4)
    mm2h_kernel<true><<<dim3((BB * SS) / 128, 4), 512, MM2H_SMEM>>>(
        d_hid, d_WgenH, b_gen, out);
}

// round 15
// speedup vs baseline: 4.6994x; 1.0586x over previous
#include <cuda_runtime.h>
#include <cuda_fp16.h>
#include <cstdint>

#define BB   2048
#define TT   64
#define DD   256
#define HH   256
#define CC   1000
#define SS   26
#define DCC  1256   // D + C
#define MROWS 16    // batch rows per recurrence CTA
#define XSH  520    // sh_xh row stride (halfs): 260 words, %32==4 -> conflict-free
#define HS   72     // mm2h smem row stride (halfs)
#define BUFH (384 * HS)
#define MM2H_SMEM (2 * BUFH * 2)

// recur smem layout (bytes)
#define SW_BYTES   (4 * 32768)                  // weight ring: 4 slices x 32 KB
#define OFF_XH     SW_BYTES                     // 16 x XSH halfs = 16640
#define OFF_HP     (OFF_XH + MROWS * XSH * 2)   // 16 x 256 f32 = 16384
#define OFF_E      (OFF_HP + MROWS * HH * 4)    // 16 x 64 f32 = 4096
#define OFF_CH     (OFF_E + MROWS * TT * 4)     // 16 ints
#define RECUR_SMEM (OFF_CH + MROWS * 4)

// Scratch (allocation-free: __device__ globals)
__device__ __half g_Hproj[(size_t)BB * TT * HH];   // 64 MB (fp16), streamed (.cs)
__device__ __half g_bhH[(size_t)BB * TT * DD];     // 64 MB fp16, L2-resident (.cg)
__device__ __half g_hidden[(size_t)BB * SS * HH];  // 26 MB (fp16)
__device__ uint2  g_WfGatesH[32 * 128 * 32];       // 1 MB  fp16 B-frags [kt][nt][lane]
__device__ uint2  g_WfH2hH[32 * 16 * 32];          // 128 KB fp16 B-frags, h2h
__device__ float  g_WohP[1000 * 1024];             // 4 MB  one-hot cols, packed
__device__ float  g_biasP[1024];                   // b_ih+b_hh, packed order
__device__ __half g_WihH[256 * 256];               // fp16 W_i2h
__device__ __half g_WgenH[1000 * 256];             // fp16 W_gen

__device__ __forceinline__ float ftanh(float x) {
    float y;
    asm("tanh.approx.f32 %0, %1;" : "=f"(y) : "f"(x));
    return y;
}
__device__ __forceinline__ float fsig(float x) {
    return 0.5f * ftanh(0.5f * x) + 0.5f;
}
__device__ __forceinline__ void mma_f16(float* c,
    uint32_t a0, uint32_t a1, uint32_t a2, uint32_t a3,
    uint32_t b0, uint32_t b1)
{
    asm volatile(
        "mma.sync.aligned.m16n8k16.row.col.f32.f16.f16.f32 "
        "{%0,%1,%2,%3}, {%4,%5,%6,%7}, {%8,%9}, {%0,%1,%2,%3};"
        : "+f"(c[0]), "+f"(c[1]), "+f"(c[2]), "+f"(c[3])
        : "r"(a0), "r"(a1), "r"(a2), "r"(a3), "r"(b0), "r"(b1));
}
__device__ __forceinline__ void cp16(uint32_t dst, const void* src, bool pred) {
    const int sz = pred ? 16 : 0;
    asm volatile("cp.async.cg.shared.global [%0], [%1], 16, %2;"
                 :: "r"(dst), "l"(src), "r"(sz));
}

__device__ __forceinline__ int packed_gate_row(int nprime) {
    const int np = nprime & 511, u = np >> 1, b = np & 1;
    const bool go = nprime >= 512;
    return u + (go ? (b ? 768 : 512) : (b ? 256 : 0));   // rows: i|f|g|o
}
__device__ __forceinline__ float gate_w(const float* W_ih, const float* W_hh,
                                        int row, int k) {
    return (k < 256) ? W_ih[(size_t)row * DCC + k]
                     : W_hh[(size_t)row * HH + k - 256];
}

// ---------------------------------------------------------------------------
// Pack kernels
// ---------------------------------------------------------------------------
__global__ void __launch_bounds__(1024) pack_gates_h(
    const float* __restrict__ W_ih, const float* __restrict__ W_hh)
{
    const int idx = blockIdx.x * 1024 + threadIdx.x;   // 131072
    const int lane = idx & 31, g = lane >> 2, tq = lane & 3;
    const int nt = (idx >> 5) & 127;
    const int kt = idx >> 12;
    const int npr = (nt & 63) * 8 + g + ((nt >= 64) ? 512 : 0);
    const int row = packed_gate_row(npr);
    const int k0 = kt * 16 + 2 * tq;
    __half2 h0 = __floats2half2_rn(gate_w(W_ih, W_hh, row, k0),
                                   gate_w(W_ih, W_hh, row, k0 + 1));
    __half2 h1 = __floats2half2_rn(gate_w(W_ih, W_hh, row, k0 + 8),
                                   gate_w(W_ih, W_hh, row, k0 + 9));
    uint2 v;
    v.x = *(uint32_t*)&h0; v.y = *(uint32_t*)&h1;
    g_WfGatesH[idx] = v;
}

__global__ void __launch_bounds__(1024) pack_h2h_h(const float* __restrict__ W_h2h)
{
    const int idx = blockIdx.x * 1024 + threadIdx.x;
    const int lane = idx & 31, g = lane >> 2, tq = lane & 3;
    const int kt = (idx >> 5) & 15;
    const int nt = idx >> 9;
    const int n = nt * 8 + g;
    const int k0 = kt * 16 + 2 * tq;
    __half2 h0 = __floats2half2_rn(W_h2h[n * HH + k0],     W_h2h[n * HH + k0 + 1]);
    __half2 h1 = __floats2half2_rn(W_h2h[n * HH + k0 + 8], W_h2h[n * HH + k0 + 9]);
    uint2 v;
    v.x = *(uint32_t*)&h0; v.y = *(uint32_t*)&h1;
    g_WfH2hH[idx] = v;
}

__global__ void __launch_bounds__(1024) pack_oh(
    const float* __restrict__ W_ih,
    const float* __restrict__ b_ih, const float* __restrict__ b_hh)
{
    const int cb = blockIdx.x;        // 0..31
    const int np = threadIdx.x;       // 0..1023
    const int row = packed_gate_row(np);
    const float* src = W_ih + (size_t)row * DCC + 256 + cb * 32;
    #pragma unroll
    for (int j4 = 0; j4 < 8; j4++) {
        const int c = cb * 32 + j4 * 4;
        if (c + 3 < CC) {
            const float4 v = *(const float4*)(src + j4 * 4);
            g_WohP[(size_t)(c    ) * 1024 + np] = v.x;
            g_WohP[(size_t)(c + 1) * 1024 + np] = v.y;
            g_WohP[(size_t)(c + 2) * 1024 + np] = v.z;
            g_WohP[(size_t)(c + 3) * 1024 + np] = v.w;
        } else {
            #pragma unroll
            for (int j = 0; j < 4; j++)
                if (c + j < CC)
                    g_WohP[(size_t)(c + j) * 1024 + np] = src[j4 * 4 + j];
        }
    }
    if (cb == 0) g_biasP[np] = b_ih[row] + b_hh[row];
}

__global__ void __launch_bounds__(1024) pack_bh(const float* __restrict__ bH)
{
    const size_t i = ((size_t)blockIdx.x * 1024 + threadIdx.x) * 4;
    const float4 v = *(const float4*)(bH + i);
    *(__half2*)(g_bhH + i)     = __floats2half2_rn(v.x, v.y);
    *(__half2*)(g_bhH + i + 2) = __floats2half2_rn(v.z, v.w);
}

__global__ void __launch_bounds__(1024) pack_w_h(
    const float* __restrict__ src, __half* __restrict__ dst, int n)
{
    const int i = blockIdx.x * 1024 + threadIdx.x;
    if (i < n) dst[i] = __float2half_rn(src[i]);
}

// ---------------------------------------------------------------------------
// fp16 mma GEMM (measured-good R12): BM=128, BN=256, BK=64h, cp.async 2-buf.
// ---------------------------------------------------------------------------
template<bool GEN>
__global__ void __launch_bounds__(512) mm2h_kernel(
    const __half* __restrict__ Ah, const __half* __restrict__ Bh,
    const float* __restrict__ bias, float* __restrict__ outp)
{
    extern __shared__ __half smh[];
    const int tid = threadIdx.x, w = tid >> 5, lane = tid & 31;
    const int g = lane >> 2, tq = lane & 3;
    const int bm = blockIdx.x * 128, bn = blockIdx.y * 256;
    const int mw = w & 3, nw = w >> 2;
    const uint32_t smem_base = (uint32_t)__cvta_generic_to_shared(smh);

    float acc[2][8][4] = {};

    auto load_block = [&](int kb, int p) {
        #pragma unroll
        for (int i = 0; i < 2; i++) {
            const int chunk = tid + i * 512;
            const int row = chunk >> 3, c = chunk & 7;
            const __half* src = Ah + (size_t)(bm + row) * 256 + kb * 64 + c * 8;
            cp16(smem_base + (uint32_t)(p * BUFH + row * HS + c * 8) * 2, src, true);
        }
        #pragma unroll
        for (int i = 0; i < 4; i++) {
            const int chunk = tid + i * 512;
            const int row = chunk >> 3, c = chunk & 7;
            const bool ok = !GEN || (bn + row < CC);
            const __half* src = Bh + (size_t)(bn + row) * 256 + kb * 64 + c * 8;
            cp16(smem_base + (uint32_t)(p * BUFH + 128 * HS + row * HS + c * 8) * 2,
                 src, ok);
        }
        asm volatile("cp.async.commit_group;");
    };

    load_block(0, 0);
    for (int kb = 0; kb < 4; kb++) {
        if (kb < 3) {
            load_block(kb + 1, (kb + 1) & 1);
            asm volatile("cp.async.wait_group 1;");
        } else {
            asm volatile("cp.async.wait_group 0;");
        }
        __syncthreads();

        const __half* sa = smh + (kb & 1) * BUFH + (mw * 32) * HS;
        const __half* sb = smh + (kb & 1) * BUFH + 128 * HS + (nw * 64) * HS;
        #pragma unroll
        for (int kt = 0; kt < 4; kt++) {
            const int k0 = kt * 16 + 2 * tq;
            uint32_t a[2][4];
            #pragma unroll
            for (int t = 0; t < 2; t++) {
                a[t][0] = *(const uint32_t*)(sa + (t * 16 + g    ) * HS + k0);
                a[t][1] = *(const uint32_t*)(sa + (t * 16 + g + 8) * HS + k0);
                a[t][2] = *(const uint32_t*)(sa + (t * 16 + g    ) * HS + k0 + 8);
                a[t][3] = *(const uint32_t*)(sa + (t * 16 + g + 8) * HS + k0 + 8);
            }
            #pragma unroll
            for (int j = 0; j < 8; j++) {
                const uint32_t b0 = *(const uint32_t*)(sb + (j * 8 + g) * HS + k0);
                const uint32_t b1 = *(const uint32_t*)(sb + (j * 8 + g) * HS + k0 + 8);
                mma_f16(acc[0][j], a[0][0], a[0][1], a[0][2], a[0][3], b0, b1);
                mma_f16(acc[1][j], a[1][0], a[1][1], a[1][2], a[1][3], b0, b1);
            }
        }
        __syncthreads();
    }

    #pragma unroll
    for (int t = 0; t < 2; t++) {
        const int row = bm + mw * 32 + t * 16 + g;
        #pragma unroll
        for (int j = 0; j < 8; j++) {
            const int col = bn + nw * 64 + j * 8 + 2 * tq;
            if (GEN) {
                if (col < CC) {
                    const float b0 = bias[col], b1 = bias[col + 1];
                    *(float2*)(outp + (size_t)row * CC + col) =
                        make_float2(acc[t][j][0] + b0, acc[t][j][1] + b1);
                    *(float2*)(outp + (size_t)(row + 8) * CC + col) =
                        make_float2(acc[t][j][2] + b0, acc[t][j][3] + b1);
                }
            } else {
                *(__half2*)(g_Hproj + (size_t)row * HH + col) =
                    __floats2half2_rn(acc[t][j][0], acc[t][j][1]);
                *(__half2*)(g_Hproj + (size_t)(row + 8) * HH + col) =
                    __floats2half2_rn(acc[t][j][2], acc[t][j][3]);
            }
        }
    }
}

// ---------------------------------------------------------------------------
// Persistent recurrence. 128 CTAs x 512 threads. fp16 k16 mma + weight ring.
// Hproj streamed (.cs evict-first), bhH L2-resident (.cg), ring prefetch at
// step top so its L2 traffic overlaps stages 1-4.
// ---------------------------------------------------------------------------
__global__ void __launch_bounds__(512) recur_kernel(
    const int* __restrict__ text,
    const float* __restrict__ b_h2h, const float* __restrict__ W_score)
{
    extern __shared__ char smraw[];
    __half* sh_xh = (__half*)(smraw + OFF_XH);
    float*  sh_hp = (float*)(smraw + OFF_HP);
    float*  sh_e  = (float*)(smraw + OFF_E);
    int*    sh_ch = (int*)(smraw + OFF_CH);

    const int tid  = threadIdx.x;
    const int w    = tid >> 5;
    const int lane = tid & 31;
    const int g    = lane >> 2;
    const int tq   = lane & 3;
    const int r0   = blockIdx.x * MROWS;
    const uint32_t swb = (uint32_t)__cvta_generic_to_shared(smraw);

    // per-warp weight-slice prefetch (defined once; used at step top + stage 5)
    auto issue_w = [&](int kt, int r) {
        const char* gb = (const char*)g_WfGatesH;
        const size_t ifo = ((size_t)(kt * 128 + w * 4) * 32) * 8;
        const size_t goo = ((size_t)(kt * 128 + 64 + w * 4) * 32) * 8;
        const uint32_t sb = swb + (uint32_t)(r * 32768 + w * 2048);
        #pragma unroll
        for (int c2 = 0; c2 < 2; c2++) {
            cp16(sb + c2 * 512 + lane * 16,
                 gb + ifo + c2 * 512 + lane * 16, true);
            cp16(sb + 1024 + c2 * 512 + lane * 16,
                 gb + goo + c2 * 512 + lane * 16, true);
        }
        asm volatile("cp.async.commit_group;");
    };

    for (int i = tid; i < MROWS * XSH / 2; i += 512) ((uint32_t*)sh_xh)[i] = 0u;

    float cst0[4] = {0.f, 0.f, 0.f, 0.f};
    float cst1[4] = {0.f, 0.f, 0.f, 0.f};

    float wsr[8];
    #pragma unroll
    for (int j = 0; j < 8; j++) wsr[j] = W_score[lane * 8 + j];

    float2 bh2h_r[2];
    #pragma unroll
    for (int jt = 0; jt < 2; jt++) {
        const int nc = w * 16 + jt * 8 + 2 * tq;
        bh2h_r[jt] = make_float2(b_h2h[nc], b_h2h[nc + 1]);
    }
    __syncthreads();

    for (int s = 0; s < SS; s++) {
        if (tid < MROWS) sh_ch[tid] = text[(r0 + tid) * SS + s];

        // prefetch first 3 weight slices now: L2 fetch overlaps stages 1-4
        issue_w(0, 0); issue_w(1, 1); issue_w(2, 2);

        // ---- Stage 1: hp = h @ W_h2h^T + b  (fp16 mma, K=256) -------------
        {
            float accH[2][4];
            #pragma unroll
            for (int jt = 0; jt < 2; jt++) {
                accH[jt][0] = bh2h_r[jt].x; accH[jt][1] = bh2h_r[jt].y;
                accH[jt][2] = bh2h_r[jt].x; accH[jt][3] = bh2h_r[jt].y;
            }
            const uint2* bp0 = g_WfH2hH + ((size_t)(w * 2    ) * 16) * 32 + lane;
            const uint2* bp1 = g_WfH2hH + ((size_t)(w * 2 + 1) * 16) * 32 + lane;
            #pragma unroll 4
            for (int kt = 0; kt < 16; kt++) {
                const __half* xk = sh_xh + 256 + kt * 16;
                uint32_t a0 = *(const uint32_t*)(xk +  g      * XSH + 2 * tq);
                uint32_t a1 = *(const uint32_t*)(xk + (g + 8) * XSH + 2 * tq);
                uint32_t a2 = *(const uint32_t*)(xk +  g      * XSH + 2 * tq + 8);
                uint32_t a3 = *(const uint32_t*)(xk + (g + 8) * XSH + 2 * tq + 8);
                const uint2 b0 = bp0[kt * 32];
                const uint2 b1 = bp1[kt * 32];
                mma_f16(accH[0], a0, a1, a2, a3, b0.x, b0.y);
                mma_f16(accH[1], a0, a1, a2, a3, b1.x, b1.y);
            }
            #pragma unroll
            for (int jt = 0; jt < 2; jt++) {
                const int nc = w * 16 + jt * 8 + 2 * tq;
                *(float2*)(sh_hp +  g      * HH + nc) = make_float2(accH[jt][0], accH[jt][1]);
                *(float2*)(sh_hp + (g + 8) * HH + nc) = make_float2(accH[jt][2], accH[jt][3]);
            }
        }
        __syncthreads();

        // ---- Stage 2: e[m,t] = Wscore . tanh(Hproj + hp), .cs stream ------
        for (int pb = w * 8; pb < MROWS * TT; pb += 128) {
            float sum[8];
            #pragma unroll
            for (int q = 0; q < 8; q++) {
                const int pp = pb + q;
                const int m = pp >> 6, t = pp & 63;
                const uint4 raw = __ldcs((const uint4*)(g_Hproj +
                    ((size_t)(r0 + m) * TT + t) * HH + lane * 8));
                const __half2* hr = (const __half2*)&raw;
                const float4 b0 = *(const float4*)(sh_hp + m * HH + lane * 8);
                const float4 b1 = *(const float4*)(sh_hp + m * HH + lane * 8 + 4);
                const float2 f0 = __half22float2(hr[0]);
                const float2 f1 = __half22float2(hr[1]);
                const float2 f2 = __half22float2(hr[2]);
                const float2 f3 = __half22float2(hr[3]);
                sum[q] = wsr[0] * ftanh(f0.x + b0.x) + wsr[1] * ftanh(f0.y + b0.y)
                       + wsr[2] * ftanh(f1.x + b0.z) + wsr[3] * ftanh(f1.y + b0.w)
                       + wsr[4] * ftanh(f2.x + b1.x) + wsr[5] * ftanh(f2.y + b1.y)
                       + wsr[6] * ftanh(f3.x + b1.z) + wsr[7] * ftanh(f3.y + b1.w);
            }
            #pragma unroll
            for (int q = 0; q < 8; q++) {
                float sq = sum[q];
                #pragma unroll
                for (int o = 16; o > 0; o >>= 1)
                    sq += __shfl_xor_sync(0xffffffffu, sq, o);
                if (lane == 0) sh_e[pb + q] = sq;
            }
        }
        __syncthreads();

        // ---- Stage 3: softmax over t, 1 row per warp ----------------------
        {
            const int m = w;
            float e0 = sh_e[m * TT + lane];
            float e1 = sh_e[m * TT + 32 + lane];
            float mx = fmaxf(e0, e1);
            #pragma unroll
            for (int o = 16; o > 0; o >>= 1)
                mx = fmaxf(mx, __shfl_xor_sync(0xffffffffu, mx, o));
            float x0 = __expf(e0 - mx), x1 = __expf(e1 - mx);
            float sume = x0 + x1;
            #pragma unroll
            for (int o = 16; o > 0; o >>= 1)
                sume += __shfl_xor_sync(0xffffffffu, sume, o);
            float inv = __frcp_rn(sume);
            sh_e[m * TT + lane]      = x0 * inv;
            sh_e[m * TT + 32 + lane] = x1 * inv;
        }
        __syncthreads();

        // ---- Stage 4: ctx[m,:] -> sh_xh (fp16). .cg: bhH stays in L2 ------
        {
            const int m = w;
            const __half* bh = g_bhH + ((size_t)(r0 + m) * TT) * DD + lane * 8;
            float acc[8] = {};
            #pragma unroll 8
            for (int t = 0; t < TT; t++) {
                const float a = sh_e[m * TT + t];
                const uint4 raw = __ldcg((const uint4*)(bh + (size_t)t * DD));
                const __half2* hr = (const __half2*)&raw;
                const float2 v0 = __half22float2(hr[0]);
                const float2 v1 = __half22float2(hr[1]);
                const float2 v2 = __half22float2(hr[2]);
                const float2 v3 = __half22float2(hr[3]);
                acc[0] += a * v0.x; acc[1] += a * v0.y;
                acc[2] += a * v1.x; acc[3] += a * v1.y;
                acc[4] += a * v2.x; acc[5] += a * v2.y;
                acc[6] += a * v3.x; acc[7] += a * v3.y;
            }
            __half* dst = sh_xh + m * XSH + lane * 8;
            uint2 p0, p1;
            __half2 t0 = __floats2half2_rn(acc[0], acc[1]);
            __half2 t1 = __floats2half2_rn(acc[2], acc[3]);
            __half2 t2 = __floats2half2_rn(acc[4], acc[5]);
            __half2 t3 = __floats2half2_rn(acc[6], acc[7]);
            p0.x = *(uint32_t*)&t0; p0.y = *(uint32_t*)&t1;
            p1.x = *(uint32_t*)&t2; p1.y = *(uint32_t*)&t3;
            *(uint2*)dst       = p0;
            *(uint2*)(dst + 4) = p1;
        }
        __syncthreads();

        // ---- Stage 5: gates (fp16 mma) + LSTM, weights via cp.async ring --
        {
            // accumulator init (one-hot + bias)
            const int chg  = sh_ch[g];
            const int chg8 = sh_ch[g + 8];
            float accIF[4][4], accGO[4][4];
            #pragma unroll
            for (int jt = 0; jt < 4; jt++) {
                const int nIF = w * 32 + jt * 8 + 2 * tq;
                const float2 bIF = *(const float2*)(g_biasP + nIF);
                const float2 bGO = *(const float2*)(g_biasP + 512 + nIF);
                const float2 oIg  = *(const float2*)(g_WohP + (size_t)chg  * 1024 + nIF);
                const float2 oIg8 = *(const float2*)(g_WohP + (size_t)chg8 * 1024 + nIF);
                const float2 oGg  = *(const float2*)(g_WohP + (size_t)chg  * 1024 + 512 + nIF);
                const float2 oGg8 = *(const float2*)(g_WohP + (size_t)chg8 * 1024 + 512 + nIF);
                accIF[jt][0] = bIF.x + oIg.x;  accIF[jt][1] = bIF.y + oIg.y;
                accIF[jt][2] = bIF.x + oIg8.x; accIF[jt][3] = bIF.y + oIg8.y;
                accGO[jt][0] = bGO.x + oGg.x;  accGO[jt][1] = bGO.y + oGg.y;
                accGO[jt][2] = bGO.x + oGg8.x; accGO[jt][3] = bGO.y + oGg8.y;
            }

            for (int kt = 0; kt < 32; kt++) {
                if (kt + 3 < 32) issue_w(kt + 3, (kt + 3) & 3);
                else asm volatile("cp.async.commit_group;");
                asm volatile("cp.async.wait_group 3;");
                __syncwarp();

                const uint2* wp = (const uint2*)(smraw + ((kt & 3) * 32768 + w * 2048));
                const __half* xk = sh_xh + kt * 16;
                uint32_t a0 = *(const uint32_t*)(xk +  g      * XSH + 2 * tq);
                uint32_t a1 = *(const uint32_t*)(xk + (g + 8) * XSH + 2 * tq);
                uint32_t a2 = *(const uint32_t*)(xk +  g      * XSH + 2 * tq + 8);
                uint32_t a3 = *(const uint32_t*)(xk + (g + 8) * XSH + 2 * tq + 8);
                #pragma unroll
                for (int jt = 0; jt < 4; jt++) {
                    const uint2 bv = wp[jt * 32 + lane];
                    mma_f16(accIF[jt], a0, a1, a2, a3, bv.x, bv.y);
                    const uint2 bw = wp[128 + jt * 32 + lane];
                    mma_f16(accGO[jt], a0, a1, a2, a3, bw.x, bw.y);
                }
            }
            __syncthreads();   // all sh_xh reads done before h overwrite
            #pragma unroll
            for (int jt = 0; jt < 4; jt++) {
                const int u = w * 16 + jt * 4 + tq;
                {
                    const float cnew = fsig(accIF[jt][1]) * cst0[jt]
                                     + fsig(accIF[jt][0]) * ftanh(accGO[jt][0]);
                    cst0[jt] = cnew;
                    const float hv = fsig(accGO[jt][1]) * ftanh(cnew);
                    g_hidden[((size_t)(r0 + g) * SS + s) * HH + u] = __float2half_rn(hv);
                    sh_xh[g * XSH + 256 + u] = __float2half_rn(hv);
                }
                {
                    const float cnew = fsig(accIF[jt][3]) * cst1[jt]
                                     + fsig(accIF[jt][2]) * ftanh(accGO[jt][2]);
                    cst1[jt] = cnew;
                    const float hv = fsig(accGO[jt][3]) * ftanh(cnew);
                    g_hidden[((size_t)(r0 + g + 8) * SS + s) * HH + u] = __float2half_rn(hv);
                    sh_xh[(g + 8) * XSH + 256 + u] = __float2half_rn(hv);
                }
            }
        }
        __syncthreads();
    }
}

// ---------------------------------------------------------------------------
extern "C" void kernel_launch(void* const* d_in, const int* in_sizes, int n_in,
                              void* d_out, int out_size)
{
    const float* batch_H = (const float*)d_in[0];
    const int*   text    = (const int*)  d_in[1];
    const float* W_i2h   = (const float*)d_in[2];
    const float* W_h2h   = (const float*)d_in[3];
    const float* b_h2h   = (const float*)d_in[4];
    const float* W_score = (const float*)d_in[5];
    const float* W_ih    = (const float*)d_in[6];
    const float* W_hh    = (const float*)d_in[7];
    const float* b_ih    = (const float*)d_in[8];
    const float* b_hh    = (const float*)d_in[9];
    const float* W_gen   = (const float*)d_in[10];
    const float* b_gen   = (const float*)d_in[11];
    float* out = (float*)d_out;

    __half* d_WihH;  cudaGetSymbolAddress((void**)&d_WihH,  g_WihH);
    __half* d_WgenH; cudaGetSymbolAddress((void**)&d_WgenH, g_WgenH);
    __half* d_bhH;   cudaGetSymbolAddress((void**)&d_bhH,   g_bhH);
    __half* d_hid;   cudaGetSymbolAddress((void**)&d_hid,   g_hidden);

    pack_gates_h<<<128, 1024>>>(W_ih, W_hh);
    pack_h2h_h<<<16, 1024>>>(W_h2h);
    pack_oh<<<32, 1024>>>(W_ih, b_ih, b_hh);
    pack_bh<<<(BB * TT * DD) / 4096, 1024>>>(batch_H);
    pack_w_h<<<64, 1024>>>(W_i2h, d_WihH, 256 * 256);
    pack_w_h<<<250, 1024>>>(W_gen, d_WgenH, 1000 * 256);

    cudaFuncSetAttribute(mm2h_kernel<false>,
                         cudaFuncAttributeMaxDynamicSharedMemorySize, MM2H_SMEM);
    cudaFuncSetAttribute(mm2h_kernel<true>,
                         cudaFuncAttributeMaxDynamicSharedMemorySize, MM2H_SMEM);

    // H_proj: M=131072, N=256 -> grid (1024, 1)
    mm2h_kernel<false><<<dim3((BB * TT) / 128, 1), 512, MM2H_SMEM>>>(
        d_bhH, d_WihH, nullptr, nullptr);

    cudaFuncSetAttribute(recur_kernel, cudaFuncAttributeMaxDynamicSharedMemorySize,
                         RECUR_SMEM);
    recur_kernel<<<BB / MROWS, 512, RECUR_SMEM>>>(text, b_h2h, W_score);

    // probs: M=53248, N=1000 -> grid (416, 4)
    mm2h_kernel<true><<<dim3((BB * SS) / 128, 4), 512, MM2H_SMEM>>>(
        d_hid, d_WgenH, b_gen, out);
}

// round 16
// speedup vs baseline: 4.7379x; 1.0082x over previous
#include <cuda_runtime.h>
#include <cuda_fp16.h>
#include <cstdint>

#define BB   2048
#define TT   64
#define DD   256
#define HH   256
#define CC   1000
#define SS   26
#define DCC  1256   // D + C
#define MROWS 16    // batch rows per recurrence CTA
#define XSH  520    // sh_xh row stride (halfs): 260 words, %32==4 -> conflict-free
#define HS   72     // mm2h smem row stride (halfs)
#define BUFH (384 * HS)
#define MM2H_SMEM (2 * BUFH * 2)

// recur smem layout (bytes)
#define SW_BYTES   (4 * 32768)                  // weight ring: 4 slices x 32 KB
#define OFF_XH     SW_BYTES                     // 16 x XSH halfs = 16640
#define OFF_HP     (OFF_XH + MROWS * XSH * 2)   // 16 x 256 f32 = 16384
#define OFF_E      (OFF_HP + MROWS * HH * 4)    // 16 x 64 f32 = 4096
#define OFF_CH     (OFF_E + MROWS * TT * 4)     // 16 ints
#define RECUR_SMEM (OFF_CH + MROWS * 4)

// Scratch (allocation-free: __device__ globals)
__device__ __half g_Hproj[(size_t)BB * TT * HH];   // 64 MB (fp16), streamed (.cs)
__device__ __half g_bhH[(size_t)BB * TT * DD];     // 64 MB fp16, L2-resident (.cg)
__device__ __half g_hidden[(size_t)BB * SS * HH];  // 26 MB (fp16)
__device__ uint2  g_WfGatesH[32 * 128 * 32];       // 1 MB  fp16 B-frags [kt][nt][lane]
__device__ uint2  g_WfH2hH[32 * 16 * 32];          // 128 KB fp16 B-frags, h2h
__device__ float  g_WohP[1000 * 1024];             // 4 MB  one-hot cols, packed
__device__ float  g_biasP[1024];                   // b_ih+b_hh, packed order
__device__ __half g_WihH[256 * 256];               // fp16 W_i2h
__device__ __half g_WgenH[1000 * 256];             // fp16 W_gen

__device__ __forceinline__ float ftanh(float x) {
    float y;
    asm("tanh.approx.f32 %0, %1;" : "=f"(y) : "f"(x));
    return y;
}
__device__ __forceinline__ float fsig(float x) {
    return 0.5f * ftanh(0.5f * x) + 0.5f;
}
__device__ __forceinline__ void mma_f16(float* c,
    uint32_t a0, uint32_t a1, uint32_t a2, uint32_t a3,
    uint32_t b0, uint32_t b1)
{
    asm volatile(
        "mma.sync.aligned.m16n8k16.row.col.f32.f16.f16.f32 "
        "{%0,%1,%2,%3}, {%4,%5,%6,%7}, {%8,%9}, {%0,%1,%2,%3};"
        : "+f"(c[0]), "+f"(c[1]), "+f"(c[2]), "+f"(c[3])
        : "r"(a0), "r"(a1), "r"(a2), "r"(a3), "r"(b0), "r"(b1));
}
__device__ __forceinline__ void cp16(uint32_t dst, const void* src, bool pred) {
    const int sz = pred ? 16 : 0;
    asm volatile("cp.async.cg.shared.global [%0], [%1], 16, %2;"
                 :: "r"(dst), "l"(src), "r"(sz));
}

__device__ __forceinline__ int packed_gate_row(int nprime) {
    const int np = nprime & 511, u = np >> 1, b = np & 1;
    const bool go = nprime >= 512;
    return u + (go ? (b ? 768 : 512) : (b ? 256 : 0));   // rows: i|f|g|o
}
__device__ __forceinline__ float gate_w(const float* W_ih, const float* W_hh,
                                        int row, int k) {
    return (k < 256) ? W_ih[(size_t)row * DCC + k]
                     : W_hh[(size_t)row * HH + k - 256];
}

// ---------------------------------------------------------------------------
// Pack kernels (unchanged from R14)
// ---------------------------------------------------------------------------
__global__ void __launch_bounds__(1024) pack_gates_h(
    const float* __restrict__ W_ih, const float* __restrict__ W_hh)
{
    const int idx = blockIdx.x * 1024 + threadIdx.x;   // 131072
    const int lane = idx & 31, g = lane >> 2, tq = lane & 3;
    const int nt = (idx >> 5) & 127;
    const int kt = idx >> 12;
    const int npr = (nt & 63) * 8 + g + ((nt >= 64) ? 512 : 0);
    const int row = packed_gate_row(npr);
    const int k0 = kt * 16 + 2 * tq;
    __half2 h0 = __floats2half2_rn(gate_w(W_ih, W_hh, row, k0),
                                   gate_w(W_ih, W_hh, row, k0 + 1));
    __half2 h1 = __floats2half2_rn(gate_w(W_ih, W_hh, row, k0 + 8),
                                   gate_w(W_ih, W_hh, row, k0 + 9));
    uint2 v;
    v.x = *(uint32_t*)&h0; v.y = *(uint32_t*)&h1;
    g_WfGatesH[idx] = v;
}

__global__ void __launch_bounds__(1024) pack_h2h_h(const float* __restrict__ W_h2h)
{
    const int idx = blockIdx.x * 1024 + threadIdx.x;
    const int lane = idx & 31, g = lane >> 2, tq = lane & 3;
    const int kt = (idx >> 5) & 15;
    const int nt = idx >> 9;
    const int n = nt * 8 + g;
    const int k0 = kt * 16 + 2 * tq;
    __half2 h0 = __floats2half2_rn(W_h2h[n * HH + k0],     W_h2h[n * HH + k0 + 1]);
    __half2 h1 = __floats2half2_rn(W_h2h[n * HH + k0 + 8], W_h2h[n * HH + k0 + 9]);
    uint2 v;
    v.x = *(uint32_t*)&h0; v.y = *(uint32_t*)&h1;
    g_WfH2hH[idx] = v;
}

__global__ void __launch_bounds__(1024) pack_oh(
    const float* __restrict__ W_ih,
    const float* __restrict__ b_ih, const float* __restrict__ b_hh)
{
    const int cb = blockIdx.x;        // 0..31
    const int np = threadIdx.x;       // 0..1023
    const int row = packed_gate_row(np);
    const float* src = W_ih + (size_t)row * DCC + 256 + cb * 32;
    #pragma unroll
    for (int j4 = 0; j4 < 8; j4++) {
        const int c = cb * 32 + j4 * 4;
        if (c + 3 < CC) {
            const float4 v = *(const float4*)(src + j4 * 4);
            g_WohP[(size_t)(c    ) * 1024 + np] = v.x;
            g_WohP[(size_t)(c + 1) * 1024 + np] = v.y;
            g_WohP[(size_t)(c + 2) * 1024 + np] = v.z;
            g_WohP[(size_t)(c + 3) * 1024 + np] = v.w;
        } else {
            #pragma unroll
            for (int j = 0; j < 4; j++)
                if (c + j < CC)
                    g_WohP[(size_t)(c + j) * 1024 + np] = src[j4 * 4 + j];
        }
    }
    if (cb == 0) g_biasP[np] = b_ih[row] + b_hh[row];
}

__global__ void __launch_bounds__(1024) pack_bh(const float* __restrict__ bH)
{
    const size_t i = ((size_t)blockIdx.x * 1024 + threadIdx.x) * 4;
    const float4 v = *(const float4*)(bH + i);
    *(__half2*)(g_bhH + i)     = __floats2half2_rn(v.x, v.y);
    *(__half2*)(g_bhH + i + 2) = __floats2half2_rn(v.z, v.w);
}

__global__ void __launch_bounds__(1024) pack_w_h(
    const float* __restrict__ src, __half* __restrict__ dst, int n)
{
    const int i = blockIdx.x * 1024 + threadIdx.x;
    if (i < n) dst[i] = __float2half_rn(src[i]);
}

// ---------------------------------------------------------------------------
// fp16 mma GEMM (measured-good R12): BM=128, BN=256, BK=64h, cp.async 2-buf.
// ---------------------------------------------------------------------------
template<bool GEN>
__global__ void __launch_bounds__(512) mm2h_kernel(
    const __half* __restrict__ Ah, const __half* __restrict__ Bh,
    const float* __restrict__ bias, float* __restrict__ outp)
{
    extern __shared__ __half smh[];
    const int tid = threadIdx.x, w = tid >> 5, lane = tid & 31;
    const int g = lane >> 2, tq = lane & 3;
    const int bm = blockIdx.x * 128, bn = blockIdx.y * 256;
    const int mw = w & 3, nw = w >> 2;
    const uint32_t smem_base = (uint32_t)__cvta_generic_to_shared(smh);

    float acc[2][8][4] = {};

    auto load_block = [&](int kb, int p) {
        #pragma unroll
        for (int i = 0; i < 2; i++) {
            const int chunk = tid + i * 512;
            const int row = chunk >> 3, c = chunk & 7;
            const __half* src = Ah + (size_t)(bm + row) * 256 + kb * 64 + c * 8;
            cp16(smem_base + (uint32_t)(p * BUFH + row * HS + c * 8) * 2, src, true);
        }
        #pragma unroll
        for (int i = 0; i < 4; i++) {
            const int chunk = tid + i * 512;
            const int row = chunk >> 3, c = chunk & 7;
            const bool ok = !GEN || (bn + row < CC);
            const __half* src = Bh + (size_t)(bn + row) * 256 + kb * 64 + c * 8;
            cp16(smem_base + (uint32_t)(p * BUFH + 128 * HS + row * HS + c * 8) * 2,
                 src, ok);
        }
        asm volatile("cp.async.commit_group;");
    };

    load_block(0, 0);
    for (int kb = 0; kb < 4; kb++) {
        if (kb < 3) {
            load_block(kb + 1, (kb + 1) & 1);
            asm volatile("cp.async.wait_group 1;");
        } else {
            asm volatile("cp.async.wait_group 0;");
        }
        __syncthreads();

        const __half* sa = smh + (kb & 1) * BUFH + (mw * 32) * HS;
        const __half* sb = smh + (kb & 1) * BUFH + 128 * HS + (nw * 64) * HS;
        #pragma unroll
        for (int kt = 0; kt < 4; kt++) {
            const int k0 = kt * 16 + 2 * tq;
            uint32_t a[2][4];
            #pragma unroll
            for (int t = 0; t < 2; t++) {
                a[t][0] = *(const uint32_t*)(sa + (t * 16 + g    ) * HS + k0);
                a[t][1] = *(const uint32_t*)(sa + (t * 16 + g + 8) * HS + k0);
                a[t][2] = *(const uint32_t*)(sa + (t * 16 + g    ) * HS + k0 + 8);
                a[t][3] = *(const uint32_t*)(sa + (t * 16 + g + 8) * HS + k0 + 8);
            }
            #pragma unroll
            for (int j = 0; j < 8; j++) {
                const uint32_t b0 = *(const uint32_t*)(sb + (j * 8 + g) * HS + k0);
                const uint32_t b1 = *(const uint32_t*)(sb + (j * 8 + g) * HS + k0 + 8);
                mma_f16(acc[0][j], a[0][0], a[0][1], a[0][2], a[0][3], b0, b1);
                mma_f16(acc[1][j], a[1][0], a[1][1], a[1][2], a[1][3], b0, b1);
            }
        }
        __syncthreads();
    }

    #pragma unroll
    for (int t = 0; t < 2; t++) {
        const int row = bm + mw * 32 + t * 16 + g;
        #pragma unroll
        for (int j = 0; j < 8; j++) {
            const int col = bn + nw * 64 + j * 8 + 2 * tq;
            if (GEN) {
                if (col < CC) {
                    const float b0 = bias[col], b1 = bias[col + 1];
                    *(float2*)(outp + (size_t)row * CC + col) =
                        make_float2(acc[t][j][0] + b0, acc[t][j][1] + b1);
                    *(float2*)(outp + (size_t)(row + 8) * CC + col) =
                        make_float2(acc[t][j][2] + b0, acc[t][j][3] + b1);
                }
            } else {
                *(__half2*)(g_Hproj + (size_t)row * HH + col) =
                    __floats2half2_rn(acc[t][j][0], acc[t][j][1]);
                *(__half2*)(g_Hproj + (size_t)(row + 8) * HH + col) =
                    __floats2half2_rn(acc[t][j][2], acc[t][j][3]);
            }
        }
    }
}

// ---------------------------------------------------------------------------
// Persistent recurrence. 128 CTAs x 512 threads.
// Stage-5 h-half (kt 16..31) interleaved into stage 2 so its L2 weight
// stream overlaps the Hproj DRAM stream. ctx-half (kt 0..15) after stage 4.
// ---------------------------------------------------------------------------
__global__ void __launch_bounds__(512) recur_kernel(
    const int* __restrict__ text,
    const float* __restrict__ b_h2h, const float* __restrict__ W_score)
{
    extern __shared__ char smraw[];
    __half* sh_xh = (__half*)(smraw + OFF_XH);
    float*  sh_hp = (float*)(smraw + OFF_HP);
    float*  sh_e  = (float*)(smraw + OFF_E);
    int*    sh_ch = (int*)(smraw + OFF_CH);

    const int tid  = threadIdx.x;
    const int w    = tid >> 5;
    const int lane = tid & 31;
    const int g    = lane >> 2;
    const int tq   = lane & 3;
    const int r0   = blockIdx.x * MROWS;
    const uint32_t swb = (uint32_t)__cvta_generic_to_shared(smraw);

    // per-warp weight-slice prefetch; ring slot r, global kt
    auto issue_w = [&](int kt, int r) {
        const char* gb = (const char*)g_WfGatesH;
        const size_t ifo = ((size_t)(kt * 128 + w * 4) * 32) * 8;
        const size_t goo = ((size_t)(kt * 128 + 64 + w * 4) * 32) * 8;
        const uint32_t sb = swb + (uint32_t)(r * 32768 + w * 2048);
        #pragma unroll
        for (int c2 = 0; c2 < 2; c2++) {
            cp16(sb + c2 * 512 + lane * 16,
                 gb + ifo + c2 * 512 + lane * 16, true);
            cp16(sb + 1024 + c2 * 512 + lane * 16,
                 gb + goo + c2 * 512 + lane * 16, true);
        }
        asm volatile("cp.async.commit_group;");
    };

    for (int i = tid; i < MROWS * XSH / 2; i += 512) ((uint32_t*)sh_xh)[i] = 0u;

    float cst0[4] = {0.f, 0.f, 0.f, 0.f};
    float cst1[4] = {0.f, 0.f, 0.f, 0.f};

    float wsr[8];
    #pragma unroll
    for (int j = 0; j < 8; j++) wsr[j] = W_score[lane * 8 + j];

    float2 bh2h_r[2];
    #pragma unroll
    for (int jt = 0; jt < 2; jt++) {
        const int nc = w * 16 + jt * 8 + 2 * tq;
        bh2h_r[jt] = make_float2(b_h2h[nc], b_h2h[nc + 1]);
    }
    __syncthreads();

    for (int s = 0; s < SS; s++) {
        if (tid < MROWS) sh_ch[tid] = text[(r0 + tid) * SS + s];

        // prefetch first 3 h-half weight slices (kt 16..18)
        issue_w(16, 0); issue_w(17, 1); issue_w(18, 2);

        // ---- Stage 1: hp = h @ W_h2h^T + b  (fp16 mma, K=256) -------------
        {
            float accH[2][4];
            #pragma unroll
            for (int jt = 0; jt < 2; jt++) {
                accH[jt][0] = bh2h_r[jt].x; accH[jt][1] = bh2h_r[jt].y;
                accH[jt][2] = bh2h_r[jt].x; accH[jt][3] = bh2h_r[jt].y;
            }
            const uint2* bp0 = g_WfH2hH + ((size_t)(w * 2    ) * 16) * 32 + lane;
            const uint2* bp1 = g_WfH2hH + ((size_t)(w * 2 + 1) * 16) * 32 + lane;
            #pragma unroll 4
            for (int kt = 0; kt < 16; kt++) {
                const __half* xk = sh_xh + 256 + kt * 16;
                uint32_t a0 = *(const uint32_t*)(xk +  g      * XSH + 2 * tq);
                uint32_t a1 = *(const uint32_t*)(xk + (g + 8) * XSH + 2 * tq);
                uint32_t a2 = *(const uint32_t*)(xk +  g      * XSH + 2 * tq + 8);
                uint32_t a3 = *(const uint32_t*)(xk + (g + 8) * XSH + 2 * tq + 8);
                const uint2 b0 = bp0[kt * 32];
                const uint2 b1 = bp1[kt * 32];
                mma_f16(accH[0], a0, a1, a2, a3, b0.x, b0.y);
                mma_f16(accH[1], a0, a1, a2, a3, b1.x, b1.y);
            }
            #pragma unroll
            for (int jt = 0; jt < 2; jt++) {
                const int nc = w * 16 + jt * 8 + 2 * tq;
                *(float2*)(sh_hp +  g      * HH + nc) = make_float2(accH[jt][0], accH[jt][1]);
                *(float2*)(sh_hp + (g + 8) * HH + nc) = make_float2(accH[jt][2], accH[jt][3]);
            }
        }
        __syncthreads();

        // gate accumulators: one-hot + bias (sh_ch visible after barrier)
        const int chg  = sh_ch[g];
        const int chg8 = sh_ch[g + 8];
        float accIF[4][4], accGO[4][4];
        #pragma unroll
        for (int jt = 0; jt < 4; jt++) {
            const int nIF = w * 32 + jt * 8 + 2 * tq;
            const float2 bIF = *(const float2*)(g_biasP + nIF);
            const float2 bGO = *(const float2*)(g_biasP + 512 + nIF);
            const float2 oIg  = *(const float2*)(g_WohP + (size_t)chg  * 1024 + nIF);
            const float2 oIg8 = *(const float2*)(g_WohP + (size_t)chg8 * 1024 + nIF);
            const float2 oGg  = *(const float2*)(g_WohP + (size_t)chg  * 1024 + 512 + nIF);
            const float2 oGg8 = *(const float2*)(g_WohP + (size_t)chg8 * 1024 + 512 + nIF);
            accIF[jt][0] = bIF.x + oIg.x;  accIF[jt][1] = bIF.y + oIg.y;
            accIF[jt][2] = bIF.x + oIg8.x; accIF[jt][3] = bIF.y + oIg8.y;
            accGO[jt][0] = bGO.x + oGg.x;  accGO[jt][1] = bGO.y + oGg.y;
            accGO[jt][2] = bGO.x + oGg8.x; accGO[jt][3] = bGO.y + oGg8.y;
        }

        // ---- Stage 2 fused with h-half gate mma (kt 16..31) ---------------
        for (int it = 0; it < 8; it++) {
            const int pb = w * 8 + it * 128;
            float sum[8];
            #pragma unroll
            for (int q = 0; q < 8; q++) {
                const int pp = pb + q;
                const int m = pp >> 6, t = pp & 63;
                const uint4 raw = __ldcs((const uint4*)(g_Hproj +
                    ((size_t)(r0 + m) * TT + t) * HH + lane * 8));
                const __half2* hr = (const __half2*)&raw;
                const float4 b0 = *(const float4*)(sh_hp + m * HH + lane * 8);
                const float4 b1 = *(const float4*)(sh_hp + m * HH + lane * 8 + 4);
                const float2 f0 = __half22float2(hr[0]);
                const float2 f1 = __half22float2(hr[1]);
                const float2 f2 = __half22float2(hr[2]);
                const float2 f3 = __half22float2(hr[3]);
                sum[q] = wsr[0] * ftanh(f0.x + b0.x) + wsr[1] * ftanh(f0.y + b0.y)
                       + wsr[2] * ftanh(f1.x + b0.z) + wsr[3] * ftanh(f1.y + b0.w)
                       + wsr[4] * ftanh(f2.x + b1.x) + wsr[5] * ftanh(f2.y + b1.y)
                       + wsr[6] * ftanh(f3.x + b1.z) + wsr[7] * ftanh(f3.y + b1.w);
            }
            #pragma unroll
            for (int q = 0; q < 8; q++) {
                float sq = sum[q];
                #pragma unroll
                for (int o = 16; o > 0; o >>= 1)
                    sq += __shfl_xor_sync(0xffffffffu, sq, o);
                if (lane == 0) sh_e[pb + q] = sq;
            }
            // two h-kt mma iterations
            #pragma unroll
            for (int j = 0; j < 2; j++) {
                const int kt = 16 + it * 2 + j;
                if (kt <= 28) {
                    issue_w(kt + 3, (kt + 3 - 16) & 3);
                    asm volatile("cp.async.wait_group 3;");
                } else {
                    asm volatile("cp.async.wait_group 0;");
                }
                __syncwarp();
                const uint2* wp = (const uint2*)(smraw +
                    (((kt - 16) & 3) * 32768 + w * 2048));
                const __half* xk = sh_xh + kt * 16;   // h region (256..511)
                uint32_t a0 = *(const uint32_t*)(xk +  g      * XSH + 2 * tq);
                uint32_t a1 = *(const uint32_t*)(xk + (g + 8) * XSH + 2 * tq);
                uint32_t a2 = *(const uint32_t*)(xk +  g      * XSH + 2 * tq + 8);
                uint32_t a3 = *(const uint32_t*)(xk + (g + 8) * XSH + 2 * tq + 8);
                #pragma unroll
                for (int jt = 0; jt < 4; jt++) {
                    const uint2 bv = wp[jt * 32 + lane];
                    mma_f16(accIF[jt], a0, a1, a2, a3, bv.x, bv.y);
                    const uint2 bw = wp[128 + jt * 32 + lane];
                    mma_f16(accGO[jt], a0, a1, a2, a3, bw.x, bw.y);
                }
            }
        }
        __syncthreads();

        // ---- Stage 3: softmax over t, 1 row per warp ----------------------
        {
            const int m = w;
            float e0 = sh_e[m * TT + lane];
            float e1 = sh_e[m * TT + 32 + lane];
            float mx = fmaxf(e0, e1);
            #pragma unroll
            for (int o = 16; o > 0; o >>= 1)
                mx = fmaxf(mx, __shfl_xor_sync(0xffffffffu, mx, o));
            float x0 = __expf(e0 - mx), x1 = __expf(e1 - mx);
            float sume = x0 + x1;
            #pragma unroll
            for (int o = 16; o > 0; o >>= 1)
                sume += __shfl_xor_sync(0xffffffffu, sume, o);
            float inv = __frcp_rn(sume);
            sh_e[m * TT + lane]      = x0 * inv;
            sh_e[m * TT + 32 + lane] = x1 * inv;
        }
        __syncwarp();   // stage 4 (same warp, same row) reads these alphas

        // ---- Stage 4: ctx[m,:] -> sh_xh (fp16). .cg: bhH stays in L2 ------
        {
            const int m = w;
            const __half* bh = g_bhH + ((size_t)(r0 + m) * TT) * DD + lane * 8;
            float acc[8] = {};
            #pragma unroll 8
            for (int t = 0; t < TT; t++) {
                const float a = sh_e[m * TT + t];
                const uint4 raw = __ldcg((const uint4*)(bh + (size_t)t * DD));
                const __half2* hr = (const __half2*)&raw;
                const float2 v0 = __half22float2(hr[0]);
                const float2 v1 = __half22float2(hr[1]);
                const float2 v2 = __half22float2(hr[2]);
                const float2 v3 = __half22float2(hr[3]);
                acc[0] += a * v0.x; acc[1] += a * v0.y;
                acc[2] += a * v1.x; acc[3] += a * v1.y;
                acc[4] += a * v2.x; acc[5] += a * v2.y;
                acc[6] += a * v3.x; acc[7] += a * v3.y;
            }
            __half* dst = sh_xh + m * XSH + lane * 8;
            uint2 p0, p1;
            __half2 t0 = __floats2half2_rn(acc[0], acc[1]);
            __half2 t1 = __floats2half2_rn(acc[2], acc[3]);
            __half2 t2 = __floats2half2_rn(acc[4], acc[5]);
            __half2 t3 = __floats2half2_rn(acc[6], acc[7]);
            p0.x = *(uint32_t*)&t0; p0.y = *(uint32_t*)&t1;
            p1.x = *(uint32_t*)&t2; p1.y = *(uint32_t*)&t3;
            *(uint2*)dst       = p0;
            *(uint2*)(dst + 4) = p1;
        }
        __syncthreads();

        // ---- Stage 5b: ctx-half gate mma (kt 0..15) + LSTM ----------------
        {
            issue_w(0, 0); issue_w(1, 1); issue_w(2, 2);
            for (int kt = 0; kt < 16; kt++) {
                if (kt <= 12) {
                    issue_w(kt + 3, (kt + 3) & 3);
                    asm volatile("cp.async.wait_group 3;");
                } else {
                    asm volatile("cp.async.wait_group 0;");
                }
                __syncwarp();
                const uint2* wp = (const uint2*)(smraw + ((kt & 3) * 32768 + w * 2048));
                const __half* xk = sh_xh + kt * 16;   // ctx region (0..255)
                uint32_t a0 = *(const uint32_t*)(xk +  g      * XSH + 2 * tq);
                uint32_t a1 = *(const uint32_t*)(xk + (g + 8) * XSH + 2 * tq);
                uint32_t a2 = *(const uint32_t*)(xk +  g      * XSH + 2 * tq + 8);
                uint32_t a3 = *(const uint32_t*)(xk + (g + 8) * XSH + 2 * tq + 8);
                #pragma unroll
                for (int jt = 0; jt < 4; jt++) {
                    const uint2 bv = wp[jt * 32 + lane];
                    mma_f16(accIF[jt], a0, a1, a2, a3, bv.x, bv.y);
                    const uint2 bw = wp[128 + jt * 32 + lane];
                    mma_f16(accGO[jt], a0, a1, a2, a3, bw.x, bw.y);
                }
            }
            __syncthreads();   // all sh_xh reads done before h overwrite
            #pragma unroll
            for (int jt = 0; jt < 4; jt++) {
                const int u = w * 16 + jt * 4 + tq;
                {
                    const float cnew = fsig(accIF[jt][1]) * cst0[jt]
                                     + fsig(accIF[jt][0]) * ftanh(accGO[jt][0]);
                    cst0[jt] = cnew;
                    const float hv = fsig(accGO[jt][1]) * ftanh(cnew);
                    g_hidden[((size_t)(r0 + g) * SS + s) * HH + u] = __float2half_rn(hv);
                    sh_xh[g * XSH + 256 + u] = __float2half_rn(hv);
                }
                {
                    const float cnew = fsig(accIF[jt][3]) * cst1[jt]
                                     + fsig(accIF[jt][2]) * ftanh(accGO[jt][2]);
                    cst1[jt] = cnew;
                    const float hv = fsig(accGO[jt][3]) * ftanh(cnew);
                    g_hidden[((size_t)(r0 + g + 8) * SS + s) * HH + u] = __float2half_rn(hv);
                    sh_xh[(g + 8) * XSH + 256 + u] = __float2half_rn(hv);
                }
            }
        }
        __syncthreads();
    }
}

// ---------------------------------------------------------------------------
extern "C" void kernel_launch(void* const* d_in, const int* in_sizes, int n_in,
                              void* d_out, int out_size)
{
    const float* batch_H = (const float*)d_in[0];
    const int*   text    = (const int*)  d_in[1];
    const float* W_i2h   = (const float*)d_in[2];
    const float* W_h2h   = (const float*)d_in[3];
    const float* b_h2h   = (const float*)d_in[4];
    const float* W_score = (const float*)d_in[5];
    const float* W_ih    = (const float*)d_in[6];
    const float* W_hh    = (const float*)d_in[7];
    const float* b_ih    = (const float*)d_in[8];
    const float* b_hh    = (const float*)d_in[9];
    const float* W_gen   = (const float*)d_in[10];
    const float* b_gen   = (const float*)d_in[11];
    float* out = (float*)d_out;

    __half* d_WihH;  cudaGetSymbolAddress((void**)&d_WihH,  g_WihH);
    __half* d_WgenH; cudaGetSymbolAddress((void**)&d_WgenH, g_WgenH);
    __half* d_bhH;   cudaGetSymbolAddress((void**)&d_bhH,   g_bhH);
    __half* d_hid;   cudaGetSymbolAddress((void**)&d_hid,   g_hidden);

    pack_gates_h<<<128, 1024>>>(W_ih, W_hh);
    pack_h2h_h<<<16, 1024>>>(W_h2h);
    pack_oh<<<32, 1024>>>(W_ih, b_ih, b_hh);
    pack_bh<<<(BB * TT * DD) / 4096, 1024>>>(batch_H);
    pack_w_h<<<64, 1024>>>(W_i2h, d_WihH, 256 * 256);
    pack_w_h<<<250, 1024>>>(W_gen, d_WgenH, 1000 * 256);

    cudaFuncSetAttribute(mm2h_kernel<false>,
                         cudaFuncAttributeMaxDynamicSharedMemorySize, MM2H_SMEM);
    cudaFuncSetAttribute(mm2h_kernel<true>,
                         cudaFuncAttributeMaxDynamicSharedMemorySize, MM2H_SMEM);

    // H_proj: M=131072, N=256 -> grid (1024, 1)
    mm2h_kernel<false><<<dim3((BB * TT) / 128, 1), 512, MM2H_SMEM>>>(
        d_bhH, d_WihH, nullptr, nullptr);

    cudaFuncSetAttribute(recur_kernel, cudaFuncAttributeMaxDynamicSharedMemorySize,
                         RECUR_SMEM);
    recur_kernel<<<BB / MROWS, 512, RECUR_SMEM>>>(text, b_h2h, W_score);

    // probs: M=53248, N=1000 -> grid (416, 4)
    mm2h_kernel<true><<<dim3((BB * SS) / 128, 4), 512, MM2H_SMEM>>>(
        d_hid, d_WgenH, b_gen, out);
}